// round 8
// baseline (speedup 1.0000x reference)
#include <cuda_runtime.h>
#include <cuda_bf16.h>
#include <math.h>
#include <cstdint>

// ---------------------------------------------------------------------------
// Problem constants
// ---------------------------------------------------------------------------
#define B_    4
#define S_    2048
#define DM_   1024
#define NH_   16
#define DH_   64
#define ROWS_ (B_ * S_)          // 8192

// ---------------------------------------------------------------------------
// Scratch (device globals: allocation-free per harness rules)
// ---------------------------------------------------------------------------
__device__ __nv_bfloat16 g_Ih[3][ROWS_ * DM_];   // split inputs (q,k,v) hi
__device__ __nv_bfloat16 g_Il[3][ROWS_ * DM_];   // split inputs lo
__device__ __nv_bfloat16 g_W4h[4][DM_ * DM_];    // W^T hi (q,k,v,o)
__device__ __nv_bfloat16 g_W4l[4][DM_ * DM_];    // W^T lo
__device__ __nv_bfloat16 g_Qh[ROWS_ * DM_];
__device__ __nv_bfloat16 g_Ql[ROWS_ * DM_];
__device__ __nv_bfloat16 g_Kh[ROWS_ * DM_];
__device__ __nv_bfloat16 g_Kl[ROWS_ * DM_];
__device__ __nv_bfloat16 g_Vh[ROWS_ * DM_];
__device__ __nv_bfloat16 g_Vl[ROWS_ * DM_];
__device__ __nv_bfloat16 g_AOh[ROWS_ * DM_];
__device__ __nv_bfloat16 g_AOl[ROWS_ * DM_];

// ===========================================================================
// Generic-PTX helpers (legal on plain sm_103 target: sm_80+ instructions)
// ===========================================================================
__device__ __forceinline__ uint32_t smem_u32(const void* p) {
    uint32_t a;
    asm("{ .reg .u64 t; cvta.to.shared.u64 t, %1; cvt.u32.u64 %0, t; }"
        : "=r"(a) : "l"(p));
    return a;
}

__device__ __forceinline__ void cp16(uint32_t s, const void* g) {
    asm volatile("cp.async.cg.shared.global [%0], [%1], 16;" :: "r"(s), "l"(g));
}
#define CP_COMMIT() asm volatile("cp.async.commit_group;" ::: "memory")
#define CP_WAIT(n)  asm volatile("cp.async.wait_group %0;" :: "n"(n) : "memory")

__device__ __forceinline__ void ldmx4(uint32_t* r, uint32_t addr) {
    asm volatile("ldmatrix.sync.aligned.m8n8.x4.shared.b16 {%0,%1,%2,%3}, [%4];"
                 : "=r"(r[0]), "=r"(r[1]), "=r"(r[2]), "=r"(r[3]) : "r"(addr));
}

__device__ __forceinline__ void ldmx4t(uint32_t* r, uint32_t addr) {
    asm volatile("ldmatrix.sync.aligned.m8n8.x4.trans.shared.b16 {%0,%1,%2,%3}, [%4];"
                 : "=r"(r[0]), "=r"(r[1]), "=r"(r[2]), "=r"(r[3]) : "r"(addr));
}

__device__ __forceinline__ void mma_bf16(float* d, const uint32_t* a,
                                         const uint32_t* b) {
    asm volatile(
        "mma.sync.aligned.m16n8k16.row.col.f32.bf16.bf16.f32 "
        "{%0,%1,%2,%3}, {%4,%5,%6,%7}, {%8,%9}, {%0,%1,%2,%3};"
        : "+f"(d[0]), "+f"(d[1]), "+f"(d[2]), "+f"(d[3])
        : "r"(a[0]), "r"(a[1]), "r"(a[2]), "r"(a[3]), "r"(b[0]), "r"(b[1]));
}

__device__ __forceinline__ uint32_t cvt_bf16x2(float hi_elem, float lo_elem) {
    uint32_t r;
    asm("cvt.rn.satfinite.bf16x2.f32 %0, %1, %2;"
        : "=r"(r) : "f"(hi_elem), "f"(lo_elem));
    return r;
}

__device__ __forceinline__ float ex2f(float x) {
    float y;
    asm("ex2.approx.ftz.f32 %0, %1;" : "=f"(y) : "f"(x));
    return y;
}

// XOR swizzles: conflict-free ldmatrix on unpadded rows.
#define SWZ128B(r, ch) ((((ch) ^ ((r) & 7)) << 4))
#define SWZ64B(r, ch)  ((((ch) ^ (((r) >> 1) & 3)) << 4))

__device__ __forceinline__ int inc3(int x) { return (x == 2) ? 0 : x + 1; }

// ===========================================================================
// Prep: split 3 inputs (grid.y selects tensor); split 4 weights (grid.z)
// ===========================================================================
__global__ __launch_bounds__(256)
void split3(const float4* __restrict__ x0, const float4* __restrict__ x1,
            const float4* __restrict__ x2,
            __nv_bfloat16* __restrict__ h0, __nv_bfloat16* __restrict__ l0,
            __nv_bfloat16* __restrict__ h1, __nv_bfloat16* __restrict__ l1,
            __nv_bfloat16* __restrict__ h2, __nv_bfloat16* __restrict__ l2,
            int n4) {
    int i = blockIdx.x * blockDim.x + threadIdx.x;
    if (i >= n4) return;
    const int z = blockIdx.y;
    const float4* x = (z == 0) ? x0 : (z == 1) ? x1 : x2;
    __nv_bfloat16* hi = (z == 0) ? h0 : (z == 1) ? h1 : h2;
    __nv_bfloat16* lo = (z == 0) ? l0 : (z == 1) ? l1 : l2;
    float4 v = x[i];
    float f[4] = {v.x, v.y, v.z, v.w};
    __nv_bfloat16 h[4], l[4];
#pragma unroll
    for (int j = 0; j < 4; ++j) {
        h[j] = __float2bfloat16_rn(f[j]);
        l[j] = __float2bfloat16_rn(f[j] - __bfloat162float(h[j]));
    }
    ((__nv_bfloat162*)hi)[i * 2 + 0] = __nv_bfloat162(h[0], h[1]);
    ((__nv_bfloat162*)hi)[i * 2 + 1] = __nv_bfloat162(h[2], h[3]);
    ((__nv_bfloat162*)lo)[i * 2 + 0] = __nv_bfloat162(l[0], l[1]);
    ((__nv_bfloat162*)lo)[i * 2 + 1] = __nv_bfloat162(l[2], l[3]);
}

__global__ __launch_bounds__(256)
void wtsplit4(const float* __restrict__ w0, const float* __restrict__ w1,
              const float* __restrict__ w2, const float* __restrict__ w3,
              __nv_bfloat16* __restrict__ hi4, __nv_bfloat16* __restrict__ lo4) {
    __shared__ float t[32][33];
    const int z = blockIdx.z;
    const float* W = (z == 0) ? w0 : (z == 1) ? w1 : (z == 2) ? w2 : w3;
    __nv_bfloat16* hi = hi4 + (size_t)z * DM_ * DM_;
    __nv_bfloat16* lo = lo4 + (size_t)z * DM_ * DM_;
    const int n0 = blockIdx.x * 32;
    const int k0 = blockIdx.y * 32;
    const int tx = threadIdx.x, ty = threadIdx.y;
#pragma unroll
    for (int i = 0; i < 4; ++i)
        t[ty + i * 8][tx] = W[(size_t)(k0 + ty + i * 8) * DM_ + n0 + tx];
    __syncthreads();
#pragma unroll
    for (int i = 0; i < 4; ++i) {
        float v = t[tx][ty + i * 8];
        __nv_bfloat16 h = __float2bfloat16_rn(v);
        __nv_bfloat16 l = __float2bfloat16_rn(v - __bfloat162float(h));
        size_t o = (size_t)(n0 + ty + i * 8) * DM_ + k0 + tx;
        hi[o] = h;
        lo[o] = l;
    }
}

// ===========================================================================
// HMMA GEMM (bf16 hi/lo x3): 3-stage cp.async ring, 1 sync/ktile,
// XOR-swizzled 64B rows. 2 CTAs/SM.  (unchanged from R7)
// ===========================================================================
#define BM 128
#define BN 128
#define BK 32
#define NKT (DM_ / BK)            // 32
#define GT_TILE 8192              // 128 rows * 64B
#define GT_STAGE (4 * GT_TILE)    // 32768
#define GEMM_SMEM (3 * GT_STAGE)  // 98304

__device__ __forceinline__ void load_ktile(uint32_t sb, int kt, int stage,
                                           const __nv_bfloat16* Ahi,
                                           const __nv_bfloat16* Alo,
                                           const __nv_bfloat16* Bhi,
                                           const __nv_bfloat16* Blo,
                                           int rowBase, int colBase) {
    const int tid = threadIdx.x;
    const uint32_t base = sb + stage * GT_STAGE;
    const __nv_bfloat16* srcs[4] = {
        Ahi + (size_t)rowBase * DM_ + kt * BK,
        Alo + (size_t)rowBase * DM_ + kt * BK,
        Bhi + (size_t)colBase * DM_ + kt * BK,
        Blo + (size_t)colBase * DM_ + kt * BK};
#pragma unroll
    for (int t = 0; t < 4; ++t) {
#pragma unroll
        for (int i = 0; i < 2; ++i) {
            int c = tid + i * 256;
            int r = c >> 2, ch = c & 3;
            cp16(base + t * GT_TILE + r * 64 + SWZ64B(r, ch),
                 srcs[t] + (size_t)r * DM_ + ch * 8);
        }
    }
}

__device__ __forceinline__ void gemm_body(
    const __nv_bfloat16* __restrict__ Ahi, const __nv_bfloat16* __restrict__ Alo,
    const __nv_bfloat16* __restrict__ Bhi, const __nv_bfloat16* __restrict__ Blo,
    const float* __restrict__ bias, float* __restrict__ C,
    __nv_bfloat16* __restrict__ Chi, __nv_bfloat16* __restrict__ Clo,
    char* smem) {
    const uint32_t sb = smem_u32(smem);
    const int tid  = threadIdx.x;
    const int wid  = tid >> 5;
    const int lane = tid & 31;
    const int rowBase = blockIdx.y * BM;
    const int colBase = blockIdx.x * BN;

    const int mbase = (wid >> 1) * 32;
    const int nbase = (wid & 1) * 64;

    float acc[2][8][4];
#pragma unroll
    for (int i = 0; i < 2; ++i)
#pragma unroll
        for (int j = 0; j < 8; ++j)
#pragma unroll
            for (int q = 0; q < 4; ++q) acc[i][j][q] = 0.f;

    load_ktile(sb, 0, 0, Ahi, Alo, Bhi, Blo, rowBase, colBase);
    CP_COMMIT();
    load_ktile(sb, 1, 1, Ahi, Alo, Bhi, Blo, rowBase, colBase);
    CP_COMMIT();

    const int a_row = lane & 15;
    const int a_kb  = lane >> 4;
    const int b_row = ((lane >> 4) & 1) * 8 + (lane & 7);
    const int b_kb  = (lane >> 3) & 1;

    int cur = 0, pf = 2;
    for (int kt = 0; kt < NKT; ++kt) {
        if (kt + 1 < NKT) { CP_WAIT(1); } else { CP_WAIT(0); }
        __syncthreads();
        if (kt + 2 < NKT) {
            load_ktile(sb, kt + 2, pf, Ahi, Alo, Bhi, Blo, rowBase, colBase);
            CP_COMMIT();
        }

        const uint32_t st = sb + cur * GT_STAGE;
#pragma unroll
        for (int s = 0; s < 2; ++s) {
            uint32_t ah[2][4], al[2][4];
#pragma unroll
            for (int i = 0; i < 2; ++i) {
                int row = mbase + i * 16 + a_row;
                uint32_t off = row * 64 + SWZ64B(row, s * 2 + a_kb);
                ldmx4(ah[i], st + 0 * GT_TILE + off);
                ldmx4(al[i], st + 1 * GT_TILE + off);
            }
#pragma unroll
            for (int jp = 0; jp < 4; ++jp) {
                int row = nbase + jp * 16 + b_row;
                uint32_t off = row * 64 + SWZ64B(row, s * 2 + b_kb);
                uint32_t th[4], tl[4];
                ldmx4(th, st + 2 * GT_TILE + off);
                ldmx4(tl, st + 3 * GT_TILE + off);
                uint32_t b0h[2] = {th[0], th[1]}, b1h[2] = {th[2], th[3]};
                uint32_t b0l[2] = {tl[0], tl[1]}, b1l[2] = {tl[2], tl[3]};
#pragma unroll
                for (int i = 0; i < 2; ++i) {
                    mma_bf16(acc[i][jp * 2],     ah[i], b0h);
                    mma_bf16(acc[i][jp * 2 + 1], ah[i], b1h);
                    mma_bf16(acc[i][jp * 2],     ah[i], b0l);
                    mma_bf16(acc[i][jp * 2 + 1], ah[i], b1l);
                    mma_bf16(acc[i][jp * 2],     al[i], b0h);
                    mma_bf16(acc[i][jp * 2 + 1], al[i], b1h);
                }
            }
        }
        cur = inc3(cur);
        pf  = inc3(pf);
    }

#pragma unroll
    for (int i = 0; i < 2; ++i) {
        const int r0 = rowBase + mbase + i * 16 + (lane >> 2);
#pragma unroll
        for (int j = 0; j < 8; ++j) {
            const int col = colBase + nbase + j * 8 + (lane & 3) * 2;
            const float b0 = bias[col], b1 = bias[col + 1];
            float f0 = acc[i][j][0] + b0, f1 = acc[i][j][1] + b1;
            float f2 = acc[i][j][2] + b0, f3 = acc[i][j][3] + b1;
            if (C) {
                *(float2*)(C + (size_t)r0 * DM_ + col)       = make_float2(f0, f1);
                *(float2*)(C + (size_t)(r0 + 8) * DM_ + col) = make_float2(f2, f3);
            } else {
                uint32_t h01 = cvt_bf16x2(f1, f0);
                uint32_t h23 = cvt_bf16x2(f3, f2);
                float r0f = f0 - __uint_as_float(h01 << 16);
                float r1f = f1 - __uint_as_float(h01 & 0xFFFF0000u);
                float r2f = f2 - __uint_as_float(h23 << 16);
                float r3f = f3 - __uint_as_float(h23 & 0xFFFF0000u);
                uint32_t l01 = cvt_bf16x2(r1f, r0f);
                uint32_t l23 = cvt_bf16x2(r3f, r2f);
                *(uint32_t*)(Chi + (size_t)r0 * DM_ + col)       = h01;
                *(uint32_t*)(Chi + (size_t)(r0 + 8) * DM_ + col) = h23;
                *(uint32_t*)(Clo + (size_t)r0 * DM_ + col)       = l01;
                *(uint32_t*)(Clo + (size_t)(r0 + 8) * DM_ + col) = l23;
            }
        }
    }
}

__global__ __launch_bounds__(256, 2)
void gemm_qkv(const __nv_bfloat16* __restrict__ Ah0, const __nv_bfloat16* __restrict__ Al0,
              const __nv_bfloat16* __restrict__ Ah1, const __nv_bfloat16* __restrict__ Al1,
              const __nv_bfloat16* __restrict__ Ah2, const __nv_bfloat16* __restrict__ Al2,
              const __nv_bfloat16* __restrict__ Wh4, const __nv_bfloat16* __restrict__ Wl4,
              const float* __restrict__ b0, const float* __restrict__ b1,
              const float* __restrict__ b2,
              __nv_bfloat16* __restrict__ Ch0, __nv_bfloat16* __restrict__ Cl0,
              __nv_bfloat16* __restrict__ Ch1, __nv_bfloat16* __restrict__ Cl1,
              __nv_bfloat16* __restrict__ Ch2, __nv_bfloat16* __restrict__ Cl2) {
    extern __shared__ char smem[];
    const int z = blockIdx.z;
    const __nv_bfloat16* Ah = (z == 0) ? Ah0 : (z == 1) ? Ah1 : Ah2;
    const __nv_bfloat16* Al = (z == 0) ? Al0 : (z == 1) ? Al1 : Al2;
    const float* bias = (z == 0) ? b0 : (z == 1) ? b1 : b2;
    __nv_bfloat16* Ch = (z == 0) ? Ch0 : (z == 1) ? Ch1 : Ch2;
    __nv_bfloat16* Cl = (z == 0) ? Cl0 : (z == 1) ? Cl1 : Cl2;
    gemm_body(Ah, Al, Wh4 + (size_t)z * DM_ * DM_, Wl4 + (size_t)z * DM_ * DM_,
              bias, nullptr, Ch, Cl, smem);
}

__global__ __launch_bounds__(256, 2)
void gemm_o(const __nv_bfloat16* __restrict__ Ahi, const __nv_bfloat16* __restrict__ Alo,
            const __nv_bfloat16* __restrict__ Whi, const __nv_bfloat16* __restrict__ Wlo,
            const float* __restrict__ bias, float* __restrict__ C) {
    extern __shared__ char smem[];
    gemm_body(Ahi, Alo, Whi, Wlo, bias, C, nullptr, nullptr, smem);
}

// ===========================================================================
// Flash attention v5: 256 q-rows/CTA, 2 q-groups (A,B) per warp so softmax
// of one group overlaps MMAs of the other in the warp's own stream.
// 1 CTA/SM, 3-stage KV ring, XOR swizzle. K frags shared between A and B.
// ===========================================================================
#define FTT  8192                  // 64 rows * 128B
#define FSTG (4 * FTT)             // 32768
#define FQT  16384                 // 128 rows * 128B
#define FA5_SMEM (3 * FSTG + 2 * FQT)  // 131072

#define C2F 0.1803368801111204f    // log2(e)/8 (Dh=64 scale folded into exp2)

__device__ __forceinline__ void fa_load(uint32_t dstBase,
    const __nv_bfloat16* Khi, const __nv_bfloat16* Klo,
    const __nv_bfloat16* Vhi, const __nv_bfloat16* Vlo,
    size_t rowStart, int k0, int colOff) {
    const int tid = threadIdx.x;
    const __nv_bfloat16* srcs[4] = {
        Khi + (rowStart + k0) * DM_ + colOff,
        Klo + (rowStart + k0) * DM_ + colOff,
        Vhi + (rowStart + k0) * DM_ + colOff,
        Vlo + (rowStart + k0) * DM_ + colOff};
#pragma unroll
    for (int i = 0; i < 8; ++i) {
        int c = tid + i * 256;
        int t = c >> 9, r = (c >> 3) & 63, ch = c & 7;
        cp16(dstBase + t * FTT + r * 128 + SWZ128B(r, ch),
             srcs[t] + (size_t)r * DM_ + ch * 8);
    }
}

// online softmax + P pack for one q-group (warp-private rows, quad shuffles)
__device__ __forceinline__ void softmax_pack(
    float (&s)[8][4], float (&o)[8][4],
    float& m0, float& m1, float& l0, float& l1,
    uint32_t (&PHa)[8], uint32_t (&PHb)[8],
    uint32_t (&PLa)[8], uint32_t (&PLb)[8]) {
    float rmax0 = -1e30f, rmax1 = -1e30f;
#pragma unroll
    for (int j = 0; j < 8; ++j) {
        rmax0 = fmaxf(rmax0, fmaxf(s[j][0], s[j][1]));
        rmax1 = fmaxf(rmax1, fmaxf(s[j][2], s[j][3]));
    }
    rmax0 = fmaxf(rmax0, __shfl_xor_sync(0xffffffffu, rmax0, 1));
    rmax0 = fmaxf(rmax0, __shfl_xor_sync(0xffffffffu, rmax0, 2));
    rmax1 = fmaxf(rmax1, __shfl_xor_sync(0xffffffffu, rmax1, 1));
    rmax1 = fmaxf(rmax1, __shfl_xor_sync(0xffffffffu, rmax1, 2));
    const float m0n = fmaxf(m0, rmax0);
    const float m1n = fmaxf(m1, rmax1);
    const float c0 = ex2f((m0 - m0n) * C2F);
    const float c1 = ex2f((m1 - m1n) * C2F);
    m0 = m0n; m1 = m1n;
    const float mc0 = m0 * C2F, mc1 = m1 * C2F;
#pragma unroll
    for (int j = 0; j < 8; ++j) {
        o[j][0] *= c0; o[j][1] *= c0;
        o[j][2] *= c1; o[j][3] *= c1;
    }
    float sum0 = 0.f, sum1 = 0.f;
#pragma unroll
    for (int j = 0; j < 8; ++j) {
        s[j][0] = ex2f(fmaf(s[j][0], C2F, -mc0));
        s[j][1] = ex2f(fmaf(s[j][1], C2F, -mc0));
        s[j][2] = ex2f(fmaf(s[j][2], C2F, -mc1));
        s[j][3] = ex2f(fmaf(s[j][3], C2F, -mc1));
        sum0 += s[j][0] + s[j][1];
        sum1 += s[j][2] + s[j][3];
    }
    sum0 += __shfl_xor_sync(0xffffffffu, sum0, 1);
    sum0 += __shfl_xor_sync(0xffffffffu, sum0, 2);
    sum1 += __shfl_xor_sync(0xffffffffu, sum1, 1);
    sum1 += __shfl_xor_sync(0xffffffffu, sum1, 2);
    l0 = l0 * c0 + sum0;
    l1 = l1 * c1 + sum1;
#pragma unroll
    for (int j = 0; j < 8; ++j) {
        PHa[j] = cvt_bf16x2(s[j][1], s[j][0]);
        PHb[j] = cvt_bf16x2(s[j][3], s[j][2]);
        float ra0 = s[j][0] - __uint_as_float(PHa[j] << 16);
        float ra1 = s[j][1] - __uint_as_float(PHa[j] & 0xFFFF0000u);
        float rb0 = s[j][2] - __uint_as_float(PHb[j] << 16);
        float rb1 = s[j][3] - __uint_as_float(PHb[j] & 0xFFFF0000u);
        PLa[j] = cvt_bf16x2(ra1, ra0);
        PLb[j] = cvt_bf16x2(rb1, rb0);
    }
}

// O += P @ V for one q-group (V^T frags via ldmatrix.trans)
__device__ __forceinline__ void pv_accum(
    uint32_t kvb, int v_k, int v_db,
    const uint32_t (&PHa)[8], const uint32_t (&PHb)[8],
    const uint32_t (&PLa)[8], const uint32_t (&PLb)[8],
    float (&o)[8][4]) {
#pragma unroll
    for (int ks = 0; ks < 4; ++ks) {
        uint32_t ah[4] = {PHa[2 * ks], PHb[2 * ks],
                          PHa[2 * ks + 1], PHb[2 * ks + 1]};
        uint32_t al[4] = {PLa[2 * ks], PLb[2 * ks],
                          PLa[2 * ks + 1], PLb[2 * ks + 1]};
        const int vrow = 16 * ks + v_k;
#pragma unroll
        for (int dt = 0; dt < 4; ++dt) {
            const uint32_t off = vrow * 128 + SWZ128B(vrow, dt * 2 + v_db);
            uint32_t vh[4], vl[4];
            ldmx4t(vh, kvb + 2 * FTT + off);
            ldmx4t(vl, kvb + 3 * FTT + off);
            uint32_t b0h[2] = {vh[0], vh[1]}, b1h[2] = {vh[2], vh[3]};
            uint32_t b0l[2] = {vl[0], vl[1]}, b1l[2] = {vl[2], vl[3]};
            mma_bf16(o[2 * dt],     ah, b0h);
            mma_bf16(o[2 * dt + 1], ah, b1h);
            mma_bf16(o[2 * dt],     ah, b0l);
            mma_bf16(o[2 * dt + 1], ah, b1l);
            mma_bf16(o[2 * dt],     al, b0h);
            mma_bf16(o[2 * dt + 1], al, b1h);
        }
    }
}

__device__ __forceinline__ void write_out(
    const float (&o)[8][4], float l0, float l1,
    __nv_bfloat16* __restrict__ AOh, __nv_bfloat16* __restrict__ AOl,
    size_t row0, int colOff, int lane) {
    const float i0 = 1.f / l0, i1 = 1.f / l1;
    const size_t row1 = row0 + 8;
#pragma unroll
    for (int j = 0; j < 8; ++j) {
        const int col = colOff + j * 8 + (lane & 3) * 2;
        float f0 = o[j][0] * i0, f1 = o[j][1] * i0;
        float f2 = o[j][2] * i1, f3 = o[j][3] * i1;
        uint32_t h01 = cvt_bf16x2(f1, f0);
        uint32_t h23 = cvt_bf16x2(f3, f2);
        float r0f = f0 - __uint_as_float(h01 << 16);
        float r1f = f1 - __uint_as_float(h01 & 0xFFFF0000u);
        float r2f = f2 - __uint_as_float(h23 << 16);
        float r3f = f3 - __uint_as_float(h23 & 0xFFFF0000u);
        uint32_t l01 = cvt_bf16x2(r1f, r0f);
        uint32_t l23 = cvt_bf16x2(r3f, r2f);
        *(uint32_t*)(AOh + row0 * DM_ + col) = h01;
        *(uint32_t*)(AOh + row1 * DM_ + col) = h23;
        *(uint32_t*)(AOl + row0 * DM_ + col) = l01;
        *(uint32_t*)(AOl + row1 * DM_ + col) = l23;
    }
}

__global__ __launch_bounds__(256, 1)
void flash_mma5(const __nv_bfloat16* __restrict__ Qhi,
                const __nv_bfloat16* __restrict__ Qlo,
                const __nv_bfloat16* __restrict__ Khi,
                const __nv_bfloat16* __restrict__ Klo,
                const __nv_bfloat16* __restrict__ Vhi,
                const __nv_bfloat16* __restrict__ Vlo,
                __nv_bfloat16* __restrict__ AOh,
                __nv_bfloat16* __restrict__ AOl) {
    extern __shared__ char smem[];
    const uint32_t sb = smem_u32(smem);
    const int tid = threadIdx.x, wid = tid >> 5, lane = tid & 31;
    const int bh = blockIdx.y, b = bh >> 4, h = bh & 15;
    const int q0 = blockIdx.x * 256;
    const size_t rowStart = (size_t)b * S_;
    const int colOff = h * DH_;

    const uint32_t sQloA = sb + 3 * FSTG;    // persistent Q-lo (A,B)
    const uint32_t sQloB = sQloA + FQT;
    const uint32_t stg1 = sb + 1 * FSTG;     // Qhi_A staging
    const uint32_t stg2 = sb + 2 * FSTG;     // Qhi_B staging

    // ---- group A: Q loads (Qhi_A->stage1, Qhi_B->stage2, Qlo->persistent) --
    {
        const __nv_bfloat16* qsrc[4] = {
            Qhi + (rowStart + q0) * DM_ + colOff,
            Qhi + (rowStart + q0 + 128) * DM_ + colOff,
            Qlo + (rowStart + q0) * DM_ + colOff,
            Qlo + (rowStart + q0 + 128) * DM_ + colOff};
        const uint32_t qdst[4] = {stg1, stg2, sQloA, sQloB};
#pragma unroll
        for (int i = 0; i < 16; ++i) {
            int c = tid + i * 256;           // 0..4095
            int t = c >> 10, r = (c >> 3) & 127, ch = c & 7;
            cp16(qdst[t] + r * 128 + SWZ128B(r, ch),
                 qsrc[t] + (size_t)r * DM_ + ch * 8);
        }
    }
    CP_COMMIT();
    fa_load(sb, Khi, Klo, Vhi, Vlo, rowStart, 0, colOff);   // KV0 -> stage0
    CP_COMMIT();
    CP_WAIT(1);                          // Q complete
    __syncthreads();

    // fragment addressing
    const int a_row = lane & 15;
    const int a_kb  = lane >> 4;
    const int b_row = ((lane >> 4) & 1) * 8 + (lane & 7);
    const int b_kb  = (lane >> 3) & 1;
    const int v_k   = (lane & 7) + ((lane >> 3) & 1) * 8;
    const int v_db  = (lane >> 4) & 1;

    // ---- Q-hi fragments (A and B) into registers ----
    uint32_t qhA[4][4], qhB[4][4];
    const int qrow = 16 * wid + a_row;
#pragma unroll
    for (int ks = 0; ks < 4; ++ks) {
        const uint32_t off = qrow * 128 + SWZ128B(qrow, ks * 2 + a_kb);
        ldmx4(qhA[ks], stg1 + off);
        ldmx4(qhB[ks], stg2 + off);
    }
    __syncthreads();                     // stages 1,2 free for KV ring
    fa_load(sb + FSTG, Khi, Klo, Vhi, Vlo, rowStart, 64, colOff);  // KV1
    CP_COMMIT();

    float mA0 = -1e30f, mA1 = -1e30f, lA0 = 0.f, lA1 = 0.f;
    float mB0 = -1e30f, mB1 = -1e30f, lB0 = 0.f, lB1 = 0.f;
    float oA[8][4], oB[8][4];
#pragma unroll
    for (int j = 0; j < 8; ++j)
#pragma unroll
        for (int q = 0; q < 4; ++q) { oA[j][q] = 0.f; oB[j][q] = 0.f; }

    int cur = 0, pf = 2;
    for (int jt = 0; jt < S_ / 64; ++jt) {
        if (jt + 1 < S_ / 64) { CP_WAIT(1); } else { CP_WAIT(0); }
        __syncthreads();
        if (jt + 2 < S_ / 64) {
            fa_load(sb + pf * FSTG, Khi, Klo, Vhi, Vlo,
                    rowStart, (jt + 2) * 64, colOff);
            CP_COMMIT();
        }
        const uint32_t kvb = sb + cur * FSTG;

        // ---- QK for both groups, K fragments loaded once ----
        float sA[8][4], sB[8][4];
#pragma unroll
        for (int j = 0; j < 8; ++j)
#pragma unroll
            for (int q = 0; q < 4; ++q) { sA[j][q] = 0.f; sB[j][q] = 0.f; }

#pragma unroll
        for (int ks = 0; ks < 4; ++ks) {
            uint32_t qlA[4], qlB[4];
            const uint32_t qoff = qrow * 128 + SWZ128B(qrow, ks * 2 + a_kb);
            ldmx4(qlA, sQloA + qoff);
            ldmx4(qlB, sQloB + qoff);
#pragma unroll
            for (int ntp = 0; ntp < 4; ++ntp) {
                const int krow = ntp * 16 + b_row;
                const uint32_t koff = krow * 128 + SWZ128B(krow, ks * 2 + b_kb);
                uint32_t th[4], tl[4];
                ldmx4(th, kvb + koff);
                ldmx4(tl, kvb + FTT + koff);
                uint32_t k0h[2] = {th[0], th[1]}, k1h[2] = {th[2], th[3]};
                uint32_t k0l[2] = {tl[0], tl[1]}, k1l[2] = {tl[2], tl[3]};
                mma_bf16(sA[2 * ntp],     qhA[ks], k0h);
                mma_bf16(sB[2 * ntp],     qhB[ks], k0h);
                mma_bf16(sA[2 * ntp + 1], qhA[ks], k1h);
                mma_bf16(sB[2 * ntp + 1], qhB[ks], k1h);
                mma_bf16(sA[2 * ntp],     qhA[ks], k0l);
                mma_bf16(sB[2 * ntp],     qhB[ks], k0l);
                mma_bf16(sA[2 * ntp + 1], qhA[ks], k1l);
                mma_bf16(sB[2 * ntp + 1], qhB[ks], k1l);
                mma_bf16(sA[2 * ntp],     qlA, k0h);
                mma_bf16(sB[2 * ntp],     qlB, k0h);
                mma_bf16(sA[2 * ntp + 1], qlA, k1h);
                mma_bf16(sB[2 * ntp + 1], qlB, k1h);
            }
        }

        // ---- sm(A); PV(A) overlaps sm(B); PV(B) — one barrier-free block ---
        uint32_t PHaA[8], PHbA[8], PLaA[8], PLbA[8];
        softmax_pack(sA, oA, mA0, mA1, lA0, lA1, PHaA, PHbA, PLaA, PLbA);
        uint32_t PHaB[8], PHbB[8], PLaB[8], PLbB[8];
        softmax_pack(sB, oB, mB0, mB1, lB0, lB1, PHaB, PHbB, PLaB, PLbB);
        pv_accum(kvb, v_k, v_db, PHaA, PHbA, PLaA, PLbA, oA);
        pv_accum(kvb, v_k, v_db, PHaB, PHbB, PLaB, PLbB, oB);

        cur = inc3(cur);
        pf  = inc3(pf);
    }

    // ---- write both groups ----
    const size_t row0A = rowStart + q0 + 16 * wid + (lane >> 2);
    write_out(oA, lA0, lA1, AOh, AOl, row0A, colOff, lane);
    write_out(oB, lB0, lB1, AOh, AOl, row0A + 128, colOff, lane);
}

// ===========================================================================
// Launch
// ===========================================================================
extern "C" void kernel_launch(void* const* d_in, const int* in_sizes, int n_in,
                              void* d_out, int out_size)
{
    const float* query = (const float*)d_in[0];
    const float* key   = (const float*)d_in[1];
    const float* value = (const float*)d_in[2];
    const float* Wq    = (const float*)d_in[3];
    const float* bq    = (const float*)d_in[4];
    const float* Wk    = (const float*)d_in[5];
    const float* bk    = (const float*)d_in[6];
    const float* Wv    = (const float*)d_in[7];
    const float* bv    = (const float*)d_in[8];
    const float* Wo    = (const float*)d_in[9];
    const float* bo    = (const float*)d_in[10];
    float* out = (float*)d_out;

    __nv_bfloat16 *pIh, *pIl, *pWh, *pWl;
    __nv_bfloat16 *pQh, *pQl, *pKh, *pKl, *pVh, *pVl, *pAOh, *pAOl;
    cudaGetSymbolAddress((void**)&pIh,  g_Ih);
    cudaGetSymbolAddress((void**)&pIl,  g_Il);
    cudaGetSymbolAddress((void**)&pWh,  g_W4h);
    cudaGetSymbolAddress((void**)&pWl,  g_W4l);
    cudaGetSymbolAddress((void**)&pQh,  g_Qh);
    cudaGetSymbolAddress((void**)&pQl,  g_Ql);
    cudaGetSymbolAddress((void**)&pKh,  g_Kh);
    cudaGetSymbolAddress((void**)&pKl,  g_Kl);
    cudaGetSymbolAddress((void**)&pVh,  g_Vh);
    cudaGetSymbolAddress((void**)&pVl,  g_Vl);
    cudaGetSymbolAddress((void**)&pAOh, g_AOh);
    cudaGetSymbolAddress((void**)&pAOl, g_AOl);

    const size_t NTOK = (size_t)ROWS_ * DM_;

    static bool attrs_set = false;
    if (!attrs_set) {
        cudaFuncSetAttribute(gemm_qkv, cudaFuncAttributeMaxDynamicSharedMemorySize, GEMM_SMEM);
        cudaFuncSetAttribute(gemm_o,   cudaFuncAttributeMaxDynamicSharedMemorySize, GEMM_SMEM);
        cudaFuncSetAttribute(flash_mma5, cudaFuncAttributeMaxDynamicSharedMemorySize, FA5_SMEM);
        attrs_set = true;
    }

    const int n4 = ROWS_ * DM_ / 4;

    // 1) split all three inputs
    split3<<<dim3((n4 + 255) / 256, 3), 256>>>(
        (const float4*)query, (const float4*)key, (const float4*)value,
        pIh + 0 * NTOK, pIl + 0 * NTOK,
        pIh + 1 * NTOK, pIl + 1 * NTOK,
        pIh + 2 * NTOK, pIl + 2 * NTOK, n4);

    // 2) split+transpose all four weights
    wtsplit4<<<dim3(32, 32, 4), dim3(32, 8)>>>(Wq, Wk, Wv, Wo, pWh, pWl);

    // 3) Q,K,V projections (batched, epilogue -> bf16 hi/lo)
    gemm_qkv<<<dim3(DM_ / BN, ROWS_ / BM, 3), 256, GEMM_SMEM>>>(
        pIh + 0 * NTOK, pIl + 0 * NTOK,
        pIh + 1 * NTOK, pIl + 1 * NTOK,
        pIh + 2 * NTOK, pIl + 2 * NTOK,
        pWh, pWl, bq, bk, bv,
        pQh, pQl, pKh, pKl, pVh, pVl);

    // 4) attention (writes bf16 hi/lo)
    flash_mma5<<<dim3(S_ / 256, B_ * NH_), 256, FA5_SMEM>>>(
        pQh, pQl, pKh, pKl, pVh, pVl, pAOh, pAOl);

    // 5) output projection (fp32 result)
    gemm_o<<<dim3(DM_ / BN, ROWS_ / BM), 256, GEMM_SMEM>>>(
        pAOh, pAOl,
        pWh + 3 * (size_t)DM_ * DM_, pWl + 3 * (size_t)DM_ * DM_,
        bo, out);
}

// round 9
// speedup vs baseline: 1.0726x; 1.0726x over previous
#include <cuda_runtime.h>
#include <cuda_bf16.h>
#include <math.h>
#include <cstdint>

// ---------------------------------------------------------------------------
// Problem constants
// ---------------------------------------------------------------------------
#define B_    4
#define S_    2048
#define DM_   1024
#define NH_   16
#define DH_   64
#define ROWS_ (B_ * S_)          // 8192

// ---------------------------------------------------------------------------
// Scratch (device globals: allocation-free per harness rules)
// ---------------------------------------------------------------------------
__device__ __nv_bfloat16 g_Ih[3][ROWS_ * DM_];   // split inputs (q,k,v) hi
__device__ __nv_bfloat16 g_Il[3][ROWS_ * DM_];   // split inputs lo
__device__ __nv_bfloat16 g_W4h[4][DM_ * DM_];    // W^T hi (q,k,v,o)
__device__ __nv_bfloat16 g_W4l[4][DM_ * DM_];    // W^T lo
__device__ __nv_bfloat16 g_Qh[ROWS_ * DM_];
__device__ __nv_bfloat16 g_Ql[ROWS_ * DM_];
__device__ __nv_bfloat16 g_Kh[ROWS_ * DM_];
__device__ __nv_bfloat16 g_Kl[ROWS_ * DM_];
__device__ __nv_bfloat16 g_Vh[ROWS_ * DM_];
__device__ __nv_bfloat16 g_Vl[ROWS_ * DM_];
__device__ __nv_bfloat16 g_AOh[ROWS_ * DM_];
__device__ __nv_bfloat16 g_AOl[ROWS_ * DM_];

// ===========================================================================
// Generic-PTX helpers (legal on plain sm_103 target: sm_80+ instructions)
// ===========================================================================
__device__ __forceinline__ uint32_t smem_u32(const void* p) {
    uint32_t a;
    asm("{ .reg .u64 t; cvta.to.shared.u64 t, %1; cvt.u32.u64 %0, t; }"
        : "=r"(a) : "l"(p));
    return a;
}

__device__ __forceinline__ void cp16(uint32_t s, const void* g) {
    asm volatile("cp.async.cg.shared.global [%0], [%1], 16;" :: "r"(s), "l"(g));
}
#define CP_COMMIT() asm volatile("cp.async.commit_group;" ::: "memory")
#define CP_WAIT(n)  asm volatile("cp.async.wait_group %0;" :: "n"(n) : "memory")

__device__ __forceinline__ void ldmx4(uint32_t* r, uint32_t addr) {
    asm volatile("ldmatrix.sync.aligned.m8n8.x4.shared.b16 {%0,%1,%2,%3}, [%4];"
                 : "=r"(r[0]), "=r"(r[1]), "=r"(r[2]), "=r"(r[3]) : "r"(addr));
}

__device__ __forceinline__ void ldmx4t(uint32_t* r, uint32_t addr) {
    asm volatile("ldmatrix.sync.aligned.m8n8.x4.trans.shared.b16 {%0,%1,%2,%3}, [%4];"
                 : "=r"(r[0]), "=r"(r[1]), "=r"(r[2]), "=r"(r[3]) : "r"(addr));
}

__device__ __forceinline__ void mma_bf16(float* d, const uint32_t* a,
                                         const uint32_t* b) {
    asm volatile(
        "mma.sync.aligned.m16n8k16.row.col.f32.bf16.bf16.f32 "
        "{%0,%1,%2,%3}, {%4,%5,%6,%7}, {%8,%9}, {%0,%1,%2,%3};"
        : "+f"(d[0]), "+f"(d[1]), "+f"(d[2]), "+f"(d[3])
        : "r"(a[0]), "r"(a[1]), "r"(a[2]), "r"(a[3]), "r"(b[0]), "r"(b[1]));
}

__device__ __forceinline__ uint32_t cvt_bf16x2(float hi_elem, float lo_elem) {
    uint32_t r;
    asm("cvt.rn.satfinite.bf16x2.f32 %0, %1, %2;"
        : "=r"(r) : "f"(hi_elem), "f"(lo_elem));
    return r;
}

__device__ __forceinline__ float ex2f(float x) {
    float y;
    asm("ex2.approx.ftz.f32 %0, %1;" : "=f"(y) : "f"(x));
    return y;
}

// XOR swizzles: conflict-free ldmatrix on unpadded rows.
#define SWZ128B(r, ch) ((((ch) ^ ((r) & 7)) << 4))
#define SWZ64B(r, ch)  ((((ch) ^ (((r) >> 1) & 3)) << 4))

__device__ __forceinline__ int inc3(int x) { return (x == 2) ? 0 : x + 1; }

// ===========================================================================
// Prep: split 3 inputs (grid.y selects tensor); split 4 weights (grid.z)
// ===========================================================================
__global__ __launch_bounds__(256)
void split3(const float4* __restrict__ x0, const float4* __restrict__ x1,
            const float4* __restrict__ x2,
            __nv_bfloat16* __restrict__ h0, __nv_bfloat16* __restrict__ l0,
            __nv_bfloat16* __restrict__ h1, __nv_bfloat16* __restrict__ l1,
            __nv_bfloat16* __restrict__ h2, __nv_bfloat16* __restrict__ l2,
            int n4) {
    int i = blockIdx.x * blockDim.x + threadIdx.x;
    if (i >= n4) return;
    const int z = blockIdx.y;
    const float4* x = (z == 0) ? x0 : (z == 1) ? x1 : x2;
    __nv_bfloat16* hi = (z == 0) ? h0 : (z == 1) ? h1 : h2;
    __nv_bfloat16* lo = (z == 0) ? l0 : (z == 1) ? l1 : l2;
    float4 v = x[i];
    float f[4] = {v.x, v.y, v.z, v.w};
    __nv_bfloat16 h[4], l[4];
#pragma unroll
    for (int j = 0; j < 4; ++j) {
        h[j] = __float2bfloat16_rn(f[j]);
        l[j] = __float2bfloat16_rn(f[j] - __bfloat162float(h[j]));
    }
    ((__nv_bfloat162*)hi)[i * 2 + 0] = __nv_bfloat162(h[0], h[1]);
    ((__nv_bfloat162*)hi)[i * 2 + 1] = __nv_bfloat162(h[2], h[3]);
    ((__nv_bfloat162*)lo)[i * 2 + 0] = __nv_bfloat162(l[0], l[1]);
    ((__nv_bfloat162*)lo)[i * 2 + 1] = __nv_bfloat162(l[2], l[3]);
}

__global__ __launch_bounds__(256)
void wtsplit4(const float* __restrict__ w0, const float* __restrict__ w1,
              const float* __restrict__ w2, const float* __restrict__ w3,
              __nv_bfloat16* __restrict__ hi4, __nv_bfloat16* __restrict__ lo4) {
    __shared__ float t[32][33];
    const int z = blockIdx.z;
    const float* W = (z == 0) ? w0 : (z == 1) ? w1 : (z == 2) ? w2 : w3;
    __nv_bfloat16* hi = hi4 + (size_t)z * DM_ * DM_;
    __nv_bfloat16* lo = lo4 + (size_t)z * DM_ * DM_;
    const int n0 = blockIdx.x * 32;
    const int k0 = blockIdx.y * 32;
    const int tx = threadIdx.x, ty = threadIdx.y;
#pragma unroll
    for (int i = 0; i < 4; ++i)
        t[ty + i * 8][tx] = W[(size_t)(k0 + ty + i * 8) * DM_ + n0 + tx];
    __syncthreads();
#pragma unroll
    for (int i = 0; i < 4; ++i) {
        float v = t[tx][ty + i * 8];
        __nv_bfloat16 h = __float2bfloat16_rn(v);
        __nv_bfloat16 l = __float2bfloat16_rn(v - __bfloat162float(h));
        size_t o = (size_t)(n0 + ty + i * 8) * DM_ + k0 + tx;
        hi[o] = h;
        lo[o] = l;
    }
}

// ===========================================================================
// HMMA GEMM (bf16 hi/lo x3): 3-stage cp.async ring, 1 sync/ktile,
// XOR-swizzled 64B rows. 2 CTAs/SM.  (unchanged from R7)
// ===========================================================================
#define BM 128
#define BN 128
#define BK 32
#define NKT (DM_ / BK)            // 32
#define GT_TILE 8192              // 128 rows * 64B
#define GT_STAGE (4 * GT_TILE)    // 32768
#define GEMM_SMEM (3 * GT_STAGE)  // 98304

__device__ __forceinline__ void load_ktile(uint32_t sb, int kt, int stage,
                                           const __nv_bfloat16* Ahi,
                                           const __nv_bfloat16* Alo,
                                           const __nv_bfloat16* Bhi,
                                           const __nv_bfloat16* Blo,
                                           int rowBase, int colBase) {
    const int tid = threadIdx.x;
    const uint32_t base = sb + stage * GT_STAGE;
    const __nv_bfloat16* srcs[4] = {
        Ahi + (size_t)rowBase * DM_ + kt * BK,
        Alo + (size_t)rowBase * DM_ + kt * BK,
        Bhi + (size_t)colBase * DM_ + kt * BK,
        Blo + (size_t)colBase * DM_ + kt * BK};
#pragma unroll
    for (int t = 0; t < 4; ++t) {
#pragma unroll
        for (int i = 0; i < 2; ++i) {
            int c = tid + i * 256;
            int r = c >> 2, ch = c & 3;
            cp16(base + t * GT_TILE + r * 64 + SWZ64B(r, ch),
                 srcs[t] + (size_t)r * DM_ + ch * 8);
        }
    }
}

__device__ __forceinline__ void gemm_body(
    const __nv_bfloat16* __restrict__ Ahi, const __nv_bfloat16* __restrict__ Alo,
    const __nv_bfloat16* __restrict__ Bhi, const __nv_bfloat16* __restrict__ Blo,
    const float* __restrict__ bias, float* __restrict__ C,
    __nv_bfloat16* __restrict__ Chi, __nv_bfloat16* __restrict__ Clo,
    char* smem) {
    const uint32_t sb = smem_u32(smem);
    const int tid  = threadIdx.x;
    const int wid  = tid >> 5;
    const int lane = tid & 31;
    const int rowBase = blockIdx.y * BM;
    const int colBase = blockIdx.x * BN;

    const int mbase = (wid >> 1) * 32;
    const int nbase = (wid & 1) * 64;

    float acc[2][8][4];
#pragma unroll
    for (int i = 0; i < 2; ++i)
#pragma unroll
        for (int j = 0; j < 8; ++j)
#pragma unroll
            for (int q = 0; q < 4; ++q) acc[i][j][q] = 0.f;

    load_ktile(sb, 0, 0, Ahi, Alo, Bhi, Blo, rowBase, colBase);
    CP_COMMIT();
    load_ktile(sb, 1, 1, Ahi, Alo, Bhi, Blo, rowBase, colBase);
    CP_COMMIT();

    const int a_row = lane & 15;
    const int a_kb  = lane >> 4;
    const int b_row = ((lane >> 4) & 1) * 8 + (lane & 7);
    const int b_kb  = (lane >> 3) & 1;

    int cur = 0, pf = 2;
    for (int kt = 0; kt < NKT; ++kt) {
        if (kt + 1 < NKT) { CP_WAIT(1); } else { CP_WAIT(0); }
        __syncthreads();
        if (kt + 2 < NKT) {
            load_ktile(sb, kt + 2, pf, Ahi, Alo, Bhi, Blo, rowBase, colBase);
            CP_COMMIT();
        }

        const uint32_t st = sb + cur * GT_STAGE;
#pragma unroll
        for (int s = 0; s < 2; ++s) {
            uint32_t ah[2][4], al[2][4];
#pragma unroll
            for (int i = 0; i < 2; ++i) {
                int row = mbase + i * 16 + a_row;
                uint32_t off = row * 64 + SWZ64B(row, s * 2 + a_kb);
                ldmx4(ah[i], st + 0 * GT_TILE + off);
                ldmx4(al[i], st + 1 * GT_TILE + off);
            }
#pragma unroll
            for (int jp = 0; jp < 4; ++jp) {
                int row = nbase + jp * 16 + b_row;
                uint32_t off = row * 64 + SWZ64B(row, s * 2 + b_kb);
                uint32_t th[4], tl[4];
                ldmx4(th, st + 2 * GT_TILE + off);
                ldmx4(tl, st + 3 * GT_TILE + off);
                uint32_t b0h[2] = {th[0], th[1]}, b1h[2] = {th[2], th[3]};
                uint32_t b0l[2] = {tl[0], tl[1]}, b1l[2] = {tl[2], tl[3]};
#pragma unroll
                for (int i = 0; i < 2; ++i) {
                    mma_bf16(acc[i][jp * 2],     ah[i], b0h);
                    mma_bf16(acc[i][jp * 2 + 1], ah[i], b1h);
                    mma_bf16(acc[i][jp * 2],     ah[i], b0l);
                    mma_bf16(acc[i][jp * 2 + 1], ah[i], b1l);
                    mma_bf16(acc[i][jp * 2],     al[i], b0h);
                    mma_bf16(acc[i][jp * 2 + 1], al[i], b1h);
                }
            }
        }
        cur = inc3(cur);
        pf  = inc3(pf);
    }

#pragma unroll
    for (int i = 0; i < 2; ++i) {
        const int r0 = rowBase + mbase + i * 16 + (lane >> 2);
#pragma unroll
        for (int j = 0; j < 8; ++j) {
            const int col = colBase + nbase + j * 8 + (lane & 3) * 2;
            const float b0 = bias[col], b1 = bias[col + 1];
            float f0 = acc[i][j][0] + b0, f1 = acc[i][j][1] + b1;
            float f2 = acc[i][j][2] + b0, f3 = acc[i][j][3] + b1;
            if (C) {
                *(float2*)(C + (size_t)r0 * DM_ + col)       = make_float2(f0, f1);
                *(float2*)(C + (size_t)(r0 + 8) * DM_ + col) = make_float2(f2, f3);
            } else {
                uint32_t h01 = cvt_bf16x2(f1, f0);
                uint32_t h23 = cvt_bf16x2(f3, f2);
                float r0f = f0 - __uint_as_float(h01 << 16);
                float r1f = f1 - __uint_as_float(h01 & 0xFFFF0000u);
                float r2f = f2 - __uint_as_float(h23 << 16);
                float r3f = f3 - __uint_as_float(h23 & 0xFFFF0000u);
                uint32_t l01 = cvt_bf16x2(r1f, r0f);
                uint32_t l23 = cvt_bf16x2(r3f, r2f);
                *(uint32_t*)(Chi + (size_t)r0 * DM_ + col)       = h01;
                *(uint32_t*)(Chi + (size_t)(r0 + 8) * DM_ + col) = h23;
                *(uint32_t*)(Clo + (size_t)r0 * DM_ + col)       = l01;
                *(uint32_t*)(Clo + (size_t)(r0 + 8) * DM_ + col) = l23;
            }
        }
    }
}

__global__ __launch_bounds__(256, 2)
void gemm_qkv(const __nv_bfloat16* __restrict__ Ah0, const __nv_bfloat16* __restrict__ Al0,
              const __nv_bfloat16* __restrict__ Ah1, const __nv_bfloat16* __restrict__ Al1,
              const __nv_bfloat16* __restrict__ Ah2, const __nv_bfloat16* __restrict__ Al2,
              const __nv_bfloat16* __restrict__ Wh4, const __nv_bfloat16* __restrict__ Wl4,
              const float* __restrict__ b0, const float* __restrict__ b1,
              const float* __restrict__ b2,
              __nv_bfloat16* __restrict__ Ch0, __nv_bfloat16* __restrict__ Cl0,
              __nv_bfloat16* __restrict__ Ch1, __nv_bfloat16* __restrict__ Cl1,
              __nv_bfloat16* __restrict__ Ch2, __nv_bfloat16* __restrict__ Cl2) {
    extern __shared__ char smem[];
    const int z = blockIdx.z;
    const __nv_bfloat16* Ah = (z == 0) ? Ah0 : (z == 1) ? Ah1 : Ah2;
    const __nv_bfloat16* Al = (z == 0) ? Al0 : (z == 1) ? Al1 : Al2;
    const float* bias = (z == 0) ? b0 : (z == 1) ? b1 : b2;
    __nv_bfloat16* Ch = (z == 0) ? Ch0 : (z == 1) ? Ch1 : Ch2;
    __nv_bfloat16* Cl = (z == 0) ? Cl0 : (z == 1) ? Cl1 : Cl2;
    gemm_body(Ah, Al, Wh4 + (size_t)z * DM_ * DM_, Wl4 + (size_t)z * DM_ * DM_,
              bias, nullptr, Ch, Cl, smem);
}

__global__ __launch_bounds__(256, 2)
void gemm_o(const __nv_bfloat16* __restrict__ Ahi, const __nv_bfloat16* __restrict__ Alo,
            const __nv_bfloat16* __restrict__ Whi, const __nv_bfloat16* __restrict__ Wlo,
            const float* __restrict__ bias, float* __restrict__ C) {
    extern __shared__ char smem[];
    gemm_body(Ahi, Alo, Whi, Wlo, bias, C, nullptr, nullptr, smem);
}

// ===========================================================================
// Flash attention v6: cross-tile software pipeline.
// Per iter: sm(jt) [indep] + QK(jt+1) MMAs interleave, then PV(jt).
// K ring[2] + V ring[2] + persistent Qhi/Qlo. 128 q-rows/CTA, 2 CTAs/SM.
// ===========================================================================
#define KTT  8192                  // 64 rows * 128B (one of hi/lo)
#define KSTG (2 * KTT)             // Khi+Klo = 16384
#define FQT  16384                 // 128 rows * 128B
#define FA6_SMEM (4 * KSTG + 2 * FQT)  // 2 K-stages + 2 V-stages + Qh + Ql = 98304

#define C2F 0.1803368801111204f    // log2(e)/8 (Dh=64 scale folded into exp2)
#define NT_ (S_ / 64)              // 32 kv tiles

__device__ __forceinline__ void fa6_load_pair(uint32_t dst,
    const __nv_bfloat16* Hi, const __nv_bfloat16* Lo,
    size_t rowStart, int k0, int colOff) {
    const int tid = threadIdx.x;
    const __nv_bfloat16* srcs[2] = {Hi + (rowStart + k0) * DM_ + colOff,
                                    Lo + (rowStart + k0) * DM_ + colOff};
#pragma unroll
    for (int i = 0; i < 4; ++i) {
        int c = tid + i * 256;           // 0..1023
        int t = c >> 9, r = (c >> 3) & 63, ch = c & 7;
        cp16(dst + t * KTT + r * 128 + SWZ128B(r, ch),
             srcs[t] + (size_t)r * DM_ + ch * 8);
    }
}

// QK for one tile: s = Q(smem hi/lo) @ K(smem hi/lo)^T, x3 passes.
__device__ __forceinline__ void qk_tile(
    uint32_t ksBase, uint32_t sQh, uint32_t sQl,
    int qrow, int a_kb, int b_row, int b_kb, float (&s)[8][4]) {
#pragma unroll
    for (int j = 0; j < 8; ++j)
#pragma unroll
        for (int q = 0; q < 4; ++q) s[j][q] = 0.f;
#pragma unroll
    for (int ks = 0; ks < 4; ++ks) {
        uint32_t qh[4], ql[4];
        const uint32_t qoff = qrow * 128 + SWZ128B(qrow, ks * 2 + a_kb);
        ldmx4(qh, sQh + qoff);
        ldmx4(ql, sQl + qoff);
#pragma unroll
        for (int ntp = 0; ntp < 4; ++ntp) {
            const int krow = ntp * 16 + b_row;
            const uint32_t koff = krow * 128 + SWZ128B(krow, ks * 2 + b_kb);
            uint32_t th[4], tl[4];
            ldmx4(th, ksBase + koff);
            ldmx4(tl, ksBase + KTT + koff);
            uint32_t k0h[2] = {th[0], th[1]}, k1h[2] = {th[2], th[3]};
            uint32_t k0l[2] = {tl[0], tl[1]}, k1l[2] = {tl[2], tl[3]};
            mma_bf16(s[2 * ntp],     qh, k0h);
            mma_bf16(s[2 * ntp + 1], qh, k1h);
            mma_bf16(s[2 * ntp],     qh, k0l);
            mma_bf16(s[2 * ntp + 1], qh, k1l);
            mma_bf16(s[2 * ntp],     ql, k0h);
            mma_bf16(s[2 * ntp + 1], ql, k1h);
        }
    }
}

// online softmax + P pack (warp-private rows, quad shuffles). Rescales o.
__device__ __forceinline__ void softmax_pack(
    float (&s)[8][4], float (&o)[8][4],
    float& m0, float& m1, float& l0, float& l1,
    uint32_t (&PHa)[8], uint32_t (&PHb)[8],
    uint32_t (&PLa)[8], uint32_t (&PLb)[8]) {
    float rmax0 = -1e30f, rmax1 = -1e30f;
#pragma unroll
    for (int j = 0; j < 8; ++j) {
        rmax0 = fmaxf(rmax0, fmaxf(s[j][0], s[j][1]));
        rmax1 = fmaxf(rmax1, fmaxf(s[j][2], s[j][3]));
    }
    rmax0 = fmaxf(rmax0, __shfl_xor_sync(0xffffffffu, rmax0, 1));
    rmax0 = fmaxf(rmax0, __shfl_xor_sync(0xffffffffu, rmax0, 2));
    rmax1 = fmaxf(rmax1, __shfl_xor_sync(0xffffffffu, rmax1, 1));
    rmax1 = fmaxf(rmax1, __shfl_xor_sync(0xffffffffu, rmax1, 2));
    const float m0n = fmaxf(m0, rmax0);
    const float m1n = fmaxf(m1, rmax1);
    const float c0 = ex2f((m0 - m0n) * C2F);
    const float c1 = ex2f((m1 - m1n) * C2F);
    m0 = m0n; m1 = m1n;
    const float mc0 = m0 * C2F, mc1 = m1 * C2F;
    float sum0 = 0.f, sum1 = 0.f;
#pragma unroll
    for (int j = 0; j < 8; ++j) {
        s[j][0] = ex2f(fmaf(s[j][0], C2F, -mc0));
        s[j][1] = ex2f(fmaf(s[j][1], C2F, -mc0));
        s[j][2] = ex2f(fmaf(s[j][2], C2F, -mc1));
        s[j][3] = ex2f(fmaf(s[j][3], C2F, -mc1));
        sum0 += s[j][0] + s[j][1];
        sum1 += s[j][2] + s[j][3];
    }
    sum0 += __shfl_xor_sync(0xffffffffu, sum0, 1);
    sum0 += __shfl_xor_sync(0xffffffffu, sum0, 2);
    sum1 += __shfl_xor_sync(0xffffffffu, sum1, 1);
    sum1 += __shfl_xor_sync(0xffffffffu, sum1, 2);
    l0 = l0 * c0 + sum0;
    l1 = l1 * c1 + sum1;
#pragma unroll
    for (int j = 0; j < 8; ++j) {
        PHa[j] = cvt_bf16x2(s[j][1], s[j][0]);
        PHb[j] = cvt_bf16x2(s[j][3], s[j][2]);
        float ra0 = s[j][0] - __uint_as_float(PHa[j] << 16);
        float ra1 = s[j][1] - __uint_as_float(PHa[j] & 0xFFFF0000u);
        float rb0 = s[j][2] - __uint_as_float(PHb[j] << 16);
        float rb1 = s[j][3] - __uint_as_float(PHb[j] & 0xFFFF0000u);
        PLa[j] = cvt_bf16x2(ra1, ra0);
        PLb[j] = cvt_bf16x2(rb1, rb0);
    }
#pragma unroll
    for (int j = 0; j < 8; ++j) {
        o[j][0] *= c0; o[j][1] *= c0;
        o[j][2] *= c1; o[j][3] *= c1;
    }
}

// O += P @ V (V^T frags via ldmatrix.trans). vsBase: Vhi at +0, Vlo at +KTT.
__device__ __forceinline__ void pv_accum(
    uint32_t vsBase, int v_k, int v_db,
    const uint32_t (&PHa)[8], const uint32_t (&PHb)[8],
    const uint32_t (&PLa)[8], const uint32_t (&PLb)[8],
    float (&o)[8][4]) {
#pragma unroll
    for (int ks = 0; ks < 4; ++ks) {
        uint32_t ah[4] = {PHa[2 * ks], PHb[2 * ks],
                          PHa[2 * ks + 1], PHb[2 * ks + 1]};
        uint32_t al[4] = {PLa[2 * ks], PLb[2 * ks],
                          PLa[2 * ks + 1], PLb[2 * ks + 1]};
        const int vrow = 16 * ks + v_k;
#pragma unroll
        for (int dt = 0; dt < 4; ++dt) {
            const uint32_t off = vrow * 128 + SWZ128B(vrow, dt * 2 + v_db);
            uint32_t vh[4], vl[4];
            ldmx4t(vh, vsBase + off);
            ldmx4t(vl, vsBase + KTT + off);
            uint32_t b0h[2] = {vh[0], vh[1]}, b1h[2] = {vh[2], vh[3]};
            uint32_t b0l[2] = {vl[0], vl[1]}, b1l[2] = {vl[2], vl[3]};
            mma_bf16(o[2 * dt],     ah, b0h);
            mma_bf16(o[2 * dt + 1], ah, b1h);
            mma_bf16(o[2 * dt],     ah, b0l);
            mma_bf16(o[2 * dt + 1], ah, b1l);
            mma_bf16(o[2 * dt],     al, b0h);
            mma_bf16(o[2 * dt + 1], al, b1h);
        }
    }
}

__global__ __launch_bounds__(256, 2)
void flash_mma6(const __nv_bfloat16* __restrict__ Qhi,
                const __nv_bfloat16* __restrict__ Qlo,
                const __nv_bfloat16* __restrict__ Khi,
                const __nv_bfloat16* __restrict__ Klo,
                const __nv_bfloat16* __restrict__ Vhi,
                const __nv_bfloat16* __restrict__ Vlo,
                __nv_bfloat16* __restrict__ AOh,
                __nv_bfloat16* __restrict__ AOl) {
    extern __shared__ char smem[];
    const uint32_t sb = smem_u32(smem);
    const int tid = threadIdx.x, wid = tid >> 5, lane = tid & 31;
    const int bh = blockIdx.y, b = bh >> 4, h = bh & 15;
    const int q0 = blockIdx.x * 128;
    const size_t rowStart = (size_t)b * S_;
    const int colOff = h * DH_;

    // smem layout
    const uint32_t Ks0 = sb;
    const uint32_t Ks1 = sb + KSTG;
    const uint32_t Vs0 = sb + 2 * KSTG;
    const uint32_t Vs1 = sb + 3 * KSTG;
    const uint32_t sQh = sb + 4 * KSTG;
    const uint32_t sQl = sQh + FQT;

    // ---- prologue loads: Q + K0 + V0 (group), K1 (group) ----
    {
        const __nv_bfloat16* qsrc[2] = {Qhi + (rowStart + q0) * DM_ + colOff,
                                        Qlo + (rowStart + q0) * DM_ + colOff};
        const uint32_t qdst[2] = {sQh, sQl};
#pragma unroll
        for (int i = 0; i < 8; ++i) {
            int c = tid + i * 256;           // 0..2047
            int t = c >> 10, r = (c >> 3) & 127, ch = c & 7;
            cp16(qdst[t] + r * 128 + SWZ128B(r, ch),
                 qsrc[t] + (size_t)r * DM_ + ch * 8);
        }
    }
    fa6_load_pair(Ks0, Khi, Klo, rowStart, 0, colOff);
    fa6_load_pair(Vs0, Vhi, Vlo, rowStart, 0, colOff);
    CP_COMMIT();
    fa6_load_pair(Ks1, Khi, Klo, rowStart, 64, colOff);
    CP_COMMIT();
    CP_WAIT(0);
    __syncthreads();

    // fragment addressing
    const int a_row = lane & 15;
    const int a_kb  = lane >> 4;
    const int b_row = ((lane >> 4) & 1) * 8 + (lane & 7);
    const int b_kb  = (lane >> 3) & 1;
    const int v_k   = (lane & 7) + ((lane >> 3) & 1) * 8;
    const int v_db  = (lane >> 4) & 1;
    const int qrow  = 16 * wid + a_row;

    float m0 = -1e30f, m1 = -1e30f, l0 = 0.f, l1 = 0.f;
    float o[8][4];
#pragma unroll
    for (int j = 0; j < 8; ++j)
#pragma unroll
        for (int q = 0; q < 4; ++q) o[j][q] = 0.f;

    // ---- software-pipeline prologue: s(0) ----
    float s[8][4];
    qk_tile(Ks0, sQh, sQl, qrow, a_kb, b_row, b_kb, s);

    // ---- main loop: iters 0..NT_-2 (QK(jt+1) unconditional) ----
    for (int jt = 0; jt < NT_ - 1; ++jt) {
        CP_WAIT(0);
        __syncthreads();                 // K(jt+1), V(jt) resident; old slots dead
        // prefetch: K(jt+2) (clamped) -> Kslot[jt&1], V(jt+1) -> Vslot[(jt+1)&1]
        const int kc = (jt + 2 < NT_) ? (jt + 2) : (NT_ - 1);
        fa6_load_pair((jt & 1) ? Ks1 : Ks0, Khi, Klo, rowStart, kc * 64, colOff);
        fa6_load_pair(((jt + 1) & 1) ? Vs1 : Vs0, Vhi, Vlo, rowStart,
                      (jt + 1) * 64, colOff);
        CP_COMMIT();

        // sm(jt): packs P, rescales o (independent of QK(jt+1) below)
        uint32_t PHa[8], PHb[8], PLa[8], PLb[8];
        softmax_pack(s, o, m0, m1, l0, l1, PHa, PHb, PLa, PLb);

        // QK(jt+1): refills s — MMAs interleave with softmax arithmetic above
        qk_tile(((jt + 1) & 1) ? Ks1 : Ks0, sQh, sQl, qrow, a_kb, b_row, b_kb, s);

        // PV(jt)
        pv_accum((jt & 1) ? Vs1 : Vs0, v_k, v_db, PHa, PHb, PLa, PLb, o);
    }

    // ---- tail: jt = NT_-1 (no QK) ----
    CP_WAIT(0);
    __syncthreads();
    {
        uint32_t PHa[8], PHb[8], PLa[8], PLb[8];
        softmax_pack(s, o, m0, m1, l0, l1, PHa, PHb, PLa, PLb);
        pv_accum(((NT_ - 1) & 1) ? Vs1 : Vs0, v_k, v_db, PHa, PHb, PLa, PLb, o);
    }

    // ---- normalize, split to bf16 hi/lo, write ----
    const float i0 = 1.f / l0, i1 = 1.f / l1;
    const size_t row0 = rowStart + q0 + 16 * wid + (lane >> 2);
    const size_t row1 = row0 + 8;
#pragma unroll
    for (int j = 0; j < 8; ++j) {
        const int col = colOff + j * 8 + (lane & 3) * 2;
        float f0 = o[j][0] * i0, f1 = o[j][1] * i0;
        float f2 = o[j][2] * i1, f3 = o[j][3] * i1;
        uint32_t h01 = cvt_bf16x2(f1, f0);
        uint32_t h23 = cvt_bf16x2(f3, f2);
        float r0f = f0 - __uint_as_float(h01 << 16);
        float r1f = f1 - __uint_as_float(h01 & 0xFFFF0000u);
        float r2f = f2 - __uint_as_float(h23 << 16);
        float r3f = f3 - __uint_as_float(h23 & 0xFFFF0000u);
        uint32_t l01 = cvt_bf16x2(r1f, r0f);
        uint32_t l23 = cvt_bf16x2(r3f, r2f);
        *(uint32_t*)(AOh + row0 * DM_ + col) = h01;
        *(uint32_t*)(AOh + row1 * DM_ + col) = h23;
        *(uint32_t*)(AOl + row0 * DM_ + col) = l01;
        *(uint32_t*)(AOl + row1 * DM_ + col) = l23;
    }
}

// ===========================================================================
// Launch
// ===========================================================================
extern "C" void kernel_launch(void* const* d_in, const int* in_sizes, int n_in,
                              void* d_out, int out_size)
{
    const float* query = (const float*)d_in[0];
    const float* key   = (const float*)d_in[1];
    const float* value = (const float*)d_in[2];
    const float* Wq    = (const float*)d_in[3];
    const float* bq    = (const float*)d_in[4];
    const float* Wk    = (const float*)d_in[5];
    const float* bk    = (const float*)d_in[6];
    const float* Wv    = (const float*)d_in[7];
    const float* bv    = (const float*)d_in[8];
    const float* Wo    = (const float*)d_in[9];
    const float* bo    = (const float*)d_in[10];
    float* out = (float*)d_out;

    __nv_bfloat16 *pIh, *pIl, *pWh, *pWl;
    __nv_bfloat16 *pQh, *pQl, *pKh, *pKl, *pVh, *pVl, *pAOh, *pAOl;
    cudaGetSymbolAddress((void**)&pIh,  g_Ih);
    cudaGetSymbolAddress((void**)&pIl,  g_Il);
    cudaGetSymbolAddress((void**)&pWh,  g_W4h);
    cudaGetSymbolAddress((void**)&pWl,  g_W4l);
    cudaGetSymbolAddress((void**)&pQh,  g_Qh);
    cudaGetSymbolAddress((void**)&pQl,  g_Ql);
    cudaGetSymbolAddress((void**)&pKh,  g_Kh);
    cudaGetSymbolAddress((void**)&pKl,  g_Kl);
    cudaGetSymbolAddress((void**)&pVh,  g_Vh);
    cudaGetSymbolAddress((void**)&pVl,  g_Vl);
    cudaGetSymbolAddress((void**)&pAOh, g_AOh);
    cudaGetSymbolAddress((void**)&pAOl, g_AOl);

    const size_t NTOK = (size_t)ROWS_ * DM_;

    static bool attrs_set = false;
    if (!attrs_set) {
        cudaFuncSetAttribute(gemm_qkv, cudaFuncAttributeMaxDynamicSharedMemorySize, GEMM_SMEM);
        cudaFuncSetAttribute(gemm_o,   cudaFuncAttributeMaxDynamicSharedMemorySize, GEMM_SMEM);
        cudaFuncSetAttribute(flash_mma6, cudaFuncAttributeMaxDynamicSharedMemorySize, FA6_SMEM);
        attrs_set = true;
    }

    const int n4 = ROWS_ * DM_ / 4;

    // 1) split all three inputs
    split3<<<dim3((n4 + 255) / 256, 3), 256>>>(
        (const float4*)query, (const float4*)key, (const float4*)value,
        pIh + 0 * NTOK, pIl + 0 * NTOK,
        pIh + 1 * NTOK, pIl + 1 * NTOK,
        pIh + 2 * NTOK, pIl + 2 * NTOK, n4);

    // 2) split+transpose all four weights
    wtsplit4<<<dim3(32, 32, 4), dim3(32, 8)>>>(Wq, Wk, Wv, Wo, pWh, pWl);

    // 3) Q,K,V projections (batched, epilogue -> bf16 hi/lo)
    gemm_qkv<<<dim3(DM_ / BN, ROWS_ / BM, 3), 256, GEMM_SMEM>>>(
        pIh + 0 * NTOK, pIl + 0 * NTOK,
        pIh + 1 * NTOK, pIl + 1 * NTOK,
        pIh + 2 * NTOK, pIl + 2 * NTOK,
        pWh, pWl, bq, bk, bv,
        pQh, pQl, pKh, pKl, pVh, pVl);

    // 4) attention (writes bf16 hi/lo)
    flash_mma6<<<dim3(S_ / 128, B_ * NH_), 256, FA6_SMEM>>>(
        pQh, pQl, pKh, pKl, pVh, pVl, pAOh, pAOl);

    // 5) output projection (fp32 result)
    gemm_o<<<dim3(DM_ / BN, ROWS_ / BM), 256, GEMM_SMEM>>>(
        pAOh, pAOl,
        pWh + 3 * (size_t)DM_ * DM_, pWl + 3 * (size_t)DM_ * DM_,
        bo, out);
}

// round 10
// speedup vs baseline: 1.1313x; 1.0547x over previous
#include <cuda_runtime.h>
#include <cuda_bf16.h>
#include <cuda_fp16.h>
#include <math.h>
#include <cstdint>

// ---------------------------------------------------------------------------
// Problem constants
// ---------------------------------------------------------------------------
#define B_    4
#define S_    2048
#define DM_   1024
#define NH_   16
#define DH_   64
#define ROWS_ (B_ * S_)          // 8192

// ---------------------------------------------------------------------------
// Scratch (device globals: allocation-free per harness rules)
// g_Vh/g_Vl hold fp16 bits (declared bf16 for storage; loads are type-blind).
// ---------------------------------------------------------------------------
__device__ __nv_bfloat16 g_Ih[3][ROWS_ * DM_];   // split inputs (q,k,v) hi
__device__ __nv_bfloat16 g_Il[3][ROWS_ * DM_];   // split inputs lo
__device__ __nv_bfloat16 g_W4h[4][DM_ * DM_];    // W^T hi (q,k,v,o)
__device__ __nv_bfloat16 g_W4l[4][DM_ * DM_];    // W^T lo
__device__ __nv_bfloat16 g_Qh[ROWS_ * DM_];
__device__ __nv_bfloat16 g_Ql[ROWS_ * DM_];
__device__ __nv_bfloat16 g_Kh[ROWS_ * DM_];
__device__ __nv_bfloat16 g_Kl[ROWS_ * DM_];
__device__ __nv_bfloat16 g_Vh[ROWS_ * DM_];      // fp16 hi bits
__device__ __nv_bfloat16 g_Vl[ROWS_ * DM_];      // fp16 lo bits
__device__ __nv_bfloat16 g_AOh[ROWS_ * DM_];
__device__ __nv_bfloat16 g_AOl[ROWS_ * DM_];

// ===========================================================================
// Generic-PTX helpers (legal on plain sm_103 target: sm_80+ instructions)
// ===========================================================================
__device__ __forceinline__ uint32_t smem_u32(const void* p) {
    uint32_t a;
    asm("{ .reg .u64 t; cvta.to.shared.u64 t, %1; cvt.u32.u64 %0, t; }"
        : "=r"(a) : "l"(p));
    return a;
}

__device__ __forceinline__ void cp16(uint32_t s, const void* g) {
    asm volatile("cp.async.cg.shared.global [%0], [%1], 16;" :: "r"(s), "l"(g));
}
#define CP_COMMIT() asm volatile("cp.async.commit_group;" ::: "memory")
#define CP_WAIT(n)  asm volatile("cp.async.wait_group %0;" :: "n"(n) : "memory")

__device__ __forceinline__ void ldmx4(uint32_t* r, uint32_t addr) {
    asm volatile("ldmatrix.sync.aligned.m8n8.x4.shared.b16 {%0,%1,%2,%3}, [%4];"
                 : "=r"(r[0]), "=r"(r[1]), "=r"(r[2]), "=r"(r[3]) : "r"(addr));
}

__device__ __forceinline__ void ldmx4t(uint32_t* r, uint32_t addr) {
    asm volatile("ldmatrix.sync.aligned.m8n8.x4.trans.shared.b16 {%0,%1,%2,%3}, [%4];"
                 : "=r"(r[0]), "=r"(r[1]), "=r"(r[2]), "=r"(r[3]) : "r"(addr));
}

__device__ __forceinline__ void mma_bf16(float* d, const uint32_t* a,
                                         const uint32_t* b) {
    asm volatile(
        "mma.sync.aligned.m16n8k16.row.col.f32.bf16.bf16.f32 "
        "{%0,%1,%2,%3}, {%4,%5,%6,%7}, {%8,%9}, {%0,%1,%2,%3};"
        : "+f"(d[0]), "+f"(d[1]), "+f"(d[2]), "+f"(d[3])
        : "r"(a[0]), "r"(a[1]), "r"(a[2]), "r"(a[3]), "r"(b[0]), "r"(b[1]));
}

__device__ __forceinline__ void mma_f16(float* d, const uint32_t* a,
                                        const uint32_t* b) {
    asm volatile(
        "mma.sync.aligned.m16n8k16.row.col.f32.f16.f16.f32 "
        "{%0,%1,%2,%3}, {%4,%5,%6,%7}, {%8,%9}, {%0,%1,%2,%3};"
        : "+f"(d[0]), "+f"(d[1]), "+f"(d[2]), "+f"(d[3])
        : "r"(a[0]), "r"(a[1]), "r"(a[2]), "r"(a[3]), "r"(b[0]), "r"(b[1]));
}

__device__ __forceinline__ uint32_t cvt_bf16x2(float hi_elem, float lo_elem) {
    uint32_t r;
    asm("cvt.rn.satfinite.bf16x2.f32 %0, %1, %2;"
        : "=r"(r) : "f"(hi_elem), "f"(lo_elem));
    return r;
}

__device__ __forceinline__ uint32_t pack_h2(float lo_elem, float hi_elem) {
    __half2 h = __floats2half2_rn(lo_elem, hi_elem);   // .x = lo bits
    return *reinterpret_cast<uint32_t*>(&h);
}

__device__ __forceinline__ float ex2f(float x) {
    float y;
    asm("ex2.approx.ftz.f32 %0, %1;" : "=f"(y) : "f"(x));
    return y;
}

// XOR swizzles: conflict-free ldmatrix on unpadded rows.
#define SWZ128B(r, ch) ((((ch) ^ ((r) & 7)) << 4))
#define SWZ64B(r, ch)  ((((ch) ^ (((r) >> 1) & 3)) << 4))

__device__ __forceinline__ int inc3(int x) { return (x == 2) ? 0 : x + 1; }

// ===========================================================================
// Prep: split 3 inputs (grid.y selects tensor); split 4 weights (grid.z)
// ===========================================================================
__global__ __launch_bounds__(256)
void split3(const float4* __restrict__ x0, const float4* __restrict__ x1,
            const float4* __restrict__ x2,
            __nv_bfloat16* __restrict__ h0, __nv_bfloat16* __restrict__ l0,
            __nv_bfloat16* __restrict__ h1, __nv_bfloat16* __restrict__ l1,
            __nv_bfloat16* __restrict__ h2, __nv_bfloat16* __restrict__ l2,
            int n4) {
    int i = blockIdx.x * blockDim.x + threadIdx.x;
    if (i >= n4) return;
    const int z = blockIdx.y;
    const float4* x = (z == 0) ? x0 : (z == 1) ? x1 : x2;
    __nv_bfloat16* hi = (z == 0) ? h0 : (z == 1) ? h1 : h2;
    __nv_bfloat16* lo = (z == 0) ? l0 : (z == 1) ? l1 : l2;
    float4 v = x[i];
    float f[4] = {v.x, v.y, v.z, v.w};
    __nv_bfloat16 h[4], l[4];
#pragma unroll
    for (int j = 0; j < 4; ++j) {
        h[j] = __float2bfloat16_rn(f[j]);
        l[j] = __float2bfloat16_rn(f[j] - __bfloat162float(h[j]));
    }
    ((__nv_bfloat162*)hi)[i * 2 + 0] = __nv_bfloat162(h[0], h[1]);
    ((__nv_bfloat162*)hi)[i * 2 + 1] = __nv_bfloat162(h[2], h[3]);
    ((__nv_bfloat162*)lo)[i * 2 + 0] = __nv_bfloat162(l[0], l[1]);
    ((__nv_bfloat162*)lo)[i * 2 + 1] = __nv_bfloat162(l[2], l[3]);
}

__global__ __launch_bounds__(256)
void wtsplit4(const float* __restrict__ w0, const float* __restrict__ w1,
              const float* __restrict__ w2, const float* __restrict__ w3,
              __nv_bfloat16* __restrict__ hi4, __nv_bfloat16* __restrict__ lo4) {
    __shared__ float t[32][33];
    const int z = blockIdx.z;
    const float* W = (z == 0) ? w0 : (z == 1) ? w1 : (z == 2) ? w2 : w3;
    __nv_bfloat16* hi = hi4 + (size_t)z * DM_ * DM_;
    __nv_bfloat16* lo = lo4 + (size_t)z * DM_ * DM_;
    const int n0 = blockIdx.x * 32;
    const int k0 = blockIdx.y * 32;
    const int tx = threadIdx.x, ty = threadIdx.y;
#pragma unroll
    for (int i = 0; i < 4; ++i)
        t[ty + i * 8][tx] = W[(size_t)(k0 + ty + i * 8) * DM_ + n0 + tx];
    __syncthreads();
#pragma unroll
    for (int i = 0; i < 4; ++i) {
        float v = t[tx][ty + i * 8];
        __nv_bfloat16 h = __float2bfloat16_rn(v);
        __nv_bfloat16 l = __float2bfloat16_rn(v - __bfloat162float(h));
        size_t o = (size_t)(n0 + ty + i * 8) * DM_ + k0 + tx;
        hi[o] = h;
        lo[o] = l;
    }
}

// ===========================================================================
// HMMA GEMM (bf16 hi/lo x3): 3-stage cp.async ring, 1 sync/ktile,
// XOR-swizzled 64B rows. 2 CTAs/SM. Epilogue: fp32 / bf16 hi-lo / fp16 hi-lo.
// ===========================================================================
#define BM 128
#define BN 128
#define BK 32
#define NKT (DM_ / BK)            // 32
#define GT_TILE 8192              // 128 rows * 64B
#define GT_STAGE (4 * GT_TILE)    // 32768
#define GEMM_SMEM (3 * GT_STAGE)  // 98304

__device__ __forceinline__ void load_ktile(uint32_t sb, int kt, int stage,
                                           const __nv_bfloat16* Ahi,
                                           const __nv_bfloat16* Alo,
                                           const __nv_bfloat16* Bhi,
                                           const __nv_bfloat16* Blo,
                                           int rowBase, int colBase) {
    const int tid = threadIdx.x;
    const uint32_t base = sb + stage * GT_STAGE;
    const __nv_bfloat16* srcs[4] = {
        Ahi + (size_t)rowBase * DM_ + kt * BK,
        Alo + (size_t)rowBase * DM_ + kt * BK,
        Bhi + (size_t)colBase * DM_ + kt * BK,
        Blo + (size_t)colBase * DM_ + kt * BK};
#pragma unroll
    for (int t = 0; t < 4; ++t) {
#pragma unroll
        for (int i = 0; i < 2; ++i) {
            int c = tid + i * 256;
            int r = c >> 2, ch = c & 3;
            cp16(base + t * GT_TILE + r * 64 + SWZ64B(r, ch),
                 srcs[t] + (size_t)r * DM_ + ch * 8);
        }
    }
}

__device__ __forceinline__ void gemm_body(
    const __nv_bfloat16* __restrict__ Ahi, const __nv_bfloat16* __restrict__ Alo,
    const __nv_bfloat16* __restrict__ Bhi, const __nv_bfloat16* __restrict__ Blo,
    const float* __restrict__ bias, float* __restrict__ C,
    __nv_bfloat16* __restrict__ Chi, __nv_bfloat16* __restrict__ Clo,
    bool toHalf, char* smem) {
    const uint32_t sb = smem_u32(smem);
    const int tid  = threadIdx.x;
    const int wid  = tid >> 5;
    const int lane = tid & 31;
    const int rowBase = blockIdx.y * BM;
    const int colBase = blockIdx.x * BN;

    const int mbase = (wid >> 1) * 32;
    const int nbase = (wid & 1) * 64;

    float acc[2][8][4];
#pragma unroll
    for (int i = 0; i < 2; ++i)
#pragma unroll
        for (int j = 0; j < 8; ++j)
#pragma unroll
            for (int q = 0; q < 4; ++q) acc[i][j][q] = 0.f;

    load_ktile(sb, 0, 0, Ahi, Alo, Bhi, Blo, rowBase, colBase);
    CP_COMMIT();
    load_ktile(sb, 1, 1, Ahi, Alo, Bhi, Blo, rowBase, colBase);
    CP_COMMIT();

    const int a_row = lane & 15;
    const int a_kb  = lane >> 4;
    const int b_row = ((lane >> 4) & 1) * 8 + (lane & 7);
    const int b_kb  = (lane >> 3) & 1;

    int cur = 0, pf = 2;
    for (int kt = 0; kt < NKT; ++kt) {
        if (kt + 1 < NKT) { CP_WAIT(1); } else { CP_WAIT(0); }
        __syncthreads();
        if (kt + 2 < NKT) {
            load_ktile(sb, kt + 2, pf, Ahi, Alo, Bhi, Blo, rowBase, colBase);
            CP_COMMIT();
        }

        const uint32_t st = sb + cur * GT_STAGE;
#pragma unroll
        for (int s = 0; s < 2; ++s) {
            uint32_t ah[2][4], al[2][4];
#pragma unroll
            for (int i = 0; i < 2; ++i) {
                int row = mbase + i * 16 + a_row;
                uint32_t off = row * 64 + SWZ64B(row, s * 2 + a_kb);
                ldmx4(ah[i], st + 0 * GT_TILE + off);
                ldmx4(al[i], st + 1 * GT_TILE + off);
            }
#pragma unroll
            for (int jp = 0; jp < 4; ++jp) {
                int row = nbase + jp * 16 + b_row;
                uint32_t off = row * 64 + SWZ64B(row, s * 2 + b_kb);
                uint32_t th[4], tl[4];
                ldmx4(th, st + 2 * GT_TILE + off);
                ldmx4(tl, st + 3 * GT_TILE + off);
                uint32_t b0h[2] = {th[0], th[1]}, b1h[2] = {th[2], th[3]};
                uint32_t b0l[2] = {tl[0], tl[1]}, b1l[2] = {tl[2], tl[3]};
#pragma unroll
                for (int i = 0; i < 2; ++i) {
                    mma_bf16(acc[i][jp * 2],     ah[i], b0h);
                    mma_bf16(acc[i][jp * 2 + 1], ah[i], b1h);
                    mma_bf16(acc[i][jp * 2],     ah[i], b0l);
                    mma_bf16(acc[i][jp * 2 + 1], ah[i], b1l);
                    mma_bf16(acc[i][jp * 2],     al[i], b0h);
                    mma_bf16(acc[i][jp * 2 + 1], al[i], b1h);
                }
            }
        }
        cur = inc3(cur);
        pf  = inc3(pf);
    }

#pragma unroll
    for (int i = 0; i < 2; ++i) {
        const int r0 = rowBase + mbase + i * 16 + (lane >> 2);
#pragma unroll
        for (int j = 0; j < 8; ++j) {
            const int col = colBase + nbase + j * 8 + (lane & 3) * 2;
            const float b0 = bias[col], b1 = bias[col + 1];
            float f0 = acc[i][j][0] + b0, f1 = acc[i][j][1] + b1;
            float f2 = acc[i][j][2] + b0, f3 = acc[i][j][3] + b1;
            if (C) {
                *(float2*)(C + (size_t)r0 * DM_ + col)       = make_float2(f0, f1);
                *(float2*)(C + (size_t)(r0 + 8) * DM_ + col) = make_float2(f2, f3);
            } else if (toHalf) {
                // fp16 hi/lo split (for V: PV runs on f16 MMAs)
                __half2 hh01 = __floats2half2_rn(f0, f1);
                __half2 hh23 = __floats2half2_rn(f2, f3);
                float r0f = f0 - __half2float(__low2half(hh01));
                float r1f = f1 - __half2float(__high2half(hh01));
                float r2f = f2 - __half2float(__low2half(hh23));
                float r3f = f3 - __half2float(__high2half(hh23));
                __half2 hl01 = __floats2half2_rn(r0f, r1f);
                __half2 hl23 = __floats2half2_rn(r2f, r3f);
                *(uint32_t*)(Chi + (size_t)r0 * DM_ + col)       = *(uint32_t*)&hh01;
                *(uint32_t*)(Chi + (size_t)(r0 + 8) * DM_ + col) = *(uint32_t*)&hh23;
                *(uint32_t*)(Clo + (size_t)r0 * DM_ + col)       = *(uint32_t*)&hl01;
                *(uint32_t*)(Clo + (size_t)(r0 + 8) * DM_ + col) = *(uint32_t*)&hl23;
            } else {
                uint32_t h01 = cvt_bf16x2(f1, f0);
                uint32_t h23 = cvt_bf16x2(f3, f2);
                float r0f = f0 - __uint_as_float(h01 << 16);
                float r1f = f1 - __uint_as_float(h01 & 0xFFFF0000u);
                float r2f = f2 - __uint_as_float(h23 << 16);
                float r3f = f3 - __uint_as_float(h23 & 0xFFFF0000u);
                uint32_t l01 = cvt_bf16x2(r1f, r0f);
                uint32_t l23 = cvt_bf16x2(r3f, r2f);
                *(uint32_t*)(Chi + (size_t)r0 * DM_ + col)       = h01;
                *(uint32_t*)(Chi + (size_t)(r0 + 8) * DM_ + col) = h23;
                *(uint32_t*)(Clo + (size_t)r0 * DM_ + col)       = l01;
                *(uint32_t*)(Clo + (size_t)(r0 + 8) * DM_ + col) = l23;
            }
        }
    }
}

__global__ __launch_bounds__(256, 2)
void gemm_qkv(const __nv_bfloat16* __restrict__ Ah0, const __nv_bfloat16* __restrict__ Al0,
              const __nv_bfloat16* __restrict__ Ah1, const __nv_bfloat16* __restrict__ Al1,
              const __nv_bfloat16* __restrict__ Ah2, const __nv_bfloat16* __restrict__ Al2,
              const __nv_bfloat16* __restrict__ Wh4, const __nv_bfloat16* __restrict__ Wl4,
              const float* __restrict__ b0, const float* __restrict__ b1,
              const float* __restrict__ b2,
              __nv_bfloat16* __restrict__ Ch0, __nv_bfloat16* __restrict__ Cl0,
              __nv_bfloat16* __restrict__ Ch1, __nv_bfloat16* __restrict__ Cl1,
              __nv_bfloat16* __restrict__ Ch2, __nv_bfloat16* __restrict__ Cl2) {
    extern __shared__ char smem[];
    const int z = blockIdx.z;
    const __nv_bfloat16* Ah = (z == 0) ? Ah0 : (z == 1) ? Ah1 : Ah2;
    const __nv_bfloat16* Al = (z == 0) ? Al0 : (z == 1) ? Al1 : Al2;
    const float* bias = (z == 0) ? b0 : (z == 1) ? b1 : b2;
    __nv_bfloat16* Ch = (z == 0) ? Ch0 : (z == 1) ? Ch1 : Ch2;
    __nv_bfloat16* Cl = (z == 0) ? Cl0 : (z == 1) ? Cl1 : Cl2;
    gemm_body(Ah, Al, Wh4 + (size_t)z * DM_ * DM_, Wl4 + (size_t)z * DM_ * DM_,
              bias, nullptr, Ch, Cl, /*toHalf=*/(z == 2), smem);
}

__global__ __launch_bounds__(256, 2)
void gemm_o(const __nv_bfloat16* __restrict__ Ahi, const __nv_bfloat16* __restrict__ Alo,
            const __nv_bfloat16* __restrict__ Whi, const __nv_bfloat16* __restrict__ Wlo,
            const float* __restrict__ bias, float* __restrict__ C) {
    extern __shared__ char smem[];
    gemm_body(Ahi, Alo, Whi, Wlo, bias, C, nullptr, nullptr, false, smem);
}

// ===========================================================================
// Flash attention v7: cross-tile pipeline + PV on fp16 (2 passes).
// QK: bf16 x3 (unchanged). P packed to single fp16; V is fp16 hi/lo.
// K ring[2] + V ring[2] + persistent Qhi/Qlo. 128 q-rows/CTA, 2 CTAs/SM.
// ===========================================================================
#define KTT  8192                  // 64 rows * 128B (one of hi/lo)
#define KSTG (2 * KTT)             // 16384
#define FQT  16384                 // 128 rows * 128B
#define FA7_SMEM (4 * KSTG + 2 * FQT)  // 98304

#define C2F 0.1803368801111204f    // log2(e)/8 (Dh=64 scale folded into exp2)
#define NT_ (S_ / 64)              // 32 kv tiles

__device__ __forceinline__ void fa_load_pair(uint32_t dst,
    const __nv_bfloat16* Hi, const __nv_bfloat16* Lo,
    size_t rowStart, int k0, int colOff) {
    const int tid = threadIdx.x;
    const __nv_bfloat16* srcs[2] = {Hi + (rowStart + k0) * DM_ + colOff,
                                    Lo + (rowStart + k0) * DM_ + colOff};
#pragma unroll
    for (int i = 0; i < 4; ++i) {
        int c = tid + i * 256;           // 0..1023
        int t = c >> 9, r = (c >> 3) & 63, ch = c & 7;
        cp16(dst + t * KTT + r * 128 + SWZ128B(r, ch),
             srcs[t] + (size_t)r * DM_ + ch * 8);
    }
}

// QK for one tile: s = Q(smem hi/lo) @ K(smem hi/lo)^T, x3 bf16 passes.
__device__ __forceinline__ void qk_tile(
    uint32_t ksBase, uint32_t sQh, uint32_t sQl,
    int qrow, int a_kb, int b_row, int b_kb, float (&s)[8][4]) {
#pragma unroll
    for (int j = 0; j < 8; ++j)
#pragma unroll
        for (int q = 0; q < 4; ++q) s[j][q] = 0.f;
#pragma unroll
    for (int ks = 0; ks < 4; ++ks) {
        uint32_t qh[4], ql[4];
        const uint32_t qoff = qrow * 128 + SWZ128B(qrow, ks * 2 + a_kb);
        ldmx4(qh, sQh + qoff);
        ldmx4(ql, sQl + qoff);
#pragma unroll
        for (int ntp = 0; ntp < 4; ++ntp) {
            const int krow = ntp * 16 + b_row;
            const uint32_t koff = krow * 128 + SWZ128B(krow, ks * 2 + b_kb);
            uint32_t th[4], tl[4];
            ldmx4(th, ksBase + koff);
            ldmx4(tl, ksBase + KTT + koff);
            uint32_t k0h[2] = {th[0], th[1]}, k1h[2] = {th[2], th[3]};
            uint32_t k0l[2] = {tl[0], tl[1]}, k1l[2] = {tl[2], tl[3]};
            mma_bf16(s[2 * ntp],     qh, k0h);
            mma_bf16(s[2 * ntp + 1], qh, k1h);
            mma_bf16(s[2 * ntp],     qh, k0l);
            mma_bf16(s[2 * ntp + 1], qh, k1l);
            mma_bf16(s[2 * ntp],     ql, k0h);
            mma_bf16(s[2 * ntp + 1], ql, k1h);
        }
    }
}

// online softmax + pack P to single fp16 fragments (no P-lo).
__device__ __forceinline__ void softmax_pack(
    float (&s)[8][4], float (&o)[8][4],
    float& m0, float& m1, float& l0, float& l1,
    uint32_t (&Pa)[8], uint32_t (&Pb)[8]) {
    float rmax0 = -1e30f, rmax1 = -1e30f;
#pragma unroll
    for (int j = 0; j < 8; ++j) {
        rmax0 = fmaxf(rmax0, fmaxf(s[j][0], s[j][1]));
        rmax1 = fmaxf(rmax1, fmaxf(s[j][2], s[j][3]));
    }
    rmax0 = fmaxf(rmax0, __shfl_xor_sync(0xffffffffu, rmax0, 1));
    rmax0 = fmaxf(rmax0, __shfl_xor_sync(0xffffffffu, rmax0, 2));
    rmax1 = fmaxf(rmax1, __shfl_xor_sync(0xffffffffu, rmax1, 1));
    rmax1 = fmaxf(rmax1, __shfl_xor_sync(0xffffffffu, rmax1, 2));
    const float m0n = fmaxf(m0, rmax0);
    const float m1n = fmaxf(m1, rmax1);
    const float c0 = ex2f((m0 - m0n) * C2F);
    const float c1 = ex2f((m1 - m1n) * C2F);
    m0 = m0n; m1 = m1n;
    const float mc0 = m0 * C2F, mc1 = m1 * C2F;
    float sum0 = 0.f, sum1 = 0.f;
#pragma unroll
    for (int j = 0; j < 8; ++j) {
        s[j][0] = ex2f(fmaf(s[j][0], C2F, -mc0));
        s[j][1] = ex2f(fmaf(s[j][1], C2F, -mc0));
        s[j][2] = ex2f(fmaf(s[j][2], C2F, -mc1));
        s[j][3] = ex2f(fmaf(s[j][3], C2F, -mc1));
        sum0 += s[j][0] + s[j][1];
        sum1 += s[j][2] + s[j][3];
    }
    sum0 += __shfl_xor_sync(0xffffffffu, sum0, 1);
    sum0 += __shfl_xor_sync(0xffffffffu, sum0, 2);
    sum1 += __shfl_xor_sync(0xffffffffu, sum1, 1);
    sum1 += __shfl_xor_sync(0xffffffffu, sum1, 2);
    l0 = l0 * c0 + sum0;
    l1 = l1 * c1 + sum1;
#pragma unroll
    for (int j = 0; j < 8; ++j) {
        Pa[j] = pack_h2(s[j][0], s[j][1]);
        Pb[j] = pack_h2(s[j][2], s[j][3]);
    }
#pragma unroll
    for (int j = 0; j < 8; ++j) {
        o[j][0] *= c0; o[j][1] *= c0;
        o[j][2] *= c1; o[j][3] *= c1;
    }
}

// O += P @ V: fp16 2-pass (P single x Vhi, P x Vlo). vsBase: Vhi +0, Vlo +KTT.
__device__ __forceinline__ void pv_accum(
    uint32_t vsBase, int v_k, int v_db,
    const uint32_t (&Pa)[8], const uint32_t (&Pb)[8],
    float (&o)[8][4]) {
#pragma unroll
    for (int ks = 0; ks < 4; ++ks) {
        uint32_t ap[4] = {Pa[2 * ks], Pb[2 * ks],
                          Pa[2 * ks + 1], Pb[2 * ks + 1]};
        const int vrow = 16 * ks + v_k;
#pragma unroll
        for (int dt = 0; dt < 4; ++dt) {
            const uint32_t off = vrow * 128 + SWZ128B(vrow, dt * 2 + v_db);
            uint32_t vh[4], vl[4];
            ldmx4t(vh, vsBase + off);
            ldmx4t(vl, vsBase + KTT + off);
            uint32_t b0h[2] = {vh[0], vh[1]}, b1h[2] = {vh[2], vh[3]};
            uint32_t b0l[2] = {vl[0], vl[1]}, b1l[2] = {vl[2], vl[3]};
            mma_f16(o[2 * dt],     ap, b0h);
            mma_f16(o[2 * dt + 1], ap, b1h);
            mma_f16(o[2 * dt],     ap, b0l);
            mma_f16(o[2 * dt + 1], ap, b1l);
        }
    }
}

__global__ __launch_bounds__(256, 2)
void flash_mma7(const __nv_bfloat16* __restrict__ Qhi,
                const __nv_bfloat16* __restrict__ Qlo,
                const __nv_bfloat16* __restrict__ Khi,
                const __nv_bfloat16* __restrict__ Klo,
                const __nv_bfloat16* __restrict__ Vhi,   // fp16 bits
                const __nv_bfloat16* __restrict__ Vlo,   // fp16 bits
                __nv_bfloat16* __restrict__ AOh,
                __nv_bfloat16* __restrict__ AOl) {
    extern __shared__ char smem[];
    const uint32_t sb = smem_u32(smem);
    const int tid = threadIdx.x, wid = tid >> 5, lane = tid & 31;
    const int bh = blockIdx.y, b = bh >> 4, h = bh & 15;
    const int q0 = blockIdx.x * 128;
    const size_t rowStart = (size_t)b * S_;
    const int colOff = h * DH_;

    // smem layout
    const uint32_t Ks0 = sb;
    const uint32_t Ks1 = sb + KSTG;
    const uint32_t Vs0 = sb + 2 * KSTG;
    const uint32_t Vs1 = sb + 3 * KSTG;
    const uint32_t sQh = sb + 4 * KSTG;
    const uint32_t sQl = sQh + FQT;

    // ---- prologue loads ----
    {
        const __nv_bfloat16* qsrc[2] = {Qhi + (rowStart + q0) * DM_ + colOff,
                                        Qlo + (rowStart + q0) * DM_ + colOff};
        const uint32_t qdst[2] = {sQh, sQl};
#pragma unroll
        for (int i = 0; i < 8; ++i) {
            int c = tid + i * 256;           // 0..2047
            int t = c >> 10, r = (c >> 3) & 127, ch = c & 7;
            cp16(qdst[t] + r * 128 + SWZ128B(r, ch),
                 qsrc[t] + (size_t)r * DM_ + ch * 8);
        }
    }
    fa_load_pair(Ks0, Khi, Klo, rowStart, 0, colOff);
    fa_load_pair(Vs0, Vhi, Vlo, rowStart, 0, colOff);
    CP_COMMIT();
    fa_load_pair(Ks1, Khi, Klo, rowStart, 64, colOff);
    CP_COMMIT();
    CP_WAIT(0);
    __syncthreads();

    // fragment addressing
    const int a_row = lane & 15;
    const int a_kb  = lane >> 4;
    const int b_row = ((lane >> 4) & 1) * 8 + (lane & 7);
    const int b_kb  = (lane >> 3) & 1;
    const int v_k   = (lane & 7) + ((lane >> 3) & 1) * 8;
    const int v_db  = (lane >> 4) & 1;
    const int qrow  = 16 * wid + a_row;

    float m0 = -1e30f, m1 = -1e30f, l0 = 0.f, l1 = 0.f;
    float o[8][4];
#pragma unroll
    for (int j = 0; j < 8; ++j)
#pragma unroll
        for (int q = 0; q < 4; ++q) o[j][q] = 0.f;

    // ---- software-pipeline prologue: s(0) ----
    float s[8][4];
    qk_tile(Ks0, sQh, sQl, qrow, a_kb, b_row, b_kb, s);

    // ---- main loop ----
    for (int jt = 0; jt < NT_ - 1; ++jt) {
        CP_WAIT(0);
        __syncthreads();                 // K(jt+1), V(jt) resident
        const int kc = (jt + 2 < NT_) ? (jt + 2) : (NT_ - 1);
        fa_load_pair((jt & 1) ? Ks1 : Ks0, Khi, Klo, rowStart, kc * 64, colOff);
        fa_load_pair(((jt + 1) & 1) ? Vs1 : Vs0, Vhi, Vlo, rowStart,
                     (jt + 1) * 64, colOff);
        CP_COMMIT();

        uint32_t Pa[8], Pb[8];
        softmax_pack(s, o, m0, m1, l0, l1, Pa, Pb);
        qk_tile(((jt + 1) & 1) ? Ks1 : Ks0, sQh, sQl, qrow, a_kb, b_row, b_kb, s);
        pv_accum((jt & 1) ? Vs1 : Vs0, v_k, v_db, Pa, Pb, o);
    }

    // ---- tail: jt = NT_-1 ----
    CP_WAIT(0);
    __syncthreads();
    {
        uint32_t Pa[8], Pb[8];
        softmax_pack(s, o, m0, m1, l0, l1, Pa, Pb);
        pv_accum(((NT_ - 1) & 1) ? Vs1 : Vs0, v_k, v_db, Pa, Pb, o);
    }

    // ---- normalize, split to bf16 hi/lo, write ----
    const float i0 = 1.f / l0, i1 = 1.f / l1;
    const size_t row0 = rowStart + q0 + 16 * wid + (lane >> 2);
    const size_t row1 = row0 + 8;
#pragma unroll
    for (int j = 0; j < 8; ++j) {
        const int col = colOff + j * 8 + (lane & 3) * 2;
        float f0 = o[j][0] * i0, f1 = o[j][1] * i0;
        float f2 = o[j][2] * i1, f3 = o[j][3] * i1;
        uint32_t h01 = cvt_bf16x2(f1, f0);
        uint32_t h23 = cvt_bf16x2(f3, f2);
        float r0f = f0 - __uint_as_float(h01 << 16);
        float r1f = f1 - __uint_as_float(h01 & 0xFFFF0000u);
        float r2f = f2 - __uint_as_float(h23 << 16);
        float r3f = f3 - __uint_as_float(h23 & 0xFFFF0000u);
        uint32_t l01 = cvt_bf16x2(r1f, r0f);
        uint32_t l23 = cvt_bf16x2(r3f, r2f);
        *(uint32_t*)(AOh + row0 * DM_ + col) = h01;
        *(uint32_t*)(AOh + row1 * DM_ + col) = h23;
        *(uint32_t*)(AOl + row0 * DM_ + col) = l01;
        *(uint32_t*)(AOl + row1 * DM_ + col) = l23;
    }
}

// ===========================================================================
// Launch
// ===========================================================================
extern "C" void kernel_launch(void* const* d_in, const int* in_sizes, int n_in,
                              void* d_out, int out_size)
{
    const float* query = (const float*)d_in[0];
    const float* key   = (const float*)d_in[1];
    const float* value = (const float*)d_in[2];
    const float* Wq    = (const float*)d_in[3];
    const float* bq    = (const float*)d_in[4];
    const float* Wk    = (const float*)d_in[5];
    const float* bk    = (const float*)d_in[6];
    const float* Wv    = (const float*)d_in[7];
    const float* bv    = (const float*)d_in[8];
    const float* Wo    = (const float*)d_in[9];
    const float* bo    = (const float*)d_in[10];
    float* out = (float*)d_out;

    __nv_bfloat16 *pIh, *pIl, *pWh, *pWl;
    __nv_bfloat16 *pQh, *pQl, *pKh, *pKl, *pVh, *pVl, *pAOh, *pAOl;
    cudaGetSymbolAddress((void**)&pIh,  g_Ih);
    cudaGetSymbolAddress((void**)&pIl,  g_Il);
    cudaGetSymbolAddress((void**)&pWh,  g_W4h);
    cudaGetSymbolAddress((void**)&pWl,  g_W4l);
    cudaGetSymbolAddress((void**)&pQh,  g_Qh);
    cudaGetSymbolAddress((void**)&pQl,  g_Ql);
    cudaGetSymbolAddress((void**)&pKh,  g_Kh);
    cudaGetSymbolAddress((void**)&pKl,  g_Kl);
    cudaGetSymbolAddress((void**)&pVh,  g_Vh);
    cudaGetSymbolAddress((void**)&pVl,  g_Vl);
    cudaGetSymbolAddress((void**)&pAOh, g_AOh);
    cudaGetSymbolAddress((void**)&pAOl, g_AOl);

    const size_t NTOK = (size_t)ROWS_ * DM_;

    static bool attrs_set = false;
    if (!attrs_set) {
        cudaFuncSetAttribute(gemm_qkv, cudaFuncAttributeMaxDynamicSharedMemorySize, GEMM_SMEM);
        cudaFuncSetAttribute(gemm_o,   cudaFuncAttributeMaxDynamicSharedMemorySize, GEMM_SMEM);
        cudaFuncSetAttribute(flash_mma7, cudaFuncAttributeMaxDynamicSharedMemorySize, FA7_SMEM);
        attrs_set = true;
    }

    const int n4 = ROWS_ * DM_ / 4;

    // 1) split all three inputs
    split3<<<dim3((n4 + 255) / 256, 3), 256>>>(
        (const float4*)query, (const float4*)key, (const float4*)value,
        pIh + 0 * NTOK, pIl + 0 * NTOK,
        pIh + 1 * NTOK, pIl + 1 * NTOK,
        pIh + 2 * NTOK, pIl + 2 * NTOK, n4);

    // 2) split+transpose all four weights
    wtsplit4<<<dim3(32, 32, 4), dim3(32, 8)>>>(Wq, Wk, Wv, Wo, pWh, pWl);

    // 3) Q,K,V projections (batched; V epilogue -> fp16 hi/lo)
    gemm_qkv<<<dim3(DM_ / BN, ROWS_ / BM, 3), 256, GEMM_SMEM>>>(
        pIh + 0 * NTOK, pIl + 0 * NTOK,
        pIh + 1 * NTOK, pIl + 1 * NTOK,
        pIh + 2 * NTOK, pIl + 2 * NTOK,
        pWh, pWl, bq, bk, bv,
        pQh, pQl, pKh, pKl, pVh, pVl);

    // 4) attention (PV on fp16, 2 passes; writes bf16 hi/lo)
    flash_mma7<<<dim3(S_ / 128, B_ * NH_), 256, FA7_SMEM>>>(
        pQh, pQl, pKh, pKl, pVh, pVl, pAOh, pAOl);

    // 5) output projection (fp32 result)
    gemm_o<<<dim3(DM_ / BN, ROWS_ / BM), 256, GEMM_SMEM>>>(
        pAOh, pAOl,
        pWh + 3 * (size_t)DM_ * DM_, pWl + 3 * (size_t)DM_ * DM_,
        bo, out);
}

// round 11
// speedup vs baseline: 1.2500x; 1.1049x over previous
#include <cuda_runtime.h>
#include <cuda_bf16.h>
#include <cuda_fp16.h>
#include <math.h>
#include <cstdint>

// ---------------------------------------------------------------------------
// Problem constants
// ---------------------------------------------------------------------------
#define B_    4
#define S_    2048
#define DM_   1024
#define NH_   16
#define DH_   64
#define ROWS_ (B_ * S_)          // 8192

// ---------------------------------------------------------------------------
// Scratch (device globals: allocation-free per harness rules)
// g_Qh holds fp16 single; g_Kh/g_Kl, g_Vh/g_Vl hold fp16 hi/lo bits.
// ---------------------------------------------------------------------------
__device__ __nv_bfloat16 g_Ih[3][ROWS_ * DM_];   // split inputs (q,k,v) hi
__device__ __nv_bfloat16 g_Il[3][ROWS_ * DM_];   // split inputs lo
__device__ __nv_bfloat16 g_W4h[4][DM_ * DM_];    // W^T hi (q,k,v,o)
__device__ __nv_bfloat16 g_W4l[4][DM_ * DM_];    // W^T lo
__device__ __nv_bfloat16 g_Qh[ROWS_ * DM_];      // fp16 single
__device__ __nv_bfloat16 g_Kh[ROWS_ * DM_];      // fp16 hi
__device__ __nv_bfloat16 g_Kl[ROWS_ * DM_];      // fp16 lo
__device__ __nv_bfloat16 g_Vh[ROWS_ * DM_];      // fp16 hi
__device__ __nv_bfloat16 g_Vl[ROWS_ * DM_];      // fp16 lo
__device__ __nv_bfloat16 g_AOh[ROWS_ * DM_];
__device__ __nv_bfloat16 g_AOl[ROWS_ * DM_];

// ===========================================================================
// Generic-PTX helpers (legal on plain sm_103 target: sm_80+ instructions)
// ===========================================================================
__device__ __forceinline__ uint32_t smem_u32(const void* p) {
    uint32_t a;
    asm("{ .reg .u64 t; cvta.to.shared.u64 t, %1; cvt.u32.u64 %0, t; }"
        : "=r"(a) : "l"(p));
    return a;
}

__device__ __forceinline__ void cp16(uint32_t s, const void* g) {
    asm volatile("cp.async.cg.shared.global [%0], [%1], 16;" :: "r"(s), "l"(g));
}
#define CP_COMMIT() asm volatile("cp.async.commit_group;" ::: "memory")
#define CP_WAIT(n)  asm volatile("cp.async.wait_group %0;" :: "n"(n) : "memory")

__device__ __forceinline__ void ldmx4(uint32_t* r, uint32_t addr) {
    asm volatile("ldmatrix.sync.aligned.m8n8.x4.shared.b16 {%0,%1,%2,%3}, [%4];"
                 : "=r"(r[0]), "=r"(r[1]), "=r"(r[2]), "=r"(r[3]) : "r"(addr));
}

__device__ __forceinline__ void ldmx4t(uint32_t* r, uint32_t addr) {
    asm volatile("ldmatrix.sync.aligned.m8n8.x4.trans.shared.b16 {%0,%1,%2,%3}, [%4];"
                 : "=r"(r[0]), "=r"(r[1]), "=r"(r[2]), "=r"(r[3]) : "r"(addr));
}

__device__ __forceinline__ void mma_bf16(float* d, const uint32_t* a,
                                         const uint32_t* b) {
    asm volatile(
        "mma.sync.aligned.m16n8k16.row.col.f32.bf16.bf16.f32 "
        "{%0,%1,%2,%3}, {%4,%5,%6,%7}, {%8,%9}, {%0,%1,%2,%3};"
        : "+f"(d[0]), "+f"(d[1]), "+f"(d[2]), "+f"(d[3])
        : "r"(a[0]), "r"(a[1]), "r"(a[2]), "r"(a[3]), "r"(b[0]), "r"(b[1]));
}

__device__ __forceinline__ void mma_f16(float* d, const uint32_t* a,
                                        const uint32_t* b) {
    asm volatile(
        "mma.sync.aligned.m16n8k16.row.col.f32.f16.f16.f32 "
        "{%0,%1,%2,%3}, {%4,%5,%6,%7}, {%8,%9}, {%0,%1,%2,%3};"
        : "+f"(d[0]), "+f"(d[1]), "+f"(d[2]), "+f"(d[3])
        : "r"(a[0]), "r"(a[1]), "r"(a[2]), "r"(a[3]), "r"(b[0]), "r"(b[1]));
}

__device__ __forceinline__ uint32_t cvt_bf16x2(float hi_elem, float lo_elem) {
    uint32_t r;
    asm("cvt.rn.satfinite.bf16x2.f32 %0, %1, %2;"
        : "=r"(r) : "f"(hi_elem), "f"(lo_elem));
    return r;
}

__device__ __forceinline__ uint32_t pack_h2(float lo_elem, float hi_elem) {
    __half2 h = __floats2half2_rn(lo_elem, hi_elem);   // .x = lo bits
    return *reinterpret_cast<uint32_t*>(&h);
}

__device__ __forceinline__ float ex2f(float x) {
    float y;
    asm("ex2.approx.ftz.f32 %0, %1;" : "=f"(y) : "f"(x));
    return y;
}

// XOR swizzles: conflict-free ldmatrix on unpadded rows.
#define SWZ128B(r, ch) ((((ch) ^ ((r) & 7)) << 4))
#define SWZ64B(r, ch)  ((((ch) ^ (((r) >> 1) & 3)) << 4))

__device__ __forceinline__ int inc3(int x) { return (x == 2) ? 0 : x + 1; }

// ===========================================================================
// Prep: split 3 inputs (grid.y selects tensor); split 4 weights (grid.z)
// ===========================================================================
__global__ __launch_bounds__(256)
void split3(const float4* __restrict__ x0, const float4* __restrict__ x1,
            const float4* __restrict__ x2,
            __nv_bfloat16* __restrict__ h0, __nv_bfloat16* __restrict__ l0,
            __nv_bfloat16* __restrict__ h1, __nv_bfloat16* __restrict__ l1,
            __nv_bfloat16* __restrict__ h2, __nv_bfloat16* __restrict__ l2,
            int n4) {
    int i = blockIdx.x * blockDim.x + threadIdx.x;
    if (i >= n4) return;
    const int z = blockIdx.y;
    const float4* x = (z == 0) ? x0 : (z == 1) ? x1 : x2;
    __nv_bfloat16* hi = (z == 0) ? h0 : (z == 1) ? h1 : h2;
    __nv_bfloat16* lo = (z == 0) ? l0 : (z == 1) ? l1 : l2;
    float4 v = x[i];
    float f[4] = {v.x, v.y, v.z, v.w};
    __nv_bfloat16 h[4], l[4];
#pragma unroll
    for (int j = 0; j < 4; ++j) {
        h[j] = __float2bfloat16_rn(f[j]);
        l[j] = __float2bfloat16_rn(f[j] - __bfloat162float(h[j]));
    }
    ((__nv_bfloat162*)hi)[i * 2 + 0] = __nv_bfloat162(h[0], h[1]);
    ((__nv_bfloat162*)hi)[i * 2 + 1] = __nv_bfloat162(h[2], h[3]);
    ((__nv_bfloat162*)lo)[i * 2 + 0] = __nv_bfloat162(l[0], l[1]);
    ((__nv_bfloat162*)lo)[i * 2 + 1] = __nv_bfloat162(l[2], l[3]);
}

__global__ __launch_bounds__(256)
void wtsplit4(const float* __restrict__ w0, const float* __restrict__ w1,
              const float* __restrict__ w2, const float* __restrict__ w3,
              __nv_bfloat16* __restrict__ hi4, __nv_bfloat16* __restrict__ lo4) {
    __shared__ float t[32][33];
    const int z = blockIdx.z;
    const float* W = (z == 0) ? w0 : (z == 1) ? w1 : (z == 2) ? w2 : w3;
    __nv_bfloat16* hi = hi4 + (size_t)z * DM_ * DM_;
    __nv_bfloat16* lo = lo4 + (size_t)z * DM_ * DM_;
    const int n0 = blockIdx.x * 32;
    const int k0 = blockIdx.y * 32;
    const int tx = threadIdx.x, ty = threadIdx.y;
#pragma unroll
    for (int i = 0; i < 4; ++i)
        t[ty + i * 8][tx] = W[(size_t)(k0 + ty + i * 8) * DM_ + n0 + tx];
    __syncthreads();
#pragma unroll
    for (int i = 0; i < 4; ++i) {
        float v = t[tx][ty + i * 8];
        __nv_bfloat16 h = __float2bfloat16_rn(v);
        __nv_bfloat16 l = __float2bfloat16_rn(v - __bfloat162float(h));
        size_t o = (size_t)(n0 + ty + i * 8) * DM_ + k0 + tx;
        hi[o] = h;
        lo[o] = l;
    }
}

// ===========================================================================
// HMMA GEMM (bf16 hi/lo x3): 3-stage cp.async ring, 1 sync/ktile,
// XOR-swizzled 64B rows. 2 CTAs/SM.
// Epilogue modes: 0 = fp32, 1 = fp16 hi/lo pair, 2 = fp16 single (hi only).
// ===========================================================================
#define BM 128
#define BN 128
#define BK 32
#define NKT (DM_ / BK)            // 32
#define GT_TILE 8192              // 128 rows * 64B
#define GT_STAGE (4 * GT_TILE)    // 32768
#define GEMM_SMEM (3 * GT_STAGE)  // 98304

__device__ __forceinline__ void load_ktile(uint32_t sb, int kt, int stage,
                                           const __nv_bfloat16* Ahi,
                                           const __nv_bfloat16* Alo,
                                           const __nv_bfloat16* Bhi,
                                           const __nv_bfloat16* Blo,
                                           int rowBase, int colBase) {
    const int tid = threadIdx.x;
    const uint32_t base = sb + stage * GT_STAGE;
    const __nv_bfloat16* srcs[4] = {
        Ahi + (size_t)rowBase * DM_ + kt * BK,
        Alo + (size_t)rowBase * DM_ + kt * BK,
        Bhi + (size_t)colBase * DM_ + kt * BK,
        Blo + (size_t)colBase * DM_ + kt * BK};
#pragma unroll
    for (int t = 0; t < 4; ++t) {
#pragma unroll
        for (int i = 0; i < 2; ++i) {
            int c = tid + i * 256;
            int r = c >> 2, ch = c & 3;
            cp16(base + t * GT_TILE + r * 64 + SWZ64B(r, ch),
                 srcs[t] + (size_t)r * DM_ + ch * 8);
        }
    }
}

__device__ __forceinline__ void gemm_body(
    const __nv_bfloat16* __restrict__ Ahi, const __nv_bfloat16* __restrict__ Alo,
    const __nv_bfloat16* __restrict__ Bhi, const __nv_bfloat16* __restrict__ Blo,
    const float* __restrict__ bias, float* __restrict__ C,
    __nv_bfloat16* __restrict__ Chi, __nv_bfloat16* __restrict__ Clo,
    int mode, char* smem) {
    const uint32_t sb = smem_u32(smem);
    const int tid  = threadIdx.x;
    const int wid  = tid >> 5;
    const int lane = tid & 31;
    const int rowBase = blockIdx.y * BM;
    const int colBase = blockIdx.x * BN;

    const int mbase = (wid >> 1) * 32;
    const int nbase = (wid & 1) * 64;

    float acc[2][8][4];
#pragma unroll
    for (int i = 0; i < 2; ++i)
#pragma unroll
        for (int j = 0; j < 8; ++j)
#pragma unroll
            for (int q = 0; q < 4; ++q) acc[i][j][q] = 0.f;

    load_ktile(sb, 0, 0, Ahi, Alo, Bhi, Blo, rowBase, colBase);
    CP_COMMIT();
    load_ktile(sb, 1, 1, Ahi, Alo, Bhi, Blo, rowBase, colBase);
    CP_COMMIT();

    const int a_row = lane & 15;
    const int a_kb  = lane >> 4;
    const int b_row = ((lane >> 4) & 1) * 8 + (lane & 7);
    const int b_kb  = (lane >> 3) & 1;

    int cur = 0, pf = 2;
    for (int kt = 0; kt < NKT; ++kt) {
        if (kt + 1 < NKT) { CP_WAIT(1); } else { CP_WAIT(0); }
        __syncthreads();
        if (kt + 2 < NKT) {
            load_ktile(sb, kt + 2, pf, Ahi, Alo, Bhi, Blo, rowBase, colBase);
            CP_COMMIT();
        }

        const uint32_t st = sb + cur * GT_STAGE;
#pragma unroll
        for (int s = 0; s < 2; ++s) {
            uint32_t ah[2][4], al[2][4];
#pragma unroll
            for (int i = 0; i < 2; ++i) {
                int row = mbase + i * 16 + a_row;
                uint32_t off = row * 64 + SWZ64B(row, s * 2 + a_kb);
                ldmx4(ah[i], st + 0 * GT_TILE + off);
                ldmx4(al[i], st + 1 * GT_TILE + off);
            }
#pragma unroll
            for (int jp = 0; jp < 4; ++jp) {
                int row = nbase + jp * 16 + b_row;
                uint32_t off = row * 64 + SWZ64B(row, s * 2 + b_kb);
                uint32_t th[4], tl[4];
                ldmx4(th, st + 2 * GT_TILE + off);
                ldmx4(tl, st + 3 * GT_TILE + off);
                uint32_t b0h[2] = {th[0], th[1]}, b1h[2] = {th[2], th[3]};
                uint32_t b0l[2] = {tl[0], tl[1]}, b1l[2] = {tl[2], tl[3]};
#pragma unroll
                for (int i = 0; i < 2; ++i) {
                    mma_bf16(acc[i][jp * 2],     ah[i], b0h);
                    mma_bf16(acc[i][jp * 2 + 1], ah[i], b1h);
                    mma_bf16(acc[i][jp * 2],     ah[i], b0l);
                    mma_bf16(acc[i][jp * 2 + 1], ah[i], b1l);
                    mma_bf16(acc[i][jp * 2],     al[i], b0h);
                    mma_bf16(acc[i][jp * 2 + 1], al[i], b1h);
                }
            }
        }
        cur = inc3(cur);
        pf  = inc3(pf);
    }

#pragma unroll
    for (int i = 0; i < 2; ++i) {
        const int r0 = rowBase + mbase + i * 16 + (lane >> 2);
#pragma unroll
        for (int j = 0; j < 8; ++j) {
            const int col = colBase + nbase + j * 8 + (lane & 3) * 2;
            const float b0 = bias[col], b1 = bias[col + 1];
            float f0 = acc[i][j][0] + b0, f1 = acc[i][j][1] + b1;
            float f2 = acc[i][j][2] + b0, f3 = acc[i][j][3] + b1;
            if (mode == 0) {
                *(float2*)(C + (size_t)r0 * DM_ + col)       = make_float2(f0, f1);
                *(float2*)(C + (size_t)(r0 + 8) * DM_ + col) = make_float2(f2, f3);
            } else {
                __half2 hh01 = __floats2half2_rn(f0, f1);
                __half2 hh23 = __floats2half2_rn(f2, f3);
                *(uint32_t*)(Chi + (size_t)r0 * DM_ + col)       = *(uint32_t*)&hh01;
                *(uint32_t*)(Chi + (size_t)(r0 + 8) * DM_ + col) = *(uint32_t*)&hh23;
                if (mode == 1) {
                    float r0f = f0 - __half2float(__low2half(hh01));
                    float r1f = f1 - __half2float(__high2half(hh01));
                    float r2f = f2 - __half2float(__low2half(hh23));
                    float r3f = f3 - __half2float(__high2half(hh23));
                    __half2 hl01 = __floats2half2_rn(r0f, r1f);
                    __half2 hl23 = __floats2half2_rn(r2f, r3f);
                    *(uint32_t*)(Clo + (size_t)r0 * DM_ + col)       = *(uint32_t*)&hl01;
                    *(uint32_t*)(Clo + (size_t)(r0 + 8) * DM_ + col) = *(uint32_t*)&hl23;
                }
            }
        }
    }
}

__global__ __launch_bounds__(256, 2)
void gemm_qkv(const __nv_bfloat16* __restrict__ Ah0, const __nv_bfloat16* __restrict__ Al0,
              const __nv_bfloat16* __restrict__ Ah1, const __nv_bfloat16* __restrict__ Al1,
              const __nv_bfloat16* __restrict__ Ah2, const __nv_bfloat16* __restrict__ Al2,
              const __nv_bfloat16* __restrict__ Wh4, const __nv_bfloat16* __restrict__ Wl4,
              const float* __restrict__ b0, const float* __restrict__ b1,
              const float* __restrict__ b2,
              __nv_bfloat16* __restrict__ Ch0, __nv_bfloat16* __restrict__ Cl0,
              __nv_bfloat16* __restrict__ Ch1, __nv_bfloat16* __restrict__ Cl1,
              __nv_bfloat16* __restrict__ Ch2, __nv_bfloat16* __restrict__ Cl2) {
    extern __shared__ char smem[];
    const int z = blockIdx.z;
    const __nv_bfloat16* Ah = (z == 0) ? Ah0 : (z == 1) ? Ah1 : Ah2;
    const __nv_bfloat16* Al = (z == 0) ? Al0 : (z == 1) ? Al1 : Al2;
    const float* bias = (z == 0) ? b0 : (z == 1) ? b1 : b2;
    __nv_bfloat16* Ch = (z == 0) ? Ch0 : (z == 1) ? Ch1 : Ch2;
    __nv_bfloat16* Cl = (z == 0) ? Cl0 : (z == 1) ? Cl1 : Cl2;
    // Q -> fp16 single (mode 2); K,V -> fp16 hi/lo (mode 1)
    gemm_body(Ah, Al, Wh4 + (size_t)z * DM_ * DM_, Wl4 + (size_t)z * DM_ * DM_,
              bias, nullptr, Ch, Cl, (z == 0) ? 2 : 1, smem);
}

__global__ __launch_bounds__(256, 2)
void gemm_o(const __nv_bfloat16* __restrict__ Ahi, const __nv_bfloat16* __restrict__ Alo,
            const __nv_bfloat16* __restrict__ Whi, const __nv_bfloat16* __restrict__ Wlo,
            const float* __restrict__ bias, float* __restrict__ C) {
    extern __shared__ char smem[];
    gemm_body(Ahi, Alo, Whi, Wlo, bias, C, nullptr, nullptr, 0, smem);
}

// ===========================================================================
// Flash attention v8: all-fp16 tensor path.
// QK: Q single fp16 (registers) x K fp16 hi/lo = 2 passes.
// PV: P single fp16 x V fp16 hi/lo = 2 passes.
// K ring[2] + V ring[2] only (64 KB smem). 128 q-rows/CTA, 2 CTAs/SM.
// ===========================================================================
#define KTT  8192                  // 64 rows * 128B (one of hi/lo)
#define KSTG (2 * KTT)             // 16384
#define FA8_SMEM (4 * KSTG)        // 65536

#define C2F 0.1803368801111204f    // log2(e)/8 (Dh=64 scale folded into exp2)
#define NT_ (S_ / 64)              // 32 kv tiles

__device__ __forceinline__ void fa_load_pair(uint32_t dst,
    const __nv_bfloat16* Hi, const __nv_bfloat16* Lo,
    size_t rowStart, int k0, int colOff) {
    const int tid = threadIdx.x;
    const __nv_bfloat16* srcs[2] = {Hi + (rowStart + k0) * DM_ + colOff,
                                    Lo + (rowStart + k0) * DM_ + colOff};
#pragma unroll
    for (int i = 0; i < 4; ++i) {
        int c = tid + i * 256;           // 0..1023
        int t = c >> 9, r = (c >> 3) & 63, ch = c & 7;
        cp16(dst + t * KTT + r * 128 + SWZ128B(r, ch),
             srcs[t] + (size_t)r * DM_ + ch * 8);
    }
}

// QK: s = Q(fp16 regs) @ K(fp16 hi/lo smem)^T, 2 passes.
__device__ __forceinline__ void qk_tile(
    uint32_t ksBase, const uint32_t (&qh)[4][4],
    int b_row, int b_kb, float (&s)[8][4]) {
#pragma unroll
    for (int j = 0; j < 8; ++j)
#pragma unroll
        for (int q = 0; q < 4; ++q) s[j][q] = 0.f;
#pragma unroll
    for (int ks = 0; ks < 4; ++ks) {
#pragma unroll
        for (int ntp = 0; ntp < 4; ++ntp) {
            const int krow = ntp * 16 + b_row;
            const uint32_t koff = krow * 128 + SWZ128B(krow, ks * 2 + b_kb);
            uint32_t th[4], tl[4];
            ldmx4(th, ksBase + koff);
            ldmx4(tl, ksBase + KTT + koff);
            uint32_t k0h[2] = {th[0], th[1]}, k1h[2] = {th[2], th[3]};
            uint32_t k0l[2] = {tl[0], tl[1]}, k1l[2] = {tl[2], tl[3]};
            mma_f16(s[2 * ntp],     qh[ks], k0h);
            mma_f16(s[2 * ntp + 1], qh[ks], k1h);
            mma_f16(s[2 * ntp],     qh[ks], k0l);
            mma_f16(s[2 * ntp + 1], qh[ks], k1l);
        }
    }
}

// online softmax + pack P to single fp16 fragments.
__device__ __forceinline__ void softmax_pack(
    float (&s)[8][4], float (&o)[8][4],
    float& m0, float& m1, float& l0, float& l1,
    uint32_t (&Pa)[8], uint32_t (&Pb)[8]) {
    float rmax0 = -1e30f, rmax1 = -1e30f;
#pragma unroll
    for (int j = 0; j < 8; ++j) {
        rmax0 = fmaxf(rmax0, fmaxf(s[j][0], s[j][1]));
        rmax1 = fmaxf(rmax1, fmaxf(s[j][2], s[j][3]));
    }
    rmax0 = fmaxf(rmax0, __shfl_xor_sync(0xffffffffu, rmax0, 1));
    rmax0 = fmaxf(rmax0, __shfl_xor_sync(0xffffffffu, rmax0, 2));
    rmax1 = fmaxf(rmax1, __shfl_xor_sync(0xffffffffu, rmax1, 1));
    rmax1 = fmaxf(rmax1, __shfl_xor_sync(0xffffffffu, rmax1, 2));
    const float m0n = fmaxf(m0, rmax0);
    const float m1n = fmaxf(m1, rmax1);
    const float c0 = ex2f((m0 - m0n) * C2F);
    const float c1 = ex2f((m1 - m1n) * C2F);
    m0 = m0n; m1 = m1n;
    const float mc0 = m0 * C2F, mc1 = m1 * C2F;
    float sum0 = 0.f, sum1 = 0.f;
#pragma unroll
    for (int j = 0; j < 8; ++j) {
        s[j][0] = ex2f(fmaf(s[j][0], C2F, -mc0));
        s[j][1] = ex2f(fmaf(s[j][1], C2F, -mc0));
        s[j][2] = ex2f(fmaf(s[j][2], C2F, -mc1));
        s[j][3] = ex2f(fmaf(s[j][3], C2F, -mc1));
        sum0 += s[j][0] + s[j][1];
        sum1 += s[j][2] + s[j][3];
    }
    sum0 += __shfl_xor_sync(0xffffffffu, sum0, 1);
    sum0 += __shfl_xor_sync(0xffffffffu, sum0, 2);
    sum1 += __shfl_xor_sync(0xffffffffu, sum1, 1);
    sum1 += __shfl_xor_sync(0xffffffffu, sum1, 2);
    l0 = l0 * c0 + sum0;
    l1 = l1 * c1 + sum1;
#pragma unroll
    for (int j = 0; j < 8; ++j) {
        Pa[j] = pack_h2(s[j][0], s[j][1]);
        Pb[j] = pack_h2(s[j][2], s[j][3]);
    }
#pragma unroll
    for (int j = 0; j < 8; ++j) {
        o[j][0] *= c0; o[j][1] *= c0;
        o[j][2] *= c1; o[j][3] *= c1;
    }
}

// O += P @ V: fp16 2-pass. vsBase: Vhi +0, Vlo +KTT.
__device__ __forceinline__ void pv_accum(
    uint32_t vsBase, int v_k, int v_db,
    const uint32_t (&Pa)[8], const uint32_t (&Pb)[8],
    float (&o)[8][4]) {
#pragma unroll
    for (int ks = 0; ks < 4; ++ks) {
        uint32_t ap[4] = {Pa[2 * ks], Pb[2 * ks],
                          Pa[2 * ks + 1], Pb[2 * ks + 1]};
        const int vrow = 16 * ks + v_k;
#pragma unroll
        for (int dt = 0; dt < 4; ++dt) {
            const uint32_t off = vrow * 128 + SWZ128B(vrow, dt * 2 + v_db);
            uint32_t vh[4], vl[4];
            ldmx4t(vh, vsBase + off);
            ldmx4t(vl, vsBase + KTT + off);
            uint32_t b0h[2] = {vh[0], vh[1]}, b1h[2] = {vh[2], vh[3]};
            uint32_t b0l[2] = {vl[0], vl[1]}, b1l[2] = {vl[2], vl[3]};
            mma_f16(o[2 * dt],     ap, b0h);
            mma_f16(o[2 * dt + 1], ap, b1h);
            mma_f16(o[2 * dt],     ap, b0l);
            mma_f16(o[2 * dt + 1], ap, b1l);
        }
    }
}

__global__ __launch_bounds__(256, 2)
void flash_mma8(const __nv_bfloat16* __restrict__ Qh,    // fp16 single bits
                const __nv_bfloat16* __restrict__ Khi,   // fp16 bits
                const __nv_bfloat16* __restrict__ Klo,
                const __nv_bfloat16* __restrict__ Vhi,
                const __nv_bfloat16* __restrict__ Vlo,
                __nv_bfloat16* __restrict__ AOh,
                __nv_bfloat16* __restrict__ AOl) {
    extern __shared__ char smem[];
    const uint32_t sb = smem_u32(smem);
    const int tid = threadIdx.x, wid = tid >> 5, lane = tid & 31;
    const int bh = blockIdx.y, b = bh >> 4, h = bh & 15;
    const int q0 = blockIdx.x * 128;
    const size_t rowStart = (size_t)b * S_;
    const int colOff = h * DH_;

    // smem layout: 4 x 16 KB
    const uint32_t Ks0 = sb;
    const uint32_t Ks1 = sb + KSTG;
    const uint32_t Vs0 = sb + 2 * KSTG;
    const uint32_t Vs1 = sb + 3 * KSTG;   // also transient Q staging (16 KB)

    // ---- prologue: Q -> Vs1 (g1); K0+V0 (g2); K1 (g3) ----
    {
        const __nv_bfloat16* qsrc = Qh + (rowStart + q0) * DM_ + colOff;
#pragma unroll
        for (int i = 0; i < 4; ++i) {
            int c = tid + i * 256;           // 0..1023: r 0..127, ch 0..7
            int r = c >> 3, ch = c & 7;
            cp16(Vs1 + r * 128 + SWZ128B(r, ch), qsrc + (size_t)r * DM_ + ch * 8);
        }
    }
    CP_COMMIT();                             // g1
    fa_load_pair(Ks0, Khi, Klo, rowStart, 0, colOff);
    fa_load_pair(Vs0, Vhi, Vlo, rowStart, 0, colOff);
    CP_COMMIT();                             // g2
    fa_load_pair(Ks1, Khi, Klo, rowStart, 64, colOff);
    CP_COMMIT();                             // g3
    CP_WAIT(2);                              // g1 (Q) done
    __syncthreads();

    // fragment addressing
    const int a_row = lane & 15;
    const int a_kb  = lane >> 4;
    const int b_row = ((lane >> 4) & 1) * 8 + (lane & 7);
    const int b_kb  = (lane >> 3) & 1;
    const int v_k   = (lane & 7) + ((lane >> 3) & 1) * 8;
    const int v_db  = (lane >> 4) & 1;
    const int qrow  = 16 * wid + a_row;

    // ---- whole Q into registers (16 regs) ----
    uint32_t qh[4][4];
#pragma unroll
    for (int ks = 0; ks < 4; ++ks)
        ldmx4(qh[ks], Vs1 + qrow * 128 + SWZ128B(qrow, ks * 2 + a_kb));

    CP_WAIT(0);                              // K0,V0,K1 landed
    __syncthreads();                         // + all warps done reading Q

    float m0 = -1e30f, m1 = -1e30f, l0 = 0.f, l1 = 0.f;
    float o[8][4];
#pragma unroll
    for (int j = 0; j < 8; ++j)
#pragma unroll
        for (int q = 0; q < 4; ++q) o[j][q] = 0.f;

    // ---- software-pipeline prologue: s(0) ----
    float s[8][4];
    qk_tile(Ks0, qh, b_row, b_kb, s);

    // ---- main loop ----
    for (int jt = 0; jt < NT_ - 1; ++jt) {
        CP_WAIT(0);
        __syncthreads();                 // K(jt+1), V(jt) resident
        const int kc = (jt + 2 < NT_) ? (jt + 2) : (NT_ - 1);
        fa_load_pair((jt & 1) ? Ks1 : Ks0, Khi, Klo, rowStart, kc * 64, colOff);
        fa_load_pair(((jt + 1) & 1) ? Vs1 : Vs0, Vhi, Vlo, rowStart,
                     (jt + 1) * 64, colOff);
        CP_COMMIT();

        uint32_t Pa[8], Pb[8];
        softmax_pack(s, o, m0, m1, l0, l1, Pa, Pb);
        qk_tile(((jt + 1) & 1) ? Ks1 : Ks0, qh, b_row, b_kb, s);
        pv_accum((jt & 1) ? Vs1 : Vs0, v_k, v_db, Pa, Pb, o);
    }

    // ---- tail ----
    CP_WAIT(0);
    __syncthreads();
    {
        uint32_t Pa[8], Pb[8];
        softmax_pack(s, o, m0, m1, l0, l1, Pa, Pb);
        pv_accum(((NT_ - 1) & 1) ? Vs1 : Vs0, v_k, v_db, Pa, Pb, o);
    }

    // ---- normalize, split to bf16 hi/lo, write ----
    const float i0 = 1.f / l0, i1 = 1.f / l1;
    const size_t row0 = rowStart + q0 + 16 * wid + (lane >> 2);
    const size_t row1 = row0 + 8;
#pragma unroll
    for (int j = 0; j < 8; ++j) {
        const int col = colOff + j * 8 + (lane & 3) * 2;
        float f0 = o[j][0] * i0, f1 = o[j][1] * i0;
        float f2 = o[j][2] * i1, f3 = o[j][3] * i1;
        uint32_t h01 = cvt_bf16x2(f1, f0);
        uint32_t h23 = cvt_bf16x2(f3, f2);
        float r0f = f0 - __uint_as_float(h01 << 16);
        float r1f = f1 - __uint_as_float(h01 & 0xFFFF0000u);
        float r2f = f2 - __uint_as_float(h23 << 16);
        float r3f = f3 - __uint_as_float(h23 & 0xFFFF0000u);
        uint32_t l01 = cvt_bf16x2(r1f, r0f);
        uint32_t l23 = cvt_bf16x2(r3f, r2f);
        *(uint32_t*)(AOh + row0 * DM_ + col) = h01;
        *(uint32_t*)(AOh + row1 * DM_ + col) = h23;
        *(uint32_t*)(AOl + row0 * DM_ + col) = l01;
        *(uint32_t*)(AOl + row1 * DM_ + col) = l23;
    }
}

// ===========================================================================
// Launch
// ===========================================================================
extern "C" void kernel_launch(void* const* d_in, const int* in_sizes, int n_in,
                              void* d_out, int out_size)
{
    const float* query = (const float*)d_in[0];
    const float* key   = (const float*)d_in[1];
    const float* value = (const float*)d_in[2];
    const float* Wq    = (const float*)d_in[3];
    const float* bq    = (const float*)d_in[4];
    const float* Wk    = (const float*)d_in[5];
    const float* bk    = (const float*)d_in[6];
    const float* Wv    = (const float*)d_in[7];
    const float* bv    = (const float*)d_in[8];
    const float* Wo    = (const float*)d_in[9];
    const float* bo    = (const float*)d_in[10];
    float* out = (float*)d_out;

    __nv_bfloat16 *pIh, *pIl, *pWh, *pWl;
    __nv_bfloat16 *pQh, *pKh, *pKl, *pVh, *pVl, *pAOh, *pAOl;
    cudaGetSymbolAddress((void**)&pIh,  g_Ih);
    cudaGetSymbolAddress((void**)&pIl,  g_Il);
    cudaGetSymbolAddress((void**)&pWh,  g_W4h);
    cudaGetSymbolAddress((void**)&pWl,  g_W4l);
    cudaGetSymbolAddress((void**)&pQh,  g_Qh);
    cudaGetSymbolAddress((void**)&pKh,  g_Kh);
    cudaGetSymbolAddress((void**)&pKl,  g_Kl);
    cudaGetSymbolAddress((void**)&pVh,  g_Vh);
    cudaGetSymbolAddress((void**)&pVl,  g_Vl);
    cudaGetSymbolAddress((void**)&pAOh, g_AOh);
    cudaGetSymbolAddress((void**)&pAOl, g_AOl);

    const size_t NTOK = (size_t)ROWS_ * DM_;

    static bool attrs_set = false;
    if (!attrs_set) {
        cudaFuncSetAttribute(gemm_qkv, cudaFuncAttributeMaxDynamicSharedMemorySize, GEMM_SMEM);
        cudaFuncSetAttribute(gemm_o,   cudaFuncAttributeMaxDynamicSharedMemorySize, GEMM_SMEM);
        cudaFuncSetAttribute(flash_mma8, cudaFuncAttributeMaxDynamicSharedMemorySize, FA8_SMEM);
        attrs_set = true;
    }

    const int n4 = ROWS_ * DM_ / 4;

    // 1) split all three inputs
    split3<<<dim3((n4 + 255) / 256, 3), 256>>>(
        (const float4*)query, (const float4*)key, (const float4*)value,
        pIh + 0 * NTOK, pIl + 0 * NTOK,
        pIh + 1 * NTOK, pIl + 1 * NTOK,
        pIh + 2 * NTOK, pIl + 2 * NTOK, n4);

    // 2) split+transpose all four weights
    wtsplit4<<<dim3(32, 32, 4), dim3(32, 8)>>>(Wq, Wk, Wv, Wo, pWh, pWl);

    // 3) Q,K,V projections (Q -> fp16 single; K,V -> fp16 hi/lo)
    gemm_qkv<<<dim3(DM_ / BN, ROWS_ / BM, 3), 256, GEMM_SMEM>>>(
        pIh + 0 * NTOK, pIl + 0 * NTOK,
        pIh + 1 * NTOK, pIl + 1 * NTOK,
        pIh + 2 * NTOK, pIl + 2 * NTOK,
        pWh, pWl, bq, bk, bv,
        pQh, nullptr, pKh, pKl, pVh, pVl);

    // 4) attention (QK + PV on fp16, 2 passes each; writes bf16 hi/lo)
    flash_mma8<<<dim3(S_ / 128, B_ * NH_), 256, FA8_SMEM>>>(
        pQh, pKh, pKl, pVh, pVl, pAOh, pAOl);

    // 5) output projection (fp32 result)
    gemm_o<<<dim3(DM_ / BN, ROWS_ / BM), 256, GEMM_SMEM>>>(
        pAOh, pAOl,
        pWh + 3 * (size_t)DM_ * DM_, pWl + 3 * (size_t)DM_ * DM_,
        bo, out);
}

// round 12
// speedup vs baseline: 1.5076x; 1.2061x over previous
#include <cuda_runtime.h>
#include <cuda_bf16.h>
#include <cuda_fp16.h>
#include <math.h>
#include <cstdint>

// ---------------------------------------------------------------------------
// Problem constants
// ---------------------------------------------------------------------------
#define B_    4
#define S_    2048
#define DM_   1024
#define NH_   16
#define DH_   64
#define ROWS_ (B_ * S_)          // 8192

// ---------------------------------------------------------------------------
// Scratch (device globals: allocation-free per harness rules)
// All fp16 bits stored in __half arrays.
// ---------------------------------------------------------------------------
__device__ __half g_Ih[3][ROWS_ * DM_];   // split inputs (q,k,v) fp16 hi
__device__ __half g_Il[3][ROWS_ * DM_];   // split inputs fp16 lo
__device__ __half g_W4[4][DM_ * DM_];     // W^T fp16 single (q,k,v,o)
__device__ __half g_Qh[ROWS_ * DM_];      // fp16 single
__device__ __half g_Kh[ROWS_ * DM_];      // fp16 hi
__device__ __half g_Kl[ROWS_ * DM_];      // fp16 lo
__device__ __half g_Vh[ROWS_ * DM_];      // fp16 hi
__device__ __half g_Vl[ROWS_ * DM_];      // fp16 lo
__device__ __half g_AOh[ROWS_ * DM_];     // attention out fp16 hi
__device__ __half g_AOl[ROWS_ * DM_];     // attention out fp16 lo

// ===========================================================================
// Generic-PTX helpers (legal on plain sm_103 target: sm_80+ instructions)
// ===========================================================================
__device__ __forceinline__ uint32_t smem_u32(const void* p) {
    uint32_t a;
    asm("{ .reg .u64 t; cvta.to.shared.u64 t, %1; cvt.u32.u64 %0, t; }"
        : "=r"(a) : "l"(p));
    return a;
}

__device__ __forceinline__ void cp16(uint32_t s, const void* g) {
    asm volatile("cp.async.cg.shared.global [%0], [%1], 16;" :: "r"(s), "l"(g));
}
#define CP_COMMIT() asm volatile("cp.async.commit_group;" ::: "memory")
#define CP_WAIT(n)  asm volatile("cp.async.wait_group %0;" :: "n"(n) : "memory")

__device__ __forceinline__ void ldmx4(uint32_t* r, uint32_t addr) {
    asm volatile("ldmatrix.sync.aligned.m8n8.x4.shared.b16 {%0,%1,%2,%3}, [%4];"
                 : "=r"(r[0]), "=r"(r[1]), "=r"(r[2]), "=r"(r[3]) : "r"(addr));
}

__device__ __forceinline__ void ldmx4t(uint32_t* r, uint32_t addr) {
    asm volatile("ldmatrix.sync.aligned.m8n8.x4.trans.shared.b16 {%0,%1,%2,%3}, [%4];"
                 : "=r"(r[0]), "=r"(r[1]), "=r"(r[2]), "=r"(r[3]) : "r"(addr));
}

__device__ __forceinline__ void mma_f16(float* d, const uint32_t* a,
                                        const uint32_t* b) {
    asm volatile(
        "mma.sync.aligned.m16n8k16.row.col.f32.f16.f16.f32 "
        "{%0,%1,%2,%3}, {%4,%5,%6,%7}, {%8,%9}, {%0,%1,%2,%3};"
        : "+f"(d[0]), "+f"(d[1]), "+f"(d[2]), "+f"(d[3])
        : "r"(a[0]), "r"(a[1]), "r"(a[2]), "r"(a[3]), "r"(b[0]), "r"(b[1]));
}

__device__ __forceinline__ uint32_t cvt_bf16x2(float hi_elem, float lo_elem) {
    uint32_t r;
    asm("cvt.rn.satfinite.bf16x2.f32 %0, %1, %2;"
        : "=r"(r) : "f"(hi_elem), "f"(lo_elem));
    return r;
}

__device__ __forceinline__ uint32_t pack_h2(float lo_elem, float hi_elem) {
    __half2 h = __floats2half2_rn(lo_elem, hi_elem);   // .x = lo bits
    return *reinterpret_cast<uint32_t*>(&h);
}

__device__ __forceinline__ float ex2f(float x) {
    float y;
    asm("ex2.approx.ftz.f32 %0, %1;" : "=f"(y) : "f"(x));
    return y;
}

// XOR swizzles: conflict-free ldmatrix on unpadded rows.
#define SWZ128B(r, ch) ((((ch) ^ ((r) & 7)) << 4))
#define SWZ64B(r, ch)  ((((ch) ^ (((r) >> 1) & 3)) << 4))

__device__ __forceinline__ int inc3(int x) { return (x == 2) ? 0 : x + 1; }

// ===========================================================================
// Prep: split 3 inputs to fp16 hi/lo; transpose 4 weights to fp16 single
// ===========================================================================
__global__ __launch_bounds__(256)
void split3(const float4* __restrict__ x0, const float4* __restrict__ x1,
            const float4* __restrict__ x2,
            __half* __restrict__ h0, __half* __restrict__ l0,
            __half* __restrict__ h1, __half* __restrict__ l1,
            __half* __restrict__ h2, __half* __restrict__ l2,
            int n4) {
    int i = blockIdx.x * blockDim.x + threadIdx.x;
    if (i >= n4) return;
    const int z = blockIdx.y;
    const float4* x = (z == 0) ? x0 : (z == 1) ? x1 : x2;
    __half* hi = (z == 0) ? h0 : (z == 1) ? h1 : h2;
    __half* lo = (z == 0) ? l0 : (z == 1) ? l1 : l2;
    float4 v = x[i];
    float f[4] = {v.x, v.y, v.z, v.w};
    __half h[4], l[4];
#pragma unroll
    for (int j = 0; j < 4; ++j) {
        h[j] = __float2half_rn(f[j]);
        l[j] = __float2half_rn(f[j] - __half2float(h[j]));
    }
    ((__half2*)hi)[i * 2 + 0] = __half2(h[0], h[1]);
    ((__half2*)hi)[i * 2 + 1] = __half2(h[2], h[3]);
    ((__half2*)lo)[i * 2 + 0] = __half2(l[0], l[1]);
    ((__half2*)lo)[i * 2 + 1] = __half2(l[2], l[3]);
}

__global__ __launch_bounds__(256)
void wtsplit4(const float* __restrict__ w0, const float* __restrict__ w1,
              const float* __restrict__ w2, const float* __restrict__ w3,
              __half* __restrict__ hi4) {
    __shared__ float t[32][33];
    const int z = blockIdx.z;
    const float* W = (z == 0) ? w0 : (z == 1) ? w1 : (z == 2) ? w2 : w3;
    __half* hi = hi4 + (size_t)z * DM_ * DM_;
    const int n0 = blockIdx.x * 32;
    const int k0 = blockIdx.y * 32;
    const int tx = threadIdx.x, ty = threadIdx.y;
#pragma unroll
    for (int i = 0; i < 4; ++i)
        t[ty + i * 8][tx] = W[(size_t)(k0 + ty + i * 8) * DM_ + n0 + tx];
    __syncthreads();
#pragma unroll
    for (int i = 0; i < 4; ++i) {
        float v = t[tx][ty + i * 8];
        hi[(size_t)(n0 + ty + i * 8) * DM_ + k0 + tx] = __float2half_rn(v);
    }
}

// ===========================================================================
// HMMA GEMM (fp16, 2 passes: Ah*W + Al*W):  C = A @ Wt^T + bias
// 3-stage cp.async ring, 1 sync/ktile, XOR-swizzled 64B rows. 2 CTAs/SM.
// Epilogue modes: 0 = fp32, 1 = fp16 hi/lo pair, 2 = fp16 single.
// ===========================================================================
#define BM 128
#define BN 128
#define BK 32
#define NKT (DM_ / BK)            // 32
#define GT_TILE 8192              // 128 rows * 64B
#define GT_STAGE (3 * GT_TILE)    // 24576: Ahi, Alo, W
#define GEMM_SMEM (3 * GT_STAGE)  // 73728

__device__ __forceinline__ void load_ktile(uint32_t sb, int kt, int stage,
                                           const __half* Ahi, const __half* Alo,
                                           const __half* W,
                                           int rowBase, int colBase) {
    const int tid = threadIdx.x;
    const uint32_t base = sb + stage * GT_STAGE;
    const __half* srcs[3] = {
        Ahi + (size_t)rowBase * DM_ + kt * BK,
        Alo + (size_t)rowBase * DM_ + kt * BK,
        W   + (size_t)colBase * DM_ + kt * BK};
#pragma unroll
    for (int t = 0; t < 3; ++t) {
#pragma unroll
        for (int i = 0; i < 2; ++i) {
            int c = tid + i * 256;          // 0..511
            int r = c >> 2, ch = c & 3;
            cp16(base + t * GT_TILE + r * 64 + SWZ64B(r, ch),
                 srcs[t] + (size_t)r * DM_ + ch * 8);
        }
    }
}

__device__ __forceinline__ void gemm_body(
    const __half* __restrict__ Ahi, const __half* __restrict__ Alo,
    const __half* __restrict__ W,
    const float* __restrict__ bias, float* __restrict__ C,
    __half* __restrict__ Chi, __half* __restrict__ Clo,
    int mode, char* smem) {
    const uint32_t sb = smem_u32(smem);
    const int tid  = threadIdx.x;
    const int wid  = tid >> 5;
    const int lane = tid & 31;
    const int rowBase = blockIdx.y * BM;
    const int colBase = blockIdx.x * BN;

    const int mbase = (wid >> 1) * 32;
    const int nbase = (wid & 1) * 64;

    float acc[2][8][4];
#pragma unroll
    for (int i = 0; i < 2; ++i)
#pragma unroll
        for (int j = 0; j < 8; ++j)
#pragma unroll
            for (int q = 0; q < 4; ++q) acc[i][j][q] = 0.f;

    load_ktile(sb, 0, 0, Ahi, Alo, W, rowBase, colBase);
    CP_COMMIT();
    load_ktile(sb, 1, 1, Ahi, Alo, W, rowBase, colBase);
    CP_COMMIT();

    const int a_row = lane & 15;
    const int a_kb  = lane >> 4;
    const int b_row = ((lane >> 4) & 1) * 8 + (lane & 7);
    const int b_kb  = (lane >> 3) & 1;

    int cur = 0, pf = 2;
    for (int kt = 0; kt < NKT; ++kt) {
        if (kt + 1 < NKT) { CP_WAIT(1); } else { CP_WAIT(0); }
        __syncthreads();
        if (kt + 2 < NKT) {
            load_ktile(sb, kt + 2, pf, Ahi, Alo, W, rowBase, colBase);
            CP_COMMIT();
        }

        const uint32_t st = sb + cur * GT_STAGE;
#pragma unroll
        for (int s = 0; s < 2; ++s) {
            uint32_t ah[2][4], al[2][4];
#pragma unroll
            for (int i = 0; i < 2; ++i) {
                int row = mbase + i * 16 + a_row;
                uint32_t off = row * 64 + SWZ64B(row, s * 2 + a_kb);
                ldmx4(ah[i], st + 0 * GT_TILE + off);
                ldmx4(al[i], st + 1 * GT_TILE + off);
            }
#pragma unroll
            for (int jp = 0; jp < 4; ++jp) {
                int row = nbase + jp * 16 + b_row;
                uint32_t off = row * 64 + SWZ64B(row, s * 2 + b_kb);
                uint32_t tw[4];
                ldmx4(tw, st + 2 * GT_TILE + off);
                uint32_t b0[2] = {tw[0], tw[1]}, b1[2] = {tw[2], tw[3]};
#pragma unroll
                for (int i = 0; i < 2; ++i) {
                    mma_f16(acc[i][jp * 2],     ah[i], b0);
                    mma_f16(acc[i][jp * 2 + 1], ah[i], b1);
                    mma_f16(acc[i][jp * 2],     al[i], b0);
                    mma_f16(acc[i][jp * 2 + 1], al[i], b1);
                }
            }
        }
        cur = inc3(cur);
        pf  = inc3(pf);
    }

#pragma unroll
    for (int i = 0; i < 2; ++i) {
        const int r0 = rowBase + mbase + i * 16 + (lane >> 2);
#pragma unroll
        for (int j = 0; j < 8; ++j) {
            const int col = colBase + nbase + j * 8 + (lane & 3) * 2;
            const float b0 = bias[col], b1 = bias[col + 1];
            float f0 = acc[i][j][0] + b0, f1 = acc[i][j][1] + b1;
            float f2 = acc[i][j][2] + b0, f3 = acc[i][j][3] + b1;
            if (mode == 0) {
                *(float2*)(C + (size_t)r0 * DM_ + col)       = make_float2(f0, f1);
                *(float2*)(C + (size_t)(r0 + 8) * DM_ + col) = make_float2(f2, f3);
            } else {
                __half2 hh01 = __floats2half2_rn(f0, f1);
                __half2 hh23 = __floats2half2_rn(f2, f3);
                *(uint32_t*)(Chi + (size_t)r0 * DM_ + col)       = *(uint32_t*)&hh01;
                *(uint32_t*)(Chi + (size_t)(r0 + 8) * DM_ + col) = *(uint32_t*)&hh23;
                if (mode == 1) {
                    float r0f = f0 - __half2float(__low2half(hh01));
                    float r1f = f1 - __half2float(__high2half(hh01));
                    float r2f = f2 - __half2float(__low2half(hh23));
                    float r3f = f3 - __half2float(__high2half(hh23));
                    __half2 hl01 = __floats2half2_rn(r0f, r1f);
                    __half2 hl23 = __floats2half2_rn(r2f, r3f);
                    *(uint32_t*)(Clo + (size_t)r0 * DM_ + col)       = *(uint32_t*)&hl01;
                    *(uint32_t*)(Clo + (size_t)(r0 + 8) * DM_ + col) = *(uint32_t*)&hl23;
                }
            }
        }
    }
}

__global__ __launch_bounds__(256, 2)
void gemm_qkv(const __half* __restrict__ Ah0, const __half* __restrict__ Al0,
              const __half* __restrict__ Ah1, const __half* __restrict__ Al1,
              const __half* __restrict__ Ah2, const __half* __restrict__ Al2,
              const __half* __restrict__ W4,
              const float* __restrict__ b0, const float* __restrict__ b1,
              const float* __restrict__ b2,
              __half* __restrict__ Ch0,
              __half* __restrict__ Ch1, __half* __restrict__ Cl1,
              __half* __restrict__ Ch2, __half* __restrict__ Cl2) {
    extern __shared__ char smem[];
    const int z = blockIdx.z;
    const __half* Ah = (z == 0) ? Ah0 : (z == 1) ? Ah1 : Ah2;
    const __half* Al = (z == 0) ? Al0 : (z == 1) ? Al1 : Al2;
    const float* bias = (z == 0) ? b0 : (z == 1) ? b1 : b2;
    __half* Ch = (z == 0) ? Ch0 : (z == 1) ? Ch1 : Ch2;
    __half* Cl = (z == 0) ? nullptr : (z == 1) ? Cl1 : Cl2;
    // Q -> fp16 single (mode 2); K,V -> fp16 hi/lo (mode 1)
    gemm_body(Ah, Al, W4 + (size_t)z * DM_ * DM_,
              bias, nullptr, Ch, Cl, (z == 0) ? 2 : 1, smem);
}

__global__ __launch_bounds__(256, 2)
void gemm_o(const __half* __restrict__ Ahi, const __half* __restrict__ Alo,
            const __half* __restrict__ W,
            const float* __restrict__ bias, float* __restrict__ C) {
    extern __shared__ char smem[];
    gemm_body(Ahi, Alo, W, bias, C, nullptr, nullptr, 0, smem);
}

// ===========================================================================
// Flash attention v8 (unchanged from R11 except fp16 hi/lo output):
// QK: Q single fp16 (registers) x K fp16 hi/lo = 2 passes.
// PV: P single fp16 x V fp16 hi/lo = 2 passes.
// K ring[2] + V ring[2] (64 KB smem). 128 q-rows/CTA, 2 CTAs/SM.
// ===========================================================================
#define KTT  8192                  // 64 rows * 128B (one of hi/lo)
#define KSTG (2 * KTT)             // 16384
#define FA8_SMEM (4 * KSTG)        // 65536

#define C2F 0.1803368801111204f    // log2(e)/8 (Dh=64 scale folded into exp2)
#define NT_ (S_ / 64)              // 32 kv tiles

__device__ __forceinline__ void fa_load_pair(uint32_t dst,
    const __half* Hi, const __half* Lo,
    size_t rowStart, int k0, int colOff) {
    const int tid = threadIdx.x;
    const __half* srcs[2] = {Hi + (rowStart + k0) * DM_ + colOff,
                             Lo + (rowStart + k0) * DM_ + colOff};
#pragma unroll
    for (int i = 0; i < 4; ++i) {
        int c = tid + i * 256;           // 0..1023
        int t = c >> 9, r = (c >> 3) & 63, ch = c & 7;
        cp16(dst + t * KTT + r * 128 + SWZ128B(r, ch),
             srcs[t] + (size_t)r * DM_ + ch * 8);
    }
}

// QK: s = Q(fp16 regs) @ K(fp16 hi/lo smem)^T, 2 passes.
__device__ __forceinline__ void qk_tile(
    uint32_t ksBase, const uint32_t (&qh)[4][4],
    int b_row, int b_kb, float (&s)[8][4]) {
#pragma unroll
    for (int j = 0; j < 8; ++j)
#pragma unroll
        for (int q = 0; q < 4; ++q) s[j][q] = 0.f;
#pragma unroll
    for (int ks = 0; ks < 4; ++ks) {
#pragma unroll
        for (int ntp = 0; ntp < 4; ++ntp) {
            const int krow = ntp * 16 + b_row;
            const uint32_t koff = krow * 128 + SWZ128B(krow, ks * 2 + b_kb);
            uint32_t th[4], tl[4];
            ldmx4(th, ksBase + koff);
            ldmx4(tl, ksBase + KTT + koff);
            uint32_t k0h[2] = {th[0], th[1]}, k1h[2] = {th[2], th[3]};
            uint32_t k0l[2] = {tl[0], tl[1]}, k1l[2] = {tl[2], tl[3]};
            mma_f16(s[2 * ntp],     qh[ks], k0h);
            mma_f16(s[2 * ntp + 1], qh[ks], k1h);
            mma_f16(s[2 * ntp],     qh[ks], k0l);
            mma_f16(s[2 * ntp + 1], qh[ks], k1l);
        }
    }
}

// online softmax + pack P to single fp16 fragments.
__device__ __forceinline__ void softmax_pack(
    float (&s)[8][4], float (&o)[8][4],
    float& m0, float& m1, float& l0, float& l1,
    uint32_t (&Pa)[8], uint32_t (&Pb)[8]) {
    float rmax0 = -1e30f, rmax1 = -1e30f;
#pragma unroll
    for (int j = 0; j < 8; ++j) {
        rmax0 = fmaxf(rmax0, fmaxf(s[j][0], s[j][1]));
        rmax1 = fmaxf(rmax1, fmaxf(s[j][2], s[j][3]));
    }
    rmax0 = fmaxf(rmax0, __shfl_xor_sync(0xffffffffu, rmax0, 1));
    rmax0 = fmaxf(rmax0, __shfl_xor_sync(0xffffffffu, rmax0, 2));
    rmax1 = fmaxf(rmax1, __shfl_xor_sync(0xffffffffu, rmax1, 1));
    rmax1 = fmaxf(rmax1, __shfl_xor_sync(0xffffffffu, rmax1, 2));
    const float m0n = fmaxf(m0, rmax0);
    const float m1n = fmaxf(m1, rmax1);
    const float c0 = ex2f((m0 - m0n) * C2F);
    const float c1 = ex2f((m1 - m1n) * C2F);
    m0 = m0n; m1 = m1n;
    const float mc0 = m0 * C2F, mc1 = m1 * C2F;
    float sum0 = 0.f, sum1 = 0.f;
#pragma unroll
    for (int j = 0; j < 8; ++j) {
        s[j][0] = ex2f(fmaf(s[j][0], C2F, -mc0));
        s[j][1] = ex2f(fmaf(s[j][1], C2F, -mc0));
        s[j][2] = ex2f(fmaf(s[j][2], C2F, -mc1));
        s[j][3] = ex2f(fmaf(s[j][3], C2F, -mc1));
        sum0 += s[j][0] + s[j][1];
        sum1 += s[j][2] + s[j][3];
    }
    sum0 += __shfl_xor_sync(0xffffffffu, sum0, 1);
    sum0 += __shfl_xor_sync(0xffffffffu, sum0, 2);
    sum1 += __shfl_xor_sync(0xffffffffu, sum1, 1);
    sum1 += __shfl_xor_sync(0xffffffffu, sum1, 2);
    l0 = l0 * c0 + sum0;
    l1 = l1 * c1 + sum1;
#pragma unroll
    for (int j = 0; j < 8; ++j) {
        Pa[j] = pack_h2(s[j][0], s[j][1]);
        Pb[j] = pack_h2(s[j][2], s[j][3]);
    }
#pragma unroll
    for (int j = 0; j < 8; ++j) {
        o[j][0] *= c0; o[j][1] *= c0;
        o[j][2] *= c1; o[j][3] *= c1;
    }
}

// O += P @ V: fp16 2-pass. vsBase: Vhi +0, Vlo +KTT.
__device__ __forceinline__ void pv_accum(
    uint32_t vsBase, int v_k, int v_db,
    const uint32_t (&Pa)[8], const uint32_t (&Pb)[8],
    float (&o)[8][4]) {
#pragma unroll
    for (int ks = 0; ks < 4; ++ks) {
        uint32_t ap[4] = {Pa[2 * ks], Pb[2 * ks],
                          Pa[2 * ks + 1], Pb[2 * ks + 1]};
        const int vrow = 16 * ks + v_k;
#pragma unroll
        for (int dt = 0; dt < 4; ++dt) {
            const uint32_t off = vrow * 128 + SWZ128B(vrow, dt * 2 + v_db);
            uint32_t vh[4], vl[4];
            ldmx4t(vh, vsBase + off);
            ldmx4t(vl, vsBase + KTT + off);
            uint32_t b0h[2] = {vh[0], vh[1]}, b1h[2] = {vh[2], vh[3]};
            uint32_t b0l[2] = {vl[0], vl[1]}, b1l[2] = {vl[2], vl[3]};
            mma_f16(o[2 * dt],     ap, b0h);
            mma_f16(o[2 * dt + 1], ap, b1h);
            mma_f16(o[2 * dt],     ap, b0l);
            mma_f16(o[2 * dt + 1], ap, b1l);
        }
    }
}

__global__ __launch_bounds__(256, 2)
void flash_mma8(const __half* __restrict__ Qh,
                const __half* __restrict__ Khi,
                const __half* __restrict__ Klo,
                const __half* __restrict__ Vhi,
                const __half* __restrict__ Vlo,
                __half* __restrict__ AOh,
                __half* __restrict__ AOl) {
    extern __shared__ char smem[];
    const uint32_t sb = smem_u32(smem);
    const int tid = threadIdx.x, wid = tid >> 5, lane = tid & 31;
    const int bh = blockIdx.y, b = bh >> 4, h = bh & 15;
    const int q0 = blockIdx.x * 128;
    const size_t rowStart = (size_t)b * S_;
    const int colOff = h * DH_;

    // smem layout: 4 x 16 KB
    const uint32_t Ks0 = sb;
    const uint32_t Ks1 = sb + KSTG;
    const uint32_t Vs0 = sb + 2 * KSTG;
    const uint32_t Vs1 = sb + 3 * KSTG;   // also transient Q staging (16 KB)

    // ---- prologue: Q -> Vs1 (g1); K0+V0 (g2); K1 (g3) ----
    {
        const __half* qsrc = Qh + (rowStart + q0) * DM_ + colOff;
#pragma unroll
        for (int i = 0; i < 4; ++i) {
            int c = tid + i * 256;           // 0..1023: r 0..127, ch 0..7
            int r = c >> 3, ch = c & 7;
            cp16(Vs1 + r * 128 + SWZ128B(r, ch), qsrc + (size_t)r * DM_ + ch * 8);
        }
    }
    CP_COMMIT();                             // g1
    fa_load_pair(Ks0, Khi, Klo, rowStart, 0, colOff);
    fa_load_pair(Vs0, Vhi, Vlo, rowStart, 0, colOff);
    CP_COMMIT();                             // g2
    fa_load_pair(Ks1, Khi, Klo, rowStart, 64, colOff);
    CP_COMMIT();                             // g3
    CP_WAIT(2);                              // g1 (Q) done
    __syncthreads();

    // fragment addressing
    const int a_row = lane & 15;
    const int a_kb  = lane >> 4;
    const int b_row = ((lane >> 4) & 1) * 8 + (lane & 7);
    const int b_kb  = (lane >> 3) & 1;
    const int v_k   = (lane & 7) + ((lane >> 3) & 1) * 8;
    const int v_db  = (lane >> 4) & 1;
    const int qrow  = 16 * wid + a_row;

    // ---- whole Q into registers (16 regs) ----
    uint32_t qh[4][4];
#pragma unroll
    for (int ks = 0; ks < 4; ++ks)
        ldmx4(qh[ks], Vs1 + qrow * 128 + SWZ128B(qrow, ks * 2 + a_kb));

    CP_WAIT(0);                              // K0,V0,K1 landed
    __syncthreads();                         // + all warps done reading Q

    float m0 = -1e30f, m1 = -1e30f, l0 = 0.f, l1 = 0.f;
    float o[8][4];
#pragma unroll
    for (int j = 0; j < 8; ++j)
#pragma unroll
        for (int q = 0; q < 4; ++q) o[j][q] = 0.f;

    // ---- software-pipeline prologue: s(0) ----
    float s[8][4];
    qk_tile(Ks0, qh, b_row, b_kb, s);

    // ---- main loop ----
    for (int jt = 0; jt < NT_ - 1; ++jt) {
        CP_WAIT(0);
        __syncthreads();                 // K(jt+1), V(jt) resident
        const int kc = (jt + 2 < NT_) ? (jt + 2) : (NT_ - 1);
        fa_load_pair((jt & 1) ? Ks1 : Ks0, Khi, Klo, rowStart, kc * 64, colOff);
        fa_load_pair(((jt + 1) & 1) ? Vs1 : Vs0, Vhi, Vlo, rowStart,
                     (jt + 1) * 64, colOff);
        CP_COMMIT();

        uint32_t Pa[8], Pb[8];
        softmax_pack(s, o, m0, m1, l0, l1, Pa, Pb);
        qk_tile(((jt + 1) & 1) ? Ks1 : Ks0, qh, b_row, b_kb, s);
        pv_accum((jt & 1) ? Vs1 : Vs0, v_k, v_db, Pa, Pb, o);
    }

    // ---- tail ----
    CP_WAIT(0);
    __syncthreads();
    {
        uint32_t Pa[8], Pb[8];
        softmax_pack(s, o, m0, m1, l0, l1, Pa, Pb);
        pv_accum(((NT_ - 1) & 1) ? Vs1 : Vs0, v_k, v_db, Pa, Pb, o);
    }

    // ---- normalize, split to fp16 hi/lo, write ----
    const float i0 = 1.f / l0, i1 = 1.f / l1;
    const size_t row0 = rowStart + q0 + 16 * wid + (lane >> 2);
    const size_t row1 = row0 + 8;
#pragma unroll
    for (int j = 0; j < 8; ++j) {
        const int col = colOff + j * 8 + (lane & 3) * 2;
        float f0 = o[j][0] * i0, f1 = o[j][1] * i0;
        float f2 = o[j][2] * i1, f3 = o[j][3] * i1;
        __half2 hh01 = __floats2half2_rn(f0, f1);
        __half2 hh23 = __floats2half2_rn(f2, f3);
        float r0f = f0 - __half2float(__low2half(hh01));
        float r1f = f1 - __half2float(__high2half(hh01));
        float r2f = f2 - __half2float(__low2half(hh23));
        float r3f = f3 - __half2float(__high2half(hh23));
        __half2 hl01 = __floats2half2_rn(r0f, r1f);
        __half2 hl23 = __floats2half2_rn(r2f, r3f);
        *(uint32_t*)(AOh + row0 * DM_ + col) = *(uint32_t*)&hh01;
        *(uint32_t*)(AOh + row1 * DM_ + col) = *(uint32_t*)&hh23;
        *(uint32_t*)(AOl + row0 * DM_ + col) = *(uint32_t*)&hl01;
        *(uint32_t*)(AOl + row1 * DM_ + col) = *(uint32_t*)&hl23;
    }
}

// ===========================================================================
// Launch
// ===========================================================================
extern "C" void kernel_launch(void* const* d_in, const int* in_sizes, int n_in,
                              void* d_out, int out_size)
{
    const float* query = (const float*)d_in[0];
    const float* key   = (const float*)d_in[1];
    const float* value = (const float*)d_in[2];
    const float* Wq    = (const float*)d_in[3];
    const float* bq    = (const float*)d_in[4];
    const float* Wk    = (const float*)d_in[5];
    const float* bk    = (const float*)d_in[6];
    const float* Wv    = (const float*)d_in[7];
    const float* bv    = (const float*)d_in[8];
    const float* Wo    = (const float*)d_in[9];
    const float* bo    = (const float*)d_in[10];
    float* out = (float*)d_out;

    __half *pIh, *pIl, *pW4;
    __half *pQh, *pKh, *pKl, *pVh, *pVl, *pAOh, *pAOl;
    cudaGetSymbolAddress((void**)&pIh,  g_Ih);
    cudaGetSymbolAddress((void**)&pIl,  g_Il);
    cudaGetSymbolAddress((void**)&pW4,  g_W4);
    cudaGetSymbolAddress((void**)&pQh,  g_Qh);
    cudaGetSymbolAddress((void**)&pKh,  g_Kh);
    cudaGetSymbolAddress((void**)&pKl,  g_Kl);
    cudaGetSymbolAddress((void**)&pVh,  g_Vh);
    cudaGetSymbolAddress((void**)&pVl,  g_Vl);
    cudaGetSymbolAddress((void**)&pAOh, g_AOh);
    cudaGetSymbolAddress((void**)&pAOl, g_AOl);

    const size_t NTOK = (size_t)ROWS_ * DM_;

    static bool attrs_set = false;
    if (!attrs_set) {
        cudaFuncSetAttribute(gemm_qkv, cudaFuncAttributeMaxDynamicSharedMemorySize, GEMM_SMEM);
        cudaFuncSetAttribute(gemm_o,   cudaFuncAttributeMaxDynamicSharedMemorySize, GEMM_SMEM);
        cudaFuncSetAttribute(flash_mma8, cudaFuncAttributeMaxDynamicSharedMemorySize, FA8_SMEM);
        attrs_set = true;
    }

    const int n4 = ROWS_ * DM_ / 4;

    // 1) split all three inputs (fp16 hi/lo)
    split3<<<dim3((n4 + 255) / 256, 3), 256>>>(
        (const float4*)query, (const float4*)key, (const float4*)value,
        pIh + 0 * NTOK, pIl + 0 * NTOK,
        pIh + 1 * NTOK, pIl + 1 * NTOK,
        pIh + 2 * NTOK, pIl + 2 * NTOK, n4);

    // 2) transpose all four weights to fp16 single
    wtsplit4<<<dim3(32, 32, 4), dim3(32, 8)>>>(Wq, Wk, Wv, Wo, pW4);

    // 3) Q,K,V projections (2-pass fp16; Q -> single, K/V -> hi/lo)
    gemm_qkv<<<dim3(DM_ / BN, ROWS_ / BM, 3), 256, GEMM_SMEM>>>(
        pIh + 0 * NTOK, pIl + 0 * NTOK,
        pIh + 1 * NTOK, pIl + 1 * NTOK,
        pIh + 2 * NTOK, pIl + 2 * NTOK,
        pW4, bq, bk, bv,
        pQh, pKh, pKl, pVh, pVl);

    // 4) attention (fp16 2-pass QK and PV; writes fp16 hi/lo)
    flash_mma8<<<dim3(S_ / 128, B_ * NH_), 256, FA8_SMEM>>>(
        pQh, pKh, pKl, pVh, pVl, pAOh, pAOl);

    // 5) output projection (2-pass fp16, fp32 result)
    gemm_o<<<dim3(DM_ / BN, ROWS_ / BM), 256, GEMM_SMEM>>>(
        pAOh, pAOl, pW4 + 3 * (size_t)DM_ * DM_, bo, out);
}

// round 13
// speedup vs baseline: 1.8899x; 1.2536x over previous
#include <cuda_runtime.h>
#include <cuda_bf16.h>
#include <cuda_fp16.h>
#include <math.h>
#include <cstdint>

// ---------------------------------------------------------------------------
// Problem constants
// ---------------------------------------------------------------------------
#define B_    4
#define S_    2048
#define DM_   1024
#define NH_   16
#define DH_   64
#define ROWS_ (B_ * S_)          // 8192

// ---------------------------------------------------------------------------
// Scratch (device globals: allocation-free per harness rules)
// ---------------------------------------------------------------------------
__device__ __half g_Ih[3][ROWS_ * DM_];   // split inputs (q,k,v) fp16 hi
__device__ __half g_Il[3][ROWS_ * DM_];   // split inputs fp16 lo
__device__ __half g_W4[4][DM_ * DM_];     // W^T fp16 single (q,k,v,o)
__device__ __half g_Qh[ROWS_ * DM_];      // fp16 single
__device__ __half g_Kh[ROWS_ * DM_];      // fp16 single
__device__ __half g_Vh[ROWS_ * DM_];      // fp16 single
__device__ __half g_AOh[ROWS_ * DM_];     // attention out fp16 hi
__device__ __half g_AOl[ROWS_ * DM_];     // attention out fp16 lo

// ===========================================================================
// Generic-PTX helpers (legal on plain sm_103 target: sm_80+ instructions)
// ===========================================================================
__device__ __forceinline__ uint32_t smem_u32(const void* p) {
    uint32_t a;
    asm("{ .reg .u64 t; cvta.to.shared.u64 t, %1; cvt.u32.u64 %0, t; }"
        : "=r"(a) : "l"(p));
    return a;
}

__device__ __forceinline__ void cp16(uint32_t s, const void* g) {
    asm volatile("cp.async.cg.shared.global [%0], [%1], 16;" :: "r"(s), "l"(g));
}
#define CP_COMMIT() asm volatile("cp.async.commit_group;" ::: "memory")
#define CP_WAIT(n)  asm volatile("cp.async.wait_group %0;" :: "n"(n) : "memory")

__device__ __forceinline__ void ldmx4(uint32_t* r, uint32_t addr) {
    asm volatile("ldmatrix.sync.aligned.m8n8.x4.shared.b16 {%0,%1,%2,%3}, [%4];"
                 : "=r"(r[0]), "=r"(r[1]), "=r"(r[2]), "=r"(r[3]) : "r"(addr));
}

__device__ __forceinline__ void ldmx4t(uint32_t* r, uint32_t addr) {
    asm volatile("ldmatrix.sync.aligned.m8n8.x4.trans.shared.b16 {%0,%1,%2,%3}, [%4];"
                 : "=r"(r[0]), "=r"(r[1]), "=r"(r[2]), "=r"(r[3]) : "r"(addr));
}

__device__ __forceinline__ void mma_f16(float* d, const uint32_t* a,
                                        const uint32_t* b) {
    asm volatile(
        "mma.sync.aligned.m16n8k16.row.col.f32.f16.f16.f32 "
        "{%0,%1,%2,%3}, {%4,%5,%6,%7}, {%8,%9}, {%0,%1,%2,%3};"
        : "+f"(d[0]), "+f"(d[1]), "+f"(d[2]), "+f"(d[3])
        : "r"(a[0]), "r"(a[1]), "r"(a[2]), "r"(a[3]), "r"(b[0]), "r"(b[1]));
}

__device__ __forceinline__ uint32_t pack_h2(float lo_elem, float hi_elem) {
    __half2 h = __floats2half2_rn(lo_elem, hi_elem);   // .x = lo bits
    return *reinterpret_cast<uint32_t*>(&h);
}

__device__ __forceinline__ float ex2f(float x) {
    float y;
    asm("ex2.approx.ftz.f32 %0, %1;" : "=f"(y) : "f"(x));
    return y;
}

// XOR swizzles: conflict-free ldmatrix on unpadded rows.
#define SWZ128B(r, ch) ((((ch) ^ ((r) & 7)) << 4))
#define SWZ64B(r, ch)  ((((ch) ^ (((r) >> 1) & 3)) << 4))

__device__ __forceinline__ int inc3(int x) { return (x == 2) ? 0 : x + 1; }

// ===========================================================================
// Prep: split 3 inputs to fp16 hi/lo; transpose 4 weights to fp16 single
// ===========================================================================
__global__ __launch_bounds__(256)
void split3(const float4* __restrict__ x0, const float4* __restrict__ x1,
            const float4* __restrict__ x2,
            __half* __restrict__ h0, __half* __restrict__ l0,
            __half* __restrict__ h1, __half* __restrict__ l1,
            __half* __restrict__ h2, __half* __restrict__ l2,
            int n4) {
    int i = blockIdx.x * blockDim.x + threadIdx.x;
    if (i >= n4) return;
    const int z = blockIdx.y;
    const float4* x = (z == 0) ? x0 : (z == 1) ? x1 : x2;
    __half* hi = (z == 0) ? h0 : (z == 1) ? h1 : h2;
    __half* lo = (z == 0) ? l0 : (z == 1) ? l1 : l2;
    float4 v = x[i];
    float f[4] = {v.x, v.y, v.z, v.w};
    __half h[4], l[4];
#pragma unroll
    for (int j = 0; j < 4; ++j) {
        h[j] = __float2half_rn(f[j]);
        l[j] = __float2half_rn(f[j] - __half2float(h[j]));
    }
    ((__half2*)hi)[i * 2 + 0] = __half2(h[0], h[1]);
    ((__half2*)hi)[i * 2 + 1] = __half2(h[2], h[3]);
    ((__half2*)lo)[i * 2 + 0] = __half2(l[0], l[1]);
    ((__half2*)lo)[i * 2 + 1] = __half2(l[2], l[3]);
}

__global__ __launch_bounds__(256)
void wtsplit4(const float* __restrict__ w0, const float* __restrict__ w1,
              const float* __restrict__ w2, const float* __restrict__ w3,
              __half* __restrict__ hi4) {
    __shared__ float t[32][33];
    const int z = blockIdx.z;
    const float* W = (z == 0) ? w0 : (z == 1) ? w1 : (z == 2) ? w2 : w3;
    __half* hi = hi4 + (size_t)z * DM_ * DM_;
    const int n0 = blockIdx.x * 32;
    const int k0 = blockIdx.y * 32;
    const int tx = threadIdx.x, ty = threadIdx.y;
#pragma unroll
    for (int i = 0; i < 4; ++i)
        t[ty + i * 8][tx] = W[(size_t)(k0 + ty + i * 8) * DM_ + n0 + tx];
    __syncthreads();
#pragma unroll
    for (int i = 0; i < 4; ++i) {
        float v = t[tx][ty + i * 8];
        hi[(size_t)(n0 + ty + i * 8) * DM_ + k0 + tx] = __float2half_rn(v);
    }
}

// ===========================================================================
// HMMA GEMM (fp16, 2 passes: Ah*W + Al*W):  C = A @ Wt^T + bias
// 3-stage cp.async ring, 1 sync/ktile, XOR-swizzled 64B rows. 2 CTAs/SM.
// Epilogue modes: 0 = fp32, 1 = fp16 hi/lo pair, 2 = fp16 single.
// ===========================================================================
#define BM 128
#define BN 128
#define BK 32
#define NKT (DM_ / BK)            // 32
#define GT_TILE 8192              // 128 rows * 64B
#define GT_STAGE (3 * GT_TILE)    // 24576: Ahi, Alo, W
#define GEMM_SMEM (3 * GT_STAGE)  // 73728

__device__ __forceinline__ void load_ktile(uint32_t sb, int kt, int stage,
                                           const __half* Ahi, const __half* Alo,
                                           const __half* W,
                                           int rowBase, int colBase) {
    const int tid = threadIdx.x;
    const uint32_t base = sb + stage * GT_STAGE;
    const __half* srcs[3] = {
        Ahi + (size_t)rowBase * DM_ + kt * BK,
        Alo + (size_t)rowBase * DM_ + kt * BK,
        W   + (size_t)colBase * DM_ + kt * BK};
#pragma unroll
    for (int t = 0; t < 3; ++t) {
#pragma unroll
        for (int i = 0; i < 2; ++i) {
            int c = tid + i * 256;          // 0..511
            int r = c >> 2, ch = c & 3;
            cp16(base + t * GT_TILE + r * 64 + SWZ64B(r, ch),
                 srcs[t] + (size_t)r * DM_ + ch * 8);
        }
    }
}

__device__ __forceinline__ void gemm_body(
    const __half* __restrict__ Ahi, const __half* __restrict__ Alo,
    const __half* __restrict__ W,
    const float* __restrict__ bias, float* __restrict__ C,
    __half* __restrict__ Chi, __half* __restrict__ Clo,
    int mode, char* smem) {
    const uint32_t sb = smem_u32(smem);
    const int tid  = threadIdx.x;
    const int wid  = tid >> 5;
    const int lane = tid & 31;
    const int rowBase = blockIdx.y * BM;
    const int colBase = blockIdx.x * BN;

    const int mbase = (wid >> 1) * 32;
    const int nbase = (wid & 1) * 64;

    float acc[2][8][4];
#pragma unroll
    for (int i = 0; i < 2; ++i)
#pragma unroll
        for (int j = 0; j < 8; ++j)
#pragma unroll
            for (int q = 0; q < 4; ++q) acc[i][j][q] = 0.f;

    load_ktile(sb, 0, 0, Ahi, Alo, W, rowBase, colBase);
    CP_COMMIT();
    load_ktile(sb, 1, 1, Ahi, Alo, W, rowBase, colBase);
    CP_COMMIT();

    const int a_row = lane & 15;
    const int a_kb  = lane >> 4;
    const int b_row = ((lane >> 4) & 1) * 8 + (lane & 7);
    const int b_kb  = (lane >> 3) & 1;

    int cur = 0, pf = 2;
    for (int kt = 0; kt < NKT; ++kt) {
        if (kt + 1 < NKT) { CP_WAIT(1); } else { CP_WAIT(0); }
        __syncthreads();
        if (kt + 2 < NKT) {
            load_ktile(sb, kt + 2, pf, Ahi, Alo, W, rowBase, colBase);
            CP_COMMIT();
        }

        const uint32_t st = sb + cur * GT_STAGE;
#pragma unroll
        for (int s = 0; s < 2; ++s) {
            uint32_t ah[2][4], al[2][4];
#pragma unroll
            for (int i = 0; i < 2; ++i) {
                int row = mbase + i * 16 + a_row;
                uint32_t off = row * 64 + SWZ64B(row, s * 2 + a_kb);
                ldmx4(ah[i], st + 0 * GT_TILE + off);
                ldmx4(al[i], st + 1 * GT_TILE + off);
            }
#pragma unroll
            for (int jp = 0; jp < 4; ++jp) {
                int row = nbase + jp * 16 + b_row;
                uint32_t off = row * 64 + SWZ64B(row, s * 2 + b_kb);
                uint32_t tw[4];
                ldmx4(tw, st + 2 * GT_TILE + off);
                uint32_t b0[2] = {tw[0], tw[1]}, b1[2] = {tw[2], tw[3]};
#pragma unroll
                for (int i = 0; i < 2; ++i) {
                    mma_f16(acc[i][jp * 2],     ah[i], b0);
                    mma_f16(acc[i][jp * 2 + 1], ah[i], b1);
                    mma_f16(acc[i][jp * 2],     al[i], b0);
                    mma_f16(acc[i][jp * 2 + 1], al[i], b1);
                }
            }
        }
        cur = inc3(cur);
        pf  = inc3(pf);
    }

#pragma unroll
    for (int i = 0; i < 2; ++i) {
        const int r0 = rowBase + mbase + i * 16 + (lane >> 2);
#pragma unroll
        for (int j = 0; j < 8; ++j) {
            const int col = colBase + nbase + j * 8 + (lane & 3) * 2;
            const float b0 = bias[col], b1 = bias[col + 1];
            float f0 = acc[i][j][0] + b0, f1 = acc[i][j][1] + b1;
            float f2 = acc[i][j][2] + b0, f3 = acc[i][j][3] + b1;
            if (mode == 0) {
                *(float2*)(C + (size_t)r0 * DM_ + col)       = make_float2(f0, f1);
                *(float2*)(C + (size_t)(r0 + 8) * DM_ + col) = make_float2(f2, f3);
            } else {
                __half2 hh01 = __floats2half2_rn(f0, f1);
                __half2 hh23 = __floats2half2_rn(f2, f3);
                *(uint32_t*)(Chi + (size_t)r0 * DM_ + col)       = *(uint32_t*)&hh01;
                *(uint32_t*)(Chi + (size_t)(r0 + 8) * DM_ + col) = *(uint32_t*)&hh23;
                if (mode == 1) {
                    float r0f = f0 - __half2float(__low2half(hh01));
                    float r1f = f1 - __half2float(__high2half(hh01));
                    float r2f = f2 - __half2float(__low2half(hh23));
                    float r3f = f3 - __half2float(__high2half(hh23));
                    __half2 hl01 = __floats2half2_rn(r0f, r1f);
                    __half2 hl23 = __floats2half2_rn(r2f, r3f);
                    *(uint32_t*)(Clo + (size_t)r0 * DM_ + col)       = *(uint32_t*)&hl01;
                    *(uint32_t*)(Clo + (size_t)(r0 + 8) * DM_ + col) = *(uint32_t*)&hl23;
                }
            }
        }
    }
}

__global__ __launch_bounds__(256, 2)
void gemm_qkv(const __half* __restrict__ Ah0, const __half* __restrict__ Al0,
              const __half* __restrict__ Ah1, const __half* __restrict__ Al1,
              const __half* __restrict__ Ah2, const __half* __restrict__ Al2,
              const __half* __restrict__ W4,
              const float* __restrict__ b0, const float* __restrict__ b1,
              const float* __restrict__ b2,
              __half* __restrict__ Ch0, __half* __restrict__ Ch1,
              __half* __restrict__ Ch2) {
    extern __shared__ char smem[];
    const int z = blockIdx.z;
    const __half* Ah = (z == 0) ? Ah0 : (z == 1) ? Ah1 : Ah2;
    const __half* Al = (z == 0) ? Al0 : (z == 1) ? Al1 : Al2;
    const float* bias = (z == 0) ? b0 : (z == 1) ? b1 : b2;
    __half* Ch = (z == 0) ? Ch0 : (z == 1) ? Ch1 : Ch2;
    // Q, K, V all -> fp16 single (mode 2)
    gemm_body(Ah, Al, W4 + (size_t)z * DM_ * DM_,
              bias, nullptr, Ch, nullptr, 2, smem);
}

__global__ __launch_bounds__(256, 2)
void gemm_o(const __half* __restrict__ Ahi, const __half* __restrict__ Alo,
            const __half* __restrict__ W,
            const float* __restrict__ bias, float* __restrict__ C) {
    extern __shared__ char smem[];
    gemm_body(Ahi, Alo, W, bias, C, nullptr, nullptr, 0, smem);
}

// ===========================================================================
// Flash attention v9: single-precision fp16 tensor path (1 pass QK, 1 pass PV).
// Q single (registers), K single, V single. K ring[2] + V ring[2] = 32 KB.
// 128 q-rows/CTA, 2 CTAs/SM. Cross-tile software pipeline retained.
// ===========================================================================
#define KTT  8192                  // 64 rows * 128B
#define FA9_SMEM (4 * KTT)         // 32768

#define C2F 0.1803368801111204f    // log2(e)/8 (Dh=64 scale folded into exp2)
#define NT_ (S_ / 64)              // 32 kv tiles

__device__ __forceinline__ void fa_load_one(uint32_t dst, const __half* Src,
                                            size_t rowStart, int k0, int colOff) {
    const int tid = threadIdx.x;
    const __half* s = Src + (rowStart + k0) * DM_ + colOff;
#pragma unroll
    for (int i = 0; i < 2; ++i) {
        int c = tid + i * 256;           // 0..511
        int r = c >> 3, ch = c & 7;
        cp16(dst + r * 128 + SWZ128B(r, ch), s + (size_t)r * DM_ + ch * 8);
    }
}

// QK: s = Q(fp16 regs) @ K(fp16 smem)^T, single pass.
__device__ __forceinline__ void qk_tile(
    uint32_t ksBase, const uint32_t (&qh)[4][4],
    int b_row, int b_kb, float (&s)[8][4]) {
#pragma unroll
    for (int j = 0; j < 8; ++j)
#pragma unroll
        for (int q = 0; q < 4; ++q) s[j][q] = 0.f;
#pragma unroll
    for (int ks = 0; ks < 4; ++ks) {
#pragma unroll
        for (int ntp = 0; ntp < 4; ++ntp) {
            const int krow = ntp * 16 + b_row;
            const uint32_t koff = krow * 128 + SWZ128B(krow, ks * 2 + b_kb);
            uint32_t th[4];
            ldmx4(th, ksBase + koff);
            uint32_t k0h[2] = {th[0], th[1]}, k1h[2] = {th[2], th[3]};
            mma_f16(s[2 * ntp],     qh[ks], k0h);
            mma_f16(s[2 * ntp + 1], qh[ks], k1h);
        }
    }
}

// online softmax + pack P to single fp16 fragments.
__device__ __forceinline__ void softmax_pack(
    float (&s)[8][4], float (&o)[8][4],
    float& m0, float& m1, float& l0, float& l1,
    uint32_t (&Pa)[8], uint32_t (&Pb)[8]) {
    float rmax0 = -1e30f, rmax1 = -1e30f;
#pragma unroll
    for (int j = 0; j < 8; ++j) {
        rmax0 = fmaxf(rmax0, fmaxf(s[j][0], s[j][1]));
        rmax1 = fmaxf(rmax1, fmaxf(s[j][2], s[j][3]));
    }
    rmax0 = fmaxf(rmax0, __shfl_xor_sync(0xffffffffu, rmax0, 1));
    rmax0 = fmaxf(rmax0, __shfl_xor_sync(0xffffffffu, rmax0, 2));
    rmax1 = fmaxf(rmax1, __shfl_xor_sync(0xffffffffu, rmax1, 1));
    rmax1 = fmaxf(rmax1, __shfl_xor_sync(0xffffffffu, rmax1, 2));
    const float m0n = fmaxf(m0, rmax0);
    const float m1n = fmaxf(m1, rmax1);
    const float c0 = ex2f((m0 - m0n) * C2F);
    const float c1 = ex2f((m1 - m1n) * C2F);
    m0 = m0n; m1 = m1n;
    const float mc0 = m0 * C2F, mc1 = m1 * C2F;
    float sum0 = 0.f, sum1 = 0.f;
#pragma unroll
    for (int j = 0; j < 8; ++j) {
        s[j][0] = ex2f(fmaf(s[j][0], C2F, -mc0));
        s[j][1] = ex2f(fmaf(s[j][1], C2F, -mc0));
        s[j][2] = ex2f(fmaf(s[j][2], C2F, -mc1));
        s[j][3] = ex2f(fmaf(s[j][3], C2F, -mc1));
        sum0 += s[j][0] + s[j][1];
        sum1 += s[j][2] + s[j][3];
    }
    sum0 += __shfl_xor_sync(0xffffffffu, sum0, 1);
    sum0 += __shfl_xor_sync(0xffffffffu, sum0, 2);
    sum1 += __shfl_xor_sync(0xffffffffu, sum1, 1);
    sum1 += __shfl_xor_sync(0xffffffffu, sum1, 2);
    l0 = l0 * c0 + sum0;
    l1 = l1 * c1 + sum1;
#pragma unroll
    for (int j = 0; j < 8; ++j) {
        Pa[j] = pack_h2(s[j][0], s[j][1]);
        Pb[j] = pack_h2(s[j][2], s[j][3]);
    }
#pragma unroll
    for (int j = 0; j < 8; ++j) {
        o[j][0] *= c0; o[j][1] *= c0;
        o[j][2] *= c1; o[j][3] *= c1;
    }
}

// O += P @ V: single fp16 pass.
__device__ __forceinline__ void pv_accum(
    uint32_t vsBase, int v_k, int v_db,
    const uint32_t (&Pa)[8], const uint32_t (&Pb)[8],
    float (&o)[8][4]) {
#pragma unroll
    for (int ks = 0; ks < 4; ++ks) {
        uint32_t ap[4] = {Pa[2 * ks], Pb[2 * ks],
                          Pa[2 * ks + 1], Pb[2 * ks + 1]};
        const int vrow = 16 * ks + v_k;
#pragma unroll
        for (int dt = 0; dt < 4; ++dt) {
            const uint32_t off = vrow * 128 + SWZ128B(vrow, dt * 2 + v_db);
            uint32_t vh[4];
            ldmx4t(vh, vsBase + off);
            uint32_t b0[2] = {vh[0], vh[1]}, b1[2] = {vh[2], vh[3]};
            mma_f16(o[2 * dt],     ap, b0);
            mma_f16(o[2 * dt + 1], ap, b1);
        }
    }
}

__global__ __launch_bounds__(256, 2)
void flash_mma9(const __half* __restrict__ Qh,
                const __half* __restrict__ Kh,
                const __half* __restrict__ Vh,
                __half* __restrict__ AOh,
                __half* __restrict__ AOl) {
    extern __shared__ char smem[];
    const uint32_t sb = smem_u32(smem);
    const int tid = threadIdx.x, wid = tid >> 5, lane = tid & 31;
    const int bh = blockIdx.y, b = bh >> 4, h = bh & 15;
    const int q0 = blockIdx.x * 128;
    const size_t rowStart = (size_t)b * S_;
    const int colOff = h * DH_;

    // smem layout: 4 x 8 KB (Q staged over Ks0+Ks1 = first 16 KB)
    const uint32_t Ks0 = sb;
    const uint32_t Ks1 = sb + KTT;
    const uint32_t Vs0 = sb + 2 * KTT;
    const uint32_t Vs1 = sb + 3 * KTT;

    // ---- prologue: Q -> [Ks0..Ks1] (g1); V0 -> Vs0 (g2) ----
    {
        const __half* qsrc = Qh + (rowStart + q0) * DM_ + colOff;
#pragma unroll
        for (int i = 0; i < 4; ++i) {
            int c = tid + i * 256;           // 0..1023: r 0..127, ch 0..7
            int r = c >> 3, ch = c & 7;
            cp16(sb + r * 128 + SWZ128B(r, ch), qsrc + (size_t)r * DM_ + ch * 8);
        }
    }
    CP_COMMIT();                             // g1 (Q)
    fa_load_one(Vs0, Vh, rowStart, 0, colOff);
    CP_COMMIT();                             // g2 (V0)
    CP_WAIT(1);                              // g1 done
    __syncthreads();

    // fragment addressing
    const int a_row = lane & 15;
    const int a_kb  = lane >> 4;
    const int b_row = ((lane >> 4) & 1) * 8 + (lane & 7);
    const int b_kb  = (lane >> 3) & 1;
    const int v_k   = (lane & 7) + ((lane >> 3) & 1) * 8;
    const int v_db  = (lane >> 4) & 1;
    const int qrow  = 16 * wid + a_row;

    // ---- whole Q into registers (16 regs) ----
    uint32_t qh[4][4];
#pragma unroll
    for (int ks = 0; ks < 4; ++ks)
        ldmx4(qh[ks], sb + qrow * 128 + SWZ128B(qrow, ks * 2 + a_kb));
    __syncthreads();                         // all warps done with Q staging

    // ---- K0 -> Ks0, K1 -> Ks1 ----
    fa_load_one(Ks0, Kh, rowStart, 0, colOff);
    fa_load_one(Ks1, Kh, rowStart, 64, colOff);
    CP_COMMIT();                             // g3
    CP_WAIT(0);                              // V0, K0, K1 all landed
    __syncthreads();

    float m0 = -1e30f, m1 = -1e30f, l0 = 0.f, l1 = 0.f;
    float o[8][4];
#pragma unroll
    for (int j = 0; j < 8; ++j)
#pragma unroll
        for (int q = 0; q < 4; ++q) o[j][q] = 0.f;

    // ---- software-pipeline prologue: s(0) ----
    float s[8][4];
    qk_tile(Ks0, qh, b_row, b_kb, s);

    // ---- main loop ----
    for (int jt = 0; jt < NT_ - 1; ++jt) {
        CP_WAIT(0);
        __syncthreads();                 // K(jt+1), V(jt) resident
        const int kc = (jt + 2 < NT_) ? (jt + 2) : (NT_ - 1);
        fa_load_one((jt & 1) ? Ks1 : Ks0, Kh, rowStart, kc * 64, colOff);
        fa_load_one(((jt + 1) & 1) ? Vs1 : Vs0, Vh, rowStart,
                    (jt + 1) * 64, colOff);
        CP_COMMIT();

        uint32_t Pa[8], Pb[8];
        softmax_pack(s, o, m0, m1, l0, l1, Pa, Pb);
        qk_tile(((jt + 1) & 1) ? Ks1 : Ks0, qh, b_row, b_kb, s);
        pv_accum((jt & 1) ? Vs1 : Vs0, v_k, v_db, Pa, Pb, o);
    }

    // ---- tail ----
    CP_WAIT(0);
    __syncthreads();
    {
        uint32_t Pa[8], Pb[8];
        softmax_pack(s, o, m0, m1, l0, l1, Pa, Pb);
        pv_accum(((NT_ - 1) & 1) ? Vs1 : Vs0, v_k, v_db, Pa, Pb, o);
    }

    // ---- normalize, split to fp16 hi/lo, write ----
    const float i0 = 1.f / l0, i1 = 1.f / l1;
    const size_t row0 = rowStart + q0 + 16 * wid + (lane >> 2);
    const size_t row1 = row0 + 8;
#pragma unroll
    for (int j = 0; j < 8; ++j) {
        const int col = colOff + j * 8 + (lane & 3) * 2;
        float f0 = o[j][0] * i0, f1 = o[j][1] * i0;
        float f2 = o[j][2] * i1, f3 = o[j][3] * i1;
        __half2 hh01 = __floats2half2_rn(f0, f1);
        __half2 hh23 = __floats2half2_rn(f2, f3);
        float r0f = f0 - __half2float(__low2half(hh01));
        float r1f = f1 - __half2float(__high2half(hh01));
        float r2f = f2 - __half2float(__low2half(hh23));
        float r3f = f3 - __half2float(__high2half(hh23));
        __half2 hl01 = __floats2half2_rn(r0f, r1f);
        __half2 hl23 = __floats2half2_rn(r2f, r3f);
        *(uint32_t*)(AOh + row0 * DM_ + col) = *(uint32_t*)&hh01;
        *(uint32_t*)(AOh + row1 * DM_ + col) = *(uint32_t*)&hh23;
        *(uint32_t*)(AOl + row0 * DM_ + col) = *(uint32_t*)&hl01;
        *(uint32_t*)(AOl + row1 * DM_ + col) = *(uint32_t*)&hl23;
    }
}

// ===========================================================================
// Launch
// ===========================================================================
extern "C" void kernel_launch(void* const* d_in, const int* in_sizes, int n_in,
                              void* d_out, int out_size)
{
    const float* query = (const float*)d_in[0];
    const float* key   = (const float*)d_in[1];
    const float* value = (const float*)d_in[2];
    const float* Wq    = (const float*)d_in[3];
    const float* bq    = (const float*)d_in[4];
    const float* Wk    = (const float*)d_in[5];
    const float* bk    = (const float*)d_in[6];
    const float* Wv    = (const float*)d_in[7];
    const float* bv    = (const float*)d_in[8];
    const float* Wo    = (const float*)d_in[9];
    const float* bo    = (const float*)d_in[10];
    float* out = (float*)d_out;

    __half *pIh, *pIl, *pW4;
    __half *pQh, *pKh, *pVh, *pAOh, *pAOl;
    cudaGetSymbolAddress((void**)&pIh,  g_Ih);
    cudaGetSymbolAddress((void**)&pIl,  g_Il);
    cudaGetSymbolAddress((void**)&pW4,  g_W4);
    cudaGetSymbolAddress((void**)&pQh,  g_Qh);
    cudaGetSymbolAddress((void**)&pKh,  g_Kh);
    cudaGetSymbolAddress((void**)&pVh,  g_Vh);
    cudaGetSymbolAddress((void**)&pAOh, g_AOh);
    cudaGetSymbolAddress((void**)&pAOl, g_AOl);

    const size_t NTOK = (size_t)ROWS_ * DM_;

    static bool attrs_set = false;
    if (!attrs_set) {
        cudaFuncSetAttribute(gemm_qkv, cudaFuncAttributeMaxDynamicSharedMemorySize, GEMM_SMEM);
        cudaFuncSetAttribute(gemm_o,   cudaFuncAttributeMaxDynamicSharedMemorySize, GEMM_SMEM);
        cudaFuncSetAttribute(flash_mma9, cudaFuncAttributeMaxDynamicSharedMemorySize, FA9_SMEM);
        attrs_set = true;
    }

    const int n4 = ROWS_ * DM_ / 4;

    // 1) split all three inputs (fp16 hi/lo)
    split3<<<dim3((n4 + 255) / 256, 3), 256>>>(
        (const float4*)query, (const float4*)key, (const float4*)value,
        pIh + 0 * NTOK, pIl + 0 * NTOK,
        pIh + 1 * NTOK, pIl + 1 * NTOK,
        pIh + 2 * NTOK, pIl + 2 * NTOK, n4);

    // 2) transpose all four weights to fp16 single
    wtsplit4<<<dim3(32, 32, 4), dim3(32, 8)>>>(Wq, Wk, Wv, Wo, pW4);

    // 3) Q,K,V projections (2-pass fp16; all outputs fp16 single)
    gemm_qkv<<<dim3(DM_ / BN, ROWS_ / BM, 3), 256, GEMM_SMEM>>>(
        pIh + 0 * NTOK, pIl + 0 * NTOK,
        pIh + 1 * NTOK, pIl + 1 * NTOK,
        pIh + 2 * NTOK, pIl + 2 * NTOK,
        pW4, bq, bk, bv,
        pQh, pKh, pVh);

    // 4) attention (single-pass fp16 QK and PV; writes fp16 hi/lo)
    flash_mma9<<<dim3(S_ / 128, B_ * NH_), 256, FA9_SMEM>>>(
        pQh, pKh, pVh, pAOh, pAOl);

    // 5) output projection (2-pass fp16, fp32 result)
    gemm_o<<<dim3(DM_ / BN, ROWS_ / BM), 256, GEMM_SMEM>>>(
        pAOh, pAOl, pW4 + 3 * (size_t)DM_ * DM_, bo, out);
}

// round 14
// speedup vs baseline: 2.5804x; 1.3653x over previous
#include <cuda_runtime.h>
#include <cuda_bf16.h>
#include <cuda_fp16.h>
#include <math.h>
#include <cstdint>

// ---------------------------------------------------------------------------
// Problem constants
// ---------------------------------------------------------------------------
#define B_    4
#define S_    2048
#define DM_   1024
#define NH_   16
#define DH_   64
#define ROWS_ (B_ * S_)          // 8192

// ---------------------------------------------------------------------------
// Scratch (device globals: allocation-free per harness rules)
// ---------------------------------------------------------------------------
__device__ __half g_I4[3][ROWS_ * DM_];   // inputs (q,k,v) fp16 single
__device__ __half g_W4[4][DM_ * DM_];     // W^T fp16 single (q,k,v,o)
__device__ __half g_Qh[ROWS_ * DM_];      // fp16 single
__device__ __half g_Kh[ROWS_ * DM_];      // fp16 single
__device__ __half g_Vh[ROWS_ * DM_];      // fp16 single
__device__ __half g_AOh[ROWS_ * DM_];     // attention out fp16 single

// ===========================================================================
// Generic-PTX helpers (legal on plain sm_103 target: sm_80+ instructions)
// ===========================================================================
__device__ __forceinline__ uint32_t smem_u32(const void* p) {
    uint32_t a;
    asm("{ .reg .u64 t; cvta.to.shared.u64 t, %1; cvt.u32.u64 %0, t; }"
        : "=r"(a) : "l"(p));
    return a;
}

__device__ __forceinline__ void cp16(uint32_t s, const void* g) {
    asm volatile("cp.async.cg.shared.global [%0], [%1], 16;" :: "r"(s), "l"(g));
}
#define CP_COMMIT() asm volatile("cp.async.commit_group;" ::: "memory")
#define CP_WAIT(n)  asm volatile("cp.async.wait_group %0;" :: "n"(n) : "memory")

__device__ __forceinline__ void ldmx4(uint32_t* r, uint32_t addr) {
    asm volatile("ldmatrix.sync.aligned.m8n8.x4.shared.b16 {%0,%1,%2,%3}, [%4];"
                 : "=r"(r[0]), "=r"(r[1]), "=r"(r[2]), "=r"(r[3]) : "r"(addr));
}

__device__ __forceinline__ void ldmx4t(uint32_t* r, uint32_t addr) {
    asm volatile("ldmatrix.sync.aligned.m8n8.x4.trans.shared.b16 {%0,%1,%2,%3}, [%4];"
                 : "=r"(r[0]), "=r"(r[1]), "=r"(r[2]), "=r"(r[3]) : "r"(addr));
}

__device__ __forceinline__ void mma_f16(float* d, const uint32_t* a,
                                        const uint32_t* b) {
    asm volatile(
        "mma.sync.aligned.m16n8k16.row.col.f32.f16.f16.f32 "
        "{%0,%1,%2,%3}, {%4,%5,%6,%7}, {%8,%9}, {%0,%1,%2,%3};"
        : "+f"(d[0]), "+f"(d[1]), "+f"(d[2]), "+f"(d[3])
        : "r"(a[0]), "r"(a[1]), "r"(a[2]), "r"(a[3]), "r"(b[0]), "r"(b[1]));
}

__device__ __forceinline__ uint32_t pack_h2(float lo_elem, float hi_elem) {
    __half2 h = __floats2half2_rn(lo_elem, hi_elem);   // .x = lo bits
    return *reinterpret_cast<uint32_t*>(&h);
}

__device__ __forceinline__ float ex2f(float x) {
    float y;
    asm("ex2.approx.ftz.f32 %0, %1;" : "=f"(y) : "f"(x));
    return y;
}

// XOR swizzles: conflict-free ldmatrix on unpadded rows.
#define SWZ128B(r, ch) ((((ch) ^ ((r) & 7)) << 4))
#define SWZ64B(r, ch)  ((((ch) ^ (((r) >> 1) & 3)) << 4))

__device__ __forceinline__ int inc3(int x) { return (x == 2) ? 0 : x + 1; }

// ===========================================================================
// Prep: convert 3 inputs to fp16 single; transpose 4 weights to fp16 single
// ===========================================================================
__global__ __launch_bounds__(256)
void cvt3(const float4* __restrict__ x0, const float4* __restrict__ x1,
          const float4* __restrict__ x2,
          __half* __restrict__ h0, __half* __restrict__ h1,
          __half* __restrict__ h2, int n4) {
    int i = blockIdx.x * blockDim.x + threadIdx.x;
    if (i >= n4) return;
    const int z = blockIdx.y;
    const float4* x = (z == 0) ? x0 : (z == 1) ? x1 : x2;
    __half* hi = (z == 0) ? h0 : (z == 1) ? h1 : h2;
    float4 v = x[i];
    __half2 a = __floats2half2_rn(v.x, v.y);
    __half2 b = __floats2half2_rn(v.z, v.w);
    ((__half2*)hi)[i * 2 + 0] = a;
    ((__half2*)hi)[i * 2 + 1] = b;
}

__global__ __launch_bounds__(256)
void wtsplit4(const float* __restrict__ w0, const float* __restrict__ w1,
              const float* __restrict__ w2, const float* __restrict__ w3,
              __half* __restrict__ hi4) {
    __shared__ float t[32][33];
    const int z = blockIdx.z;
    const float* W = (z == 0) ? w0 : (z == 1) ? w1 : (z == 2) ? w2 : w3;
    __half* hi = hi4 + (size_t)z * DM_ * DM_;
    const int n0 = blockIdx.x * 32;
    const int k0 = blockIdx.y * 32;
    const int tx = threadIdx.x, ty = threadIdx.y;
#pragma unroll
    for (int i = 0; i < 4; ++i)
        t[ty + i * 8][tx] = W[(size_t)(k0 + ty + i * 8) * DM_ + n0 + tx];
    __syncthreads();
#pragma unroll
    for (int i = 0; i < 4; ++i) {
        float v = t[tx][ty + i * 8];
        hi[(size_t)(n0 + ty + i * 8) * DM_ + k0 + tx] = __float2half_rn(v);
    }
}

// ===========================================================================
// HMMA GEMM (fp16 single, 1 pass):  C = A @ Wt^T + bias
// 3-stage cp.async ring, 1 sync/ktile, XOR-swizzled 64B rows. 2 CTAs/SM.
// Epilogue modes: 0 = fp32, 2 = fp16 single.
// ===========================================================================
#define BM 128
#define BN 128
#define BK 32
#define NKT (DM_ / BK)            // 32
#define GT_TILE 8192              // 128 rows * 64B
#define GT_STAGE (2 * GT_TILE)    // 16384: A, W
#define GEMM_SMEM (3 * GT_STAGE)  // 49152

__device__ __forceinline__ void load_ktile(uint32_t sb, int kt, int stage,
                                           const __half* A, const __half* W,
                                           int rowBase, int colBase) {
    const int tid = threadIdx.x;
    const uint32_t base = sb + stage * GT_STAGE;
    const __half* srcs[2] = {
        A + (size_t)rowBase * DM_ + kt * BK,
        W + (size_t)colBase * DM_ + kt * BK};
#pragma unroll
    for (int t = 0; t < 2; ++t) {
#pragma unroll
        for (int i = 0; i < 2; ++i) {
            int c = tid + i * 256;          // 0..511
            int r = c >> 2, ch = c & 3;
            cp16(base + t * GT_TILE + r * 64 + SWZ64B(r, ch),
                 srcs[t] + (size_t)r * DM_ + ch * 8);
        }
    }
}

__device__ __forceinline__ void gemm_body(
    const __half* __restrict__ A, const __half* __restrict__ W,
    const float* __restrict__ bias, float* __restrict__ C,
    __half* __restrict__ Ch, int mode, char* smem) {
    const uint32_t sb = smem_u32(smem);
    const int tid  = threadIdx.x;
    const int wid  = tid >> 5;
    const int lane = tid & 31;
    const int rowBase = blockIdx.y * BM;
    const int colBase = blockIdx.x * BN;

    const int mbase = (wid >> 1) * 32;
    const int nbase = (wid & 1) * 64;

    float acc[2][8][4];
#pragma unroll
    for (int i = 0; i < 2; ++i)
#pragma unroll
        for (int j = 0; j < 8; ++j)
#pragma unroll
            for (int q = 0; q < 4; ++q) acc[i][j][q] = 0.f;

    load_ktile(sb, 0, 0, A, W, rowBase, colBase);
    CP_COMMIT();
    load_ktile(sb, 1, 1, A, W, rowBase, colBase);
    CP_COMMIT();

    const int a_row = lane & 15;
    const int a_kb  = lane >> 4;
    const int b_row = ((lane >> 4) & 1) * 8 + (lane & 7);
    const int b_kb  = (lane >> 3) & 1;

    int cur = 0, pf = 2;
    for (int kt = 0; kt < NKT; ++kt) {
        if (kt + 1 < NKT) { CP_WAIT(1); } else { CP_WAIT(0); }
        __syncthreads();
        if (kt + 2 < NKT) {
            load_ktile(sb, kt + 2, pf, A, W, rowBase, colBase);
            CP_COMMIT();
        }

        const uint32_t st = sb + cur * GT_STAGE;
#pragma unroll
        for (int s = 0; s < 2; ++s) {
            uint32_t ah[2][4];
#pragma unroll
            for (int i = 0; i < 2; ++i) {
                int row = mbase + i * 16 + a_row;
                uint32_t off = row * 64 + SWZ64B(row, s * 2 + a_kb);
                ldmx4(ah[i], st + 0 * GT_TILE + off);
            }
#pragma unroll
            for (int jp = 0; jp < 4; ++jp) {
                int row = nbase + jp * 16 + b_row;
                uint32_t off = row * 64 + SWZ64B(row, s * 2 + b_kb);
                uint32_t tw[4];
                ldmx4(tw, st + 1 * GT_TILE + off);
                uint32_t b0[2] = {tw[0], tw[1]}, b1[2] = {tw[2], tw[3]};
#pragma unroll
                for (int i = 0; i < 2; ++i) {
                    mma_f16(acc[i][jp * 2],     ah[i], b0);
                    mma_f16(acc[i][jp * 2 + 1], ah[i], b1);
                }
            }
        }
        cur = inc3(cur);
        pf  = inc3(pf);
    }

#pragma unroll
    for (int i = 0; i < 2; ++i) {
        const int r0 = rowBase + mbase + i * 16 + (lane >> 2);
#pragma unroll
        for (int j = 0; j < 8; ++j) {
            const int col = colBase + nbase + j * 8 + (lane & 3) * 2;
            const float b0 = bias[col], b1 = bias[col + 1];
            float f0 = acc[i][j][0] + b0, f1 = acc[i][j][1] + b1;
            float f2 = acc[i][j][2] + b0, f3 = acc[i][j][3] + b1;
            if (mode == 0) {
                *(float2*)(C + (size_t)r0 * DM_ + col)       = make_float2(f0, f1);
                *(float2*)(C + (size_t)(r0 + 8) * DM_ + col) = make_float2(f2, f3);
            } else {
                __half2 hh01 = __floats2half2_rn(f0, f1);
                __half2 hh23 = __floats2half2_rn(f2, f3);
                *(uint32_t*)(Ch + (size_t)r0 * DM_ + col)       = *(uint32_t*)&hh01;
                *(uint32_t*)(Ch + (size_t)(r0 + 8) * DM_ + col) = *(uint32_t*)&hh23;
            }
        }
    }
}

__global__ __launch_bounds__(256, 2)
void gemm_qkv(const __half* __restrict__ A0, const __half* __restrict__ A1,
              const __half* __restrict__ A2, const __half* __restrict__ W4,
              const float* __restrict__ b0, const float* __restrict__ b1,
              const float* __restrict__ b2,
              __half* __restrict__ C0, __half* __restrict__ C1,
              __half* __restrict__ C2) {
    extern __shared__ char smem[];
    const int z = blockIdx.z;
    const __half* A = (z == 0) ? A0 : (z == 1) ? A1 : A2;
    const float* bias = (z == 0) ? b0 : (z == 1) ? b1 : b2;
    __half* Ch = (z == 0) ? C0 : (z == 1) ? C1 : C2;
    gemm_body(A, W4 + (size_t)z * DM_ * DM_, bias, nullptr, Ch, 2, smem);
}

__global__ __launch_bounds__(256, 2)
void gemm_o(const __half* __restrict__ A, const __half* __restrict__ W,
            const float* __restrict__ bias, float* __restrict__ C) {
    extern __shared__ char smem[];
    gemm_body(A, W, bias, C, nullptr, 0, smem);
}

// ===========================================================================
// Flash attention v9 (single-pass fp16; writes AO fp16 single).
// Q single (registers), K single, V single. K ring[2] + V ring[2] = 32 KB.
// 128 q-rows/CTA, 2 CTAs/SM. Cross-tile software pipeline.
// ===========================================================================
#define KTT  8192                  // 64 rows * 128B
#define FA9_SMEM (4 * KTT)         // 32768

#define C2F 0.1803368801111204f    // log2(e)/8 (Dh=64 scale folded into exp2)
#define NT_ (S_ / 64)              // 32 kv tiles

__device__ __forceinline__ void fa_load_one(uint32_t dst, const __half* Src,
                                            size_t rowStart, int k0, int colOff) {
    const int tid = threadIdx.x;
    const __half* s = Src + (rowStart + k0) * DM_ + colOff;
#pragma unroll
    for (int i = 0; i < 2; ++i) {
        int c = tid + i * 256;           // 0..511
        int r = c >> 3, ch = c & 7;
        cp16(dst + r * 128 + SWZ128B(r, ch), s + (size_t)r * DM_ + ch * 8);
    }
}

__device__ __forceinline__ void qk_tile(
    uint32_t ksBase, const uint32_t (&qh)[4][4],
    int b_row, int b_kb, float (&s)[8][4]) {
#pragma unroll
    for (int j = 0; j < 8; ++j)
#pragma unroll
        for (int q = 0; q < 4; ++q) s[j][q] = 0.f;
#pragma unroll
    for (int ks = 0; ks < 4; ++ks) {
#pragma unroll
        for (int ntp = 0; ntp < 4; ++ntp) {
            const int krow = ntp * 16 + b_row;
            const uint32_t koff = krow * 128 + SWZ128B(krow, ks * 2 + b_kb);
            uint32_t th[4];
            ldmx4(th, ksBase + koff);
            uint32_t k0h[2] = {th[0], th[1]}, k1h[2] = {th[2], th[3]};
            mma_f16(s[2 * ntp],     qh[ks], k0h);
            mma_f16(s[2 * ntp + 1], qh[ks], k1h);
        }
    }
}

__device__ __forceinline__ void softmax_pack(
    float (&s)[8][4], float (&o)[8][4],
    float& m0, float& m1, float& l0, float& l1,
    uint32_t (&Pa)[8], uint32_t (&Pb)[8]) {
    float rmax0 = -1e30f, rmax1 = -1e30f;
#pragma unroll
    for (int j = 0; j < 8; ++j) {
        rmax0 = fmaxf(rmax0, fmaxf(s[j][0], s[j][1]));
        rmax1 = fmaxf(rmax1, fmaxf(s[j][2], s[j][3]));
    }
    rmax0 = fmaxf(rmax0, __shfl_xor_sync(0xffffffffu, rmax0, 1));
    rmax0 = fmaxf(rmax0, __shfl_xor_sync(0xffffffffu, rmax0, 2));
    rmax1 = fmaxf(rmax1, __shfl_xor_sync(0xffffffffu, rmax1, 1));
    rmax1 = fmaxf(rmax1, __shfl_xor_sync(0xffffffffu, rmax1, 2));
    const float m0n = fmaxf(m0, rmax0);
    const float m1n = fmaxf(m1, rmax1);
    const float c0 = ex2f((m0 - m0n) * C2F);
    const float c1 = ex2f((m1 - m1n) * C2F);
    m0 = m0n; m1 = m1n;
    const float mc0 = m0 * C2F, mc1 = m1 * C2F;
    float sum0 = 0.f, sum1 = 0.f;
#pragma unroll
    for (int j = 0; j < 8; ++j) {
        s[j][0] = ex2f(fmaf(s[j][0], C2F, -mc0));
        s[j][1] = ex2f(fmaf(s[j][1], C2F, -mc0));
        s[j][2] = ex2f(fmaf(s[j][2], C2F, -mc1));
        s[j][3] = ex2f(fmaf(s[j][3], C2F, -mc1));
        sum0 += s[j][0] + s[j][1];
        sum1 += s[j][2] + s[j][3];
    }
    sum0 += __shfl_xor_sync(0xffffffffu, sum0, 1);
    sum0 += __shfl_xor_sync(0xffffffffu, sum0, 2);
    sum1 += __shfl_xor_sync(0xffffffffu, sum1, 1);
    sum1 += __shfl_xor_sync(0xffffffffu, sum1, 2);
    l0 = l0 * c0 + sum0;
    l1 = l1 * c1 + sum1;
#pragma unroll
    for (int j = 0; j < 8; ++j) {
        Pa[j] = pack_h2(s[j][0], s[j][1]);
        Pb[j] = pack_h2(s[j][2], s[j][3]);
    }
#pragma unroll
    for (int j = 0; j < 8; ++j) {
        o[j][0] *= c0; o[j][1] *= c0;
        o[j][2] *= c1; o[j][3] *= c1;
    }
}

__device__ __forceinline__ void pv_accum(
    uint32_t vsBase, int v_k, int v_db,
    const uint32_t (&Pa)[8], const uint32_t (&Pb)[8],
    float (&o)[8][4]) {
#pragma unroll
    for (int ks = 0; ks < 4; ++ks) {
        uint32_t ap[4] = {Pa[2 * ks], Pb[2 * ks],
                          Pa[2 * ks + 1], Pb[2 * ks + 1]};
        const int vrow = 16 * ks + v_k;
#pragma unroll
        for (int dt = 0; dt < 4; ++dt) {
            const uint32_t off = vrow * 128 + SWZ128B(vrow, dt * 2 + v_db);
            uint32_t vh[4];
            ldmx4t(vh, vsBase + off);
            uint32_t b0[2] = {vh[0], vh[1]}, b1[2] = {vh[2], vh[3]};
            mma_f16(o[2 * dt],     ap, b0);
            mma_f16(o[2 * dt + 1], ap, b1);
        }
    }
}

__global__ __launch_bounds__(256, 2)
void flash_mma9(const __half* __restrict__ Qh,
                const __half* __restrict__ Kh,
                const __half* __restrict__ Vh,
                __half* __restrict__ AOh) {
    extern __shared__ char smem[];
    const uint32_t sb = smem_u32(smem);
    const int tid = threadIdx.x, wid = tid >> 5, lane = tid & 31;
    const int bh = blockIdx.y, b = bh >> 4, h = bh & 15;
    const int q0 = blockIdx.x * 128;
    const size_t rowStart = (size_t)b * S_;
    const int colOff = h * DH_;

    const uint32_t Ks0 = sb;
    const uint32_t Ks1 = sb + KTT;
    const uint32_t Vs0 = sb + 2 * KTT;
    const uint32_t Vs1 = sb + 3 * KTT;

    // ---- prologue: Q -> [Ks0..Ks1] (g1); V0 -> Vs0 (g2) ----
    {
        const __half* qsrc = Qh + (rowStart + q0) * DM_ + colOff;
#pragma unroll
        for (int i = 0; i < 4; ++i) {
            int c = tid + i * 256;           // 0..1023: r 0..127, ch 0..7
            int r = c >> 3, ch = c & 7;
            cp16(sb + r * 128 + SWZ128B(r, ch), qsrc + (size_t)r * DM_ + ch * 8);
        }
    }
    CP_COMMIT();                             // g1 (Q)
    fa_load_one(Vs0, Vh, rowStart, 0, colOff);
    CP_COMMIT();                             // g2 (V0)
    CP_WAIT(1);                              // g1 done
    __syncthreads();

    const int a_row = lane & 15;
    const int a_kb  = lane >> 4;
    const int b_row = ((lane >> 4) & 1) * 8 + (lane & 7);
    const int b_kb  = (lane >> 3) & 1;
    const int v_k   = (lane & 7) + ((lane >> 3) & 1) * 8;
    const int v_db  = (lane >> 4) & 1;
    const int qrow  = 16 * wid + a_row;

    uint32_t qh[4][4];
#pragma unroll
    for (int ks = 0; ks < 4; ++ks)
        ldmx4(qh[ks], sb + qrow * 128 + SWZ128B(qrow, ks * 2 + a_kb));
    __syncthreads();                         // all warps done with Q staging

    fa_load_one(Ks0, Kh, rowStart, 0, colOff);
    fa_load_one(Ks1, Kh, rowStart, 64, colOff);
    CP_COMMIT();                             // g3
    CP_WAIT(0);                              // V0, K0, K1 landed
    __syncthreads();

    float m0 = -1e30f, m1 = -1e30f, l0 = 0.f, l1 = 0.f;
    float o[8][4];
#pragma unroll
    for (int j = 0; j < 8; ++j)
#pragma unroll
        for (int q = 0; q < 4; ++q) o[j][q] = 0.f;

    float s[8][4];
    qk_tile(Ks0, qh, b_row, b_kb, s);

    for (int jt = 0; jt < NT_ - 1; ++jt) {
        CP_WAIT(0);
        __syncthreads();                 // K(jt+1), V(jt) resident
        const int kc = (jt + 2 < NT_) ? (jt + 2) : (NT_ - 1);
        fa_load_one((jt & 1) ? Ks1 : Ks0, Kh, rowStart, kc * 64, colOff);
        fa_load_one(((jt + 1) & 1) ? Vs1 : Vs0, Vh, rowStart,
                    (jt + 1) * 64, colOff);
        CP_COMMIT();

        uint32_t Pa[8], Pb[8];
        softmax_pack(s, o, m0, m1, l0, l1, Pa, Pb);
        qk_tile(((jt + 1) & 1) ? Ks1 : Ks0, qh, b_row, b_kb, s);
        pv_accum((jt & 1) ? Vs1 : Vs0, v_k, v_db, Pa, Pb, o);
    }

    CP_WAIT(0);
    __syncthreads();
    {
        uint32_t Pa[8], Pb[8];
        softmax_pack(s, o, m0, m1, l0, l1, Pa, Pb);
        pv_accum(((NT_ - 1) & 1) ? Vs1 : Vs0, v_k, v_db, Pa, Pb, o);
    }

    // ---- normalize, write fp16 single ----
    const float i0 = 1.f / l0, i1 = 1.f / l1;
    const size_t row0 = rowStart + q0 + 16 * wid + (lane >> 2);
    const size_t row1 = row0 + 8;
#pragma unroll
    for (int j = 0; j < 8; ++j) {
        const int col = colOff + j * 8 + (lane & 3) * 2;
        __half2 hh01 = __floats2half2_rn(o[j][0] * i0, o[j][1] * i0);
        __half2 hh23 = __floats2half2_rn(o[j][2] * i1, o[j][3] * i1);
        *(uint32_t*)(AOh + row0 * DM_ + col) = *(uint32_t*)&hh01;
        *(uint32_t*)(AOh + row1 * DM_ + col) = *(uint32_t*)&hh23;
    }
}

// ===========================================================================
// Launch
// ===========================================================================
extern "C" void kernel_launch(void* const* d_in, const int* in_sizes, int n_in,
                              void* d_out, int out_size)
{
    const float* query = (const float*)d_in[0];
    const float* key   = (const float*)d_in[1];
    const float* value = (const float*)d_in[2];
    const float* Wq    = (const float*)d_in[3];
    const float* bq    = (const float*)d_in[4];
    const float* Wk    = (const float*)d_in[5];
    const float* bk    = (const float*)d_in[6];
    const float* Wv    = (const float*)d_in[7];
    const float* bv    = (const float*)d_in[8];
    const float* Wo    = (const float*)d_in[9];
    const float* bo    = (const float*)d_in[10];
    float* out = (float*)d_out;

    __half *pI4, *pW4, *pQh, *pKh, *pVh, *pAOh;
    cudaGetSymbolAddress((void**)&pI4,  g_I4);
    cudaGetSymbolAddress((void**)&pW4,  g_W4);
    cudaGetSymbolAddress((void**)&pQh,  g_Qh);
    cudaGetSymbolAddress((void**)&pKh,  g_Kh);
    cudaGetSymbolAddress((void**)&pVh,  g_Vh);
    cudaGetSymbolAddress((void**)&pAOh, g_AOh);

    const size_t NTOK = (size_t)ROWS_ * DM_;

    static bool attrs_set = false;
    if (!attrs_set) {
        cudaFuncSetAttribute(gemm_qkv, cudaFuncAttributeMaxDynamicSharedMemorySize, GEMM_SMEM);
        cudaFuncSetAttribute(gemm_o,   cudaFuncAttributeMaxDynamicSharedMemorySize, GEMM_SMEM);
        cudaFuncSetAttribute(flash_mma9, cudaFuncAttributeMaxDynamicSharedMemorySize, FA9_SMEM);
        attrs_set = true;
    }

    const int n4 = ROWS_ * DM_ / 4;

    // 1) convert all three inputs to fp16 single
    cvt3<<<dim3((n4 + 255) / 256, 3), 256>>>(
        (const float4*)query, (const float4*)key, (const float4*)value,
        pI4 + 0 * NTOK, pI4 + 1 * NTOK, pI4 + 2 * NTOK, n4);

    // 2) transpose all four weights to fp16 single
    wtsplit4<<<dim3(32, 32, 4), dim3(32, 8)>>>(Wq, Wk, Wv, Wo, pW4);

    // 3) Q,K,V projections (1-pass fp16)
    gemm_qkv<<<dim3(DM_ / BN, ROWS_ / BM, 3), 256, GEMM_SMEM>>>(
        pI4 + 0 * NTOK, pI4 + 1 * NTOK, pI4 + 2 * NTOK,
        pW4, bq, bk, bv, pQh, pKh, pVh);

    // 4) attention (single-pass fp16 QK and PV; writes fp16 single)
    flash_mma9<<<dim3(S_ / 128, B_ * NH_), 256, FA9_SMEM>>>(
        pQh, pKh, pVh, pAOh);

    // 5) output projection (1-pass fp16, fp32 result)
    gemm_o<<<dim3(DM_ / BN, ROWS_ / BM), 256, GEMM_SMEM>>>(
        pAOh, pW4 + 3 * (size_t)DM_ * DM_, bo, out);
}

// round 15
// speedup vs baseline: 2.7076x; 1.0493x over previous
#include <cuda_runtime.h>
#include <cuda_bf16.h>
#include <cuda_fp16.h>
#include <math.h>
#include <cstdint>

// ---------------------------------------------------------------------------
// Problem constants
// ---------------------------------------------------------------------------
#define B_    4
#define S_    2048
#define DM_   1024
#define NH_   16
#define DH_   64
#define ROWS_ (B_ * S_)          // 8192

// ---------------------------------------------------------------------------
// Scratch (device globals: allocation-free per harness rules)
// ---------------------------------------------------------------------------
__device__ __half g_I4[3][ROWS_ * DM_];   // inputs (q,k,v) fp16 single
__device__ __half g_W4[4][DM_ * DM_];     // W^T fp16 single (q,k,v,o)
__device__ __half g_Qh[ROWS_ * DM_];      // fp16 single
__device__ __half g_Kh[ROWS_ * DM_];      // fp16 single
__device__ __half g_Vh[ROWS_ * DM_];      // fp16 single
__device__ __half g_AOh[ROWS_ * DM_];     // attention out fp16 single

// ===========================================================================
// Generic-PTX helpers (legal on plain sm_103 target: sm_80+ instructions)
// ===========================================================================
__device__ __forceinline__ uint32_t smem_u32(const void* p) {
    uint32_t a;
    asm("{ .reg .u64 t; cvta.to.shared.u64 t, %1; cvt.u32.u64 %0, t; }"
        : "=r"(a) : "l"(p));
    return a;
}

__device__ __forceinline__ void cp16(uint32_t s, const void* g) {
    asm volatile("cp.async.cg.shared.global [%0], [%1], 16;" :: "r"(s), "l"(g));
}
#define CP_COMMIT() asm volatile("cp.async.commit_group;" ::: "memory")
#define CP_WAIT(n)  asm volatile("cp.async.wait_group %0;" :: "n"(n) : "memory")

__device__ __forceinline__ void ldmx4(uint32_t* r, uint32_t addr) {
    asm volatile("ldmatrix.sync.aligned.m8n8.x4.shared.b16 {%0,%1,%2,%3}, [%4];"
                 : "=r"(r[0]), "=r"(r[1]), "=r"(r[2]), "=r"(r[3]) : "r"(addr));
}

__device__ __forceinline__ void ldmx4t(uint32_t* r, uint32_t addr) {
    asm volatile("ldmatrix.sync.aligned.m8n8.x4.trans.shared.b16 {%0,%1,%2,%3}, [%4];"
                 : "=r"(r[0]), "=r"(r[1]), "=r"(r[2]), "=r"(r[3]) : "r"(addr));
}

__device__ __forceinline__ void mma_f16(float* d, const uint32_t* a,
                                        const uint32_t* b) {
    asm volatile(
        "mma.sync.aligned.m16n8k16.row.col.f32.f16.f16.f32 "
        "{%0,%1,%2,%3}, {%4,%5,%6,%7}, {%8,%9}, {%0,%1,%2,%3};"
        : "+f"(d[0]), "+f"(d[1]), "+f"(d[2]), "+f"(d[3])
        : "r"(a[0]), "r"(a[1]), "r"(a[2]), "r"(a[3]), "r"(b[0]), "r"(b[1]));
}

__device__ __forceinline__ uint32_t pack_h2(float lo_elem, float hi_elem) {
    __half2 h = __floats2half2_rn(lo_elem, hi_elem);   // .x = lo bits
    return *reinterpret_cast<uint32_t*>(&h);
}

__device__ __forceinline__ float ex2f(float x) {
    float y;
    asm("ex2.approx.ftz.f32 %0, %1;" : "=f"(y) : "f"(x));
    return y;
}

// XOR swizzles: conflict-free ldmatrix on unpadded rows.
#define SWZ128B(r, ch) ((((ch) ^ ((r) & 7)) << 4))

__device__ __forceinline__ int inc3(int x) { return (x == 2) ? 0 : x + 1; }

// ===========================================================================
// Prep: convert 3 inputs to fp16 single; transpose 4 weights to fp16 single
// ===========================================================================
__global__ __launch_bounds__(256)
void cvt3(const float4* __restrict__ x0, const float4* __restrict__ x1,
          const float4* __restrict__ x2,
          __half* __restrict__ h0, __half* __restrict__ h1,
          __half* __restrict__ h2, int n4) {
    int i = blockIdx.x * blockDim.x + threadIdx.x;
    if (i >= n4) return;
    const int z = blockIdx.y;
    const float4* x = (z == 0) ? x0 : (z == 1) ? x1 : x2;
    __half* hi = (z == 0) ? h0 : (z == 1) ? h1 : h2;
    float4 v = x[i];
    __half2 a = __floats2half2_rn(v.x, v.y);
    __half2 b = __floats2half2_rn(v.z, v.w);
    ((__half2*)hi)[i * 2 + 0] = a;
    ((__half2*)hi)[i * 2 + 1] = b;
}

__global__ __launch_bounds__(256)
void wtsplit4(const float* __restrict__ w0, const float* __restrict__ w1,
              const float* __restrict__ w2, const float* __restrict__ w3,
              __half* __restrict__ hi4) {
    __shared__ float t[32][33];
    const int z = blockIdx.z;
    const float* W = (z == 0) ? w0 : (z == 1) ? w1 : (z == 2) ? w2 : w3;
    __half* hi = hi4 + (size_t)z * DM_ * DM_;
    const int n0 = blockIdx.x * 32;
    const int k0 = blockIdx.y * 32;
    const int tx = threadIdx.x, ty = threadIdx.y;
#pragma unroll
    for (int i = 0; i < 4; ++i)
        t[ty + i * 8][tx] = W[(size_t)(k0 + ty + i * 8) * DM_ + n0 + tx];
    __syncthreads();
#pragma unroll
    for (int i = 0; i < 4; ++i) {
        float v = t[tx][ty + i * 8];
        hi[(size_t)(n0 + ty + i * 8) * DM_ + k0 + tx] = __float2half_rn(v);
    }
}

// ===========================================================================
// HMMA GEMM (fp16 single, 1 pass, BK=64):  C = A @ Wt^T + bias
// 3-stage cp.async ring, 1 sync per 64-K tile, SWZ128B rows. 2 CTAs/SM.
// Epilogue modes: 0 = fp32, 2 = fp16 single.
// ===========================================================================
#define BM 128
#define BN 128
#define BK 64
#define NKT (DM_ / BK)            // 16
#define GT_TILE 16384             // 128 rows * 128B
#define GT_STAGE (2 * GT_TILE)    // 32768: A, W
#define GEMM_SMEM (3 * GT_STAGE)  // 98304

__device__ __forceinline__ void load_ktile(uint32_t sb, int kt, int stage,
                                           const __half* A, const __half* W,
                                           int rowBase, int colBase) {
    const int tid = threadIdx.x;
    const uint32_t base = sb + stage * GT_STAGE;
    const __half* srcs[2] = {
        A + (size_t)rowBase * DM_ + kt * BK,
        W + (size_t)colBase * DM_ + kt * BK};
#pragma unroll
    for (int t = 0; t < 2; ++t) {
#pragma unroll
        for (int i = 0; i < 4; ++i) {
            int c = tid + i * 256;          // 0..1023: r 0..127, ch 0..7
            int r = c >> 3, ch = c & 7;
            cp16(base + t * GT_TILE + r * 128 + SWZ128B(r, ch),
                 srcs[t] + (size_t)r * DM_ + ch * 8);
        }
    }
}

__device__ __forceinline__ void gemm_body(
    const __half* __restrict__ A, const __half* __restrict__ W,
    const float* __restrict__ bias, float* __restrict__ C,
    __half* __restrict__ Ch, int mode, char* smem) {
    const uint32_t sb = smem_u32(smem);
    const int tid  = threadIdx.x;
    const int wid  = tid >> 5;
    const int lane = tid & 31;
    const int rowBase = blockIdx.y * BM;
    const int colBase = blockIdx.x * BN;

    const int mbase = (wid >> 1) * 32;
    const int nbase = (wid & 1) * 64;

    float acc[2][8][4];
#pragma unroll
    for (int i = 0; i < 2; ++i)
#pragma unroll
        for (int j = 0; j < 8; ++j)
#pragma unroll
            for (int q = 0; q < 4; ++q) acc[i][j][q] = 0.f;

    load_ktile(sb, 0, 0, A, W, rowBase, colBase);
    CP_COMMIT();
    load_ktile(sb, 1, 1, A, W, rowBase, colBase);
    CP_COMMIT();

    const int a_row = lane & 15;
    const int a_kb  = lane >> 4;
    const int b_row = ((lane >> 4) & 1) * 8 + (lane & 7);
    const int b_kb  = (lane >> 3) & 1;

    int cur = 0, pf = 2;
    for (int kt = 0; kt < NKT; ++kt) {
        if (kt + 1 < NKT) { CP_WAIT(1); } else { CP_WAIT(0); }
        __syncthreads();
        if (kt + 2 < NKT) {
            load_ktile(sb, kt + 2, pf, A, W, rowBase, colBase);
            CP_COMMIT();
        }

        const uint32_t st = sb + cur * GT_STAGE;
#pragma unroll
        for (int s = 0; s < 4; ++s) {       // four k16 steps per 64-K tile
            uint32_t ah[2][4];
#pragma unroll
            for (int i = 0; i < 2; ++i) {
                int row = mbase + i * 16 + a_row;
                uint32_t off = row * 128 + SWZ128B(row, s * 2 + a_kb);
                ldmx4(ah[i], st + 0 * GT_TILE + off);
            }
#pragma unroll
            for (int jp = 0; jp < 4; ++jp) {
                int row = nbase + jp * 16 + b_row;
                uint32_t off = row * 128 + SWZ128B(row, s * 2 + b_kb);
                uint32_t tw[4];
                ldmx4(tw, st + 1 * GT_TILE + off);
                uint32_t b0[2] = {tw[0], tw[1]}, b1[2] = {tw[2], tw[3]};
#pragma unroll
                for (int i = 0; i < 2; ++i) {
                    mma_f16(acc[i][jp * 2],     ah[i], b0);
                    mma_f16(acc[i][jp * 2 + 1], ah[i], b1);
                }
            }
        }
        cur = inc3(cur);
        pf  = inc3(pf);
    }

#pragma unroll
    for (int i = 0; i < 2; ++i) {
        const int r0 = rowBase + mbase + i * 16 + (lane >> 2);
#pragma unroll
        for (int j = 0; j < 8; ++j) {
            const int col = colBase + nbase + j * 8 + (lane & 3) * 2;
            const float b0 = bias[col], b1 = bias[col + 1];
            float f0 = acc[i][j][0] + b0, f1 = acc[i][j][1] + b1;
            float f2 = acc[i][j][2] + b0, f3 = acc[i][j][3] + b1;
            if (mode == 0) {
                *(float2*)(C + (size_t)r0 * DM_ + col)       = make_float2(f0, f1);
                *(float2*)(C + (size_t)(r0 + 8) * DM_ + col) = make_float2(f2, f3);
            } else {
                __half2 hh01 = __floats2half2_rn(f0, f1);
                __half2 hh23 = __floats2half2_rn(f2, f3);
                *(uint32_t*)(Ch + (size_t)r0 * DM_ + col)       = *(uint32_t*)&hh01;
                *(uint32_t*)(Ch + (size_t)(r0 + 8) * DM_ + col) = *(uint32_t*)&hh23;
            }
        }
    }
}

__global__ __launch_bounds__(256, 2)
void gemm_qkv(const __half* __restrict__ A0, const __half* __restrict__ A1,
              const __half* __restrict__ A2, const __half* __restrict__ W4,
              const float* __restrict__ b0, const float* __restrict__ b1,
              const float* __restrict__ b2,
              __half* __restrict__ C0, __half* __restrict__ C1,
              __half* __restrict__ C2) {
    extern __shared__ char smem[];
    const int z = blockIdx.z;
    const __half* A = (z == 0) ? A0 : (z == 1) ? A1 : A2;
    const float* bias = (z == 0) ? b0 : (z == 1) ? b1 : b2;
    __half* Ch = (z == 0) ? C0 : (z == 1) ? C1 : C2;
    gemm_body(A, W4 + (size_t)z * DM_ * DM_, bias, nullptr, Ch, 2, smem);
}

__global__ __launch_bounds__(256, 2)
void gemm_o(const __half* __restrict__ A, const __half* __restrict__ W,
            const float* __restrict__ bias, float* __restrict__ C) {
    extern __shared__ char smem[];
    gemm_body(A, W, bias, C, nullptr, 0, smem);
}

// ===========================================================================
// Flash attention v10: single-pass fp16; row sums via ones-column MMA
// (l accumulated on the tensor pipe, rescaled like o each tile).
// ===========================================================================
#define KTT  8192                  // 64 rows * 128B
#define FA_SMEM (4 * KTT)          // 32768

#define C2F 0.1803368801111204f    // log2(e)/8 (Dh=64 scale folded into exp2)
#define NT_ (S_ / 64)              // 32 kv tiles
#define ONES2 0x3C003C00u          // fp16 {1.0, 1.0}

__device__ __forceinline__ void fa_load_one(uint32_t dst, const __half* Src,
                                            size_t rowStart, int k0, int colOff) {
    const int tid = threadIdx.x;
    const __half* s = Src + (rowStart + k0) * DM_ + colOff;
#pragma unroll
    for (int i = 0; i < 2; ++i) {
        int c = tid + i * 256;           // 0..511
        int r = c >> 3, ch = c & 7;
        cp16(dst + r * 128 + SWZ128B(r, ch), s + (size_t)r * DM_ + ch * 8);
    }
}

__device__ __forceinline__ void qk_tile(
    uint32_t ksBase, const uint32_t (&qh)[4][4],
    int b_row, int b_kb, float (&s)[8][4]) {
#pragma unroll
    for (int j = 0; j < 8; ++j)
#pragma unroll
        for (int q = 0; q < 4; ++q) s[j][q] = 0.f;
#pragma unroll
    for (int ks = 0; ks < 4; ++ks) {
#pragma unroll
        for (int ntp = 0; ntp < 4; ++ntp) {
            const int krow = ntp * 16 + b_row;
            const uint32_t koff = krow * 128 + SWZ128B(krow, ks * 2 + b_kb);
            uint32_t th[4];
            ldmx4(th, ksBase + koff);
            uint32_t k0h[2] = {th[0], th[1]}, k1h[2] = {th[2], th[3]};
            mma_f16(s[2 * ntp],     qh[ks], k0h);
            mma_f16(s[2 * ntp + 1], qh[ks], k1h);
        }
    }
}

// online softmax: max-reduce, exp, pack P; rescale o and accl. (No scalar sums
// — row sums come from the ones-column MMA in pv_accum.)
__device__ __forceinline__ void softmax_pack(
    float (&s)[8][4], float (&o)[8][4], float (&accl)[4],
    float& m0, float& m1,
    uint32_t (&Pa)[8], uint32_t (&Pb)[8]) {
    float rmax0 = -1e30f, rmax1 = -1e30f;
#pragma unroll
    for (int j = 0; j < 8; ++j) {
        rmax0 = fmaxf(rmax0, fmaxf(s[j][0], s[j][1]));
        rmax1 = fmaxf(rmax1, fmaxf(s[j][2], s[j][3]));
    }
    rmax0 = fmaxf(rmax0, __shfl_xor_sync(0xffffffffu, rmax0, 1));
    rmax0 = fmaxf(rmax0, __shfl_xor_sync(0xffffffffu, rmax0, 2));
    rmax1 = fmaxf(rmax1, __shfl_xor_sync(0xffffffffu, rmax1, 1));
    rmax1 = fmaxf(rmax1, __shfl_xor_sync(0xffffffffu, rmax1, 2));
    const float m0n = fmaxf(m0, rmax0);
    const float m1n = fmaxf(m1, rmax1);
    const float c0 = ex2f((m0 - m0n) * C2F);
    const float c1 = ex2f((m1 - m1n) * C2F);
    m0 = m0n; m1 = m1n;
    const float mc0 = m0 * C2F, mc1 = m1 * C2F;
#pragma unroll
    for (int j = 0; j < 8; ++j) {
        s[j][0] = ex2f(fmaf(s[j][0], C2F, -mc0));
        s[j][1] = ex2f(fmaf(s[j][1], C2F, -mc0));
        s[j][2] = ex2f(fmaf(s[j][2], C2F, -mc1));
        s[j][3] = ex2f(fmaf(s[j][3], C2F, -mc1));
    }
#pragma unroll
    for (int j = 0; j < 8; ++j) {
        Pa[j] = pack_h2(s[j][0], s[j][1]);
        Pb[j] = pack_h2(s[j][2], s[j][3]);
    }
#pragma unroll
    for (int j = 0; j < 8; ++j) {
        o[j][0] *= c0; o[j][1] *= c0;
        o[j][2] *= c1; o[j][3] *= c1;
    }
    accl[0] *= c0; accl[1] *= c0;
    accl[2] *= c1; accl[3] *= c1;
}

// O += P @ V; accl += P @ ones (row sums on the tensor pipe).
__device__ __forceinline__ void pv_accum(
    uint32_t vsBase, int v_k, int v_db,
    const uint32_t (&Pa)[8], const uint32_t (&Pb)[8],
    float (&o)[8][4], float (&accl)[4]) {
    const uint32_t onesb[2] = {ONES2, ONES2};
#pragma unroll
    for (int ks = 0; ks < 4; ++ks) {
        uint32_t ap[4] = {Pa[2 * ks], Pb[2 * ks],
                          Pa[2 * ks + 1], Pb[2 * ks + 1]};
        mma_f16(accl, ap, onesb);        // row sums of this k16 slice
        const int vrow = 16 * ks + v_k;
#pragma unroll
        for (int dt = 0; dt < 4; ++dt) {
            const uint32_t off = vrow * 128 + SWZ128B(vrow, dt * 2 + v_db);
            uint32_t vh[4];
            ldmx4t(vh, vsBase + off);
            uint32_t b0[2] = {vh[0], vh[1]}, b1[2] = {vh[2], vh[3]};
            mma_f16(o[2 * dt],     ap, b0);
            mma_f16(o[2 * dt + 1], ap, b1);
        }
    }
}

__global__ __launch_bounds__(256, 2)
void flash_mma10(const __half* __restrict__ Qh,
                 const __half* __restrict__ Kh,
                 const __half* __restrict__ Vh,
                 __half* __restrict__ AOh) {
    extern __shared__ char smem[];
    const uint32_t sb = smem_u32(smem);
    const int tid = threadIdx.x, wid = tid >> 5, lane = tid & 31;
    const int bh = blockIdx.y, b = bh >> 4, h = bh & 15;
    const int q0 = blockIdx.x * 128;
    const size_t rowStart = (size_t)b * S_;
    const int colOff = h * DH_;

    const uint32_t Ks0 = sb;
    const uint32_t Ks1 = sb + KTT;
    const uint32_t Vs0 = sb + 2 * KTT;
    const uint32_t Vs1 = sb + 3 * KTT;

    // ---- prologue: Q -> [Ks0..Ks1] (g1); V0 -> Vs0 (g2) ----
    {
        const __half* qsrc = Qh + (rowStart + q0) * DM_ + colOff;
#pragma unroll
        for (int i = 0; i < 4; ++i) {
            int c = tid + i * 256;           // 0..1023: r 0..127, ch 0..7
            int r = c >> 3, ch = c & 7;
            cp16(sb + r * 128 + SWZ128B(r, ch), qsrc + (size_t)r * DM_ + ch * 8);
        }
    }
    CP_COMMIT();                             // g1 (Q)
    fa_load_one(Vs0, Vh, rowStart, 0, colOff);
    CP_COMMIT();                             // g2 (V0)
    CP_WAIT(1);                              // g1 done
    __syncthreads();

    const int a_row = lane & 15;
    const int a_kb  = lane >> 4;
    const int b_row = ((lane >> 4) & 1) * 8 + (lane & 7);
    const int b_kb  = (lane >> 3) & 1;
    const int v_k   = (lane & 7) + ((lane >> 3) & 1) * 8;
    const int v_db  = (lane >> 4) & 1;
    const int qrow  = 16 * wid + a_row;

    uint32_t qh[4][4];
#pragma unroll
    for (int ks = 0; ks < 4; ++ks)
        ldmx4(qh[ks], sb + qrow * 128 + SWZ128B(qrow, ks * 2 + a_kb));
    __syncthreads();                         // all warps done with Q staging

    fa_load_one(Ks0, Kh, rowStart, 0, colOff);
    fa_load_one(Ks1, Kh, rowStart, 64, colOff);
    CP_COMMIT();                             // g3
    CP_WAIT(0);                              // V0, K0, K1 landed
    __syncthreads();

    float m0 = -1e30f, m1 = -1e30f;
    float accl[4] = {0.f, 0.f, 0.f, 0.f};
    float o[8][4];
#pragma unroll
    for (int j = 0; j < 8; ++j)
#pragma unroll
        for (int q = 0; q < 4; ++q) o[j][q] = 0.f;

    float s[8][4];
    qk_tile(Ks0, qh, b_row, b_kb, s);

    for (int jt = 0; jt < NT_ - 1; ++jt) {
        CP_WAIT(0);
        __syncthreads();                 // K(jt+1), V(jt) resident
        const int kc = (jt + 2 < NT_) ? (jt + 2) : (NT_ - 1);
        fa_load_one((jt & 1) ? Ks1 : Ks0, Kh, rowStart, kc * 64, colOff);
        fa_load_one(((jt + 1) & 1) ? Vs1 : Vs0, Vh, rowStart,
                    (jt + 1) * 64, colOff);
        CP_COMMIT();

        uint32_t Pa[8], Pb[8];
        softmax_pack(s, o, accl, m0, m1, Pa, Pb);
        qk_tile(((jt + 1) & 1) ? Ks1 : Ks0, qh, b_row, b_kb, s);
        pv_accum((jt & 1) ? Vs1 : Vs0, v_k, v_db, Pa, Pb, o, accl);
    }

    CP_WAIT(0);
    __syncthreads();
    {
        uint32_t Pa[8], Pb[8];
        softmax_pack(s, o, accl, m0, m1, Pa, Pb);
        pv_accum(((NT_ - 1) & 1) ? Vs1 : Vs0, v_k, v_db, Pa, Pb, o, accl);
    }

    // ---- normalize, write fp16 single ----
    const float i0 = 1.f / accl[0], i1 = 1.f / accl[2];
    const size_t row0 = rowStart + q0 + 16 * wid + (lane >> 2);
    const size_t row1 = row0 + 8;
#pragma unroll
    for (int j = 0; j < 8; ++j) {
        const int col = colOff + j * 8 + (lane & 3) * 2;
        __half2 hh01 = __floats2half2_rn(o[j][0] * i0, o[j][1] * i0);
        __half2 hh23 = __floats2half2_rn(o[j][2] * i1, o[j][3] * i1);
        *(uint32_t*)(AOh + row0 * DM_ + col) = *(uint32_t*)&hh01;
        *(uint32_t*)(AOh + row1 * DM_ + col) = *(uint32_t*)&hh23;
    }
}

// ===========================================================================
// Launch
// ===========================================================================
extern "C" void kernel_launch(void* const* d_in, const int* in_sizes, int n_in,
                              void* d_out, int out_size)
{
    const float* query = (const float*)d_in[0];
    const float* key   = (const float*)d_in[1];
    const float* value = (const float*)d_in[2];
    const float* Wq    = (const float*)d_in[3];
    const float* bq    = (const float*)d_in[4];
    const float* Wk    = (const float*)d_in[5];
    const float* bk    = (const float*)d_in[6];
    const float* Wv    = (const float*)d_in[7];
    const float* bv    = (const float*)d_in[8];
    const float* Wo    = (const float*)d_in[9];
    const float* bo    = (const float*)d_in[10];
    float* out = (float*)d_out;

    __half *pI4, *pW4, *pQh, *pKh, *pVh, *pAOh;
    cudaGetSymbolAddress((void**)&pI4,  g_I4);
    cudaGetSymbolAddress((void**)&pW4,  g_W4);
    cudaGetSymbolAddress((void**)&pQh,  g_Qh);
    cudaGetSymbolAddress((void**)&pKh,  g_Kh);
    cudaGetSymbolAddress((void**)&pVh,  g_Vh);
    cudaGetSymbolAddress((void**)&pAOh, g_AOh);

    const size_t NTOK = (size_t)ROWS_ * DM_;

    static bool attrs_set = false;
    if (!attrs_set) {
        cudaFuncSetAttribute(gemm_qkv, cudaFuncAttributeMaxDynamicSharedMemorySize, GEMM_SMEM);
        cudaFuncSetAttribute(gemm_o,   cudaFuncAttributeMaxDynamicSharedMemorySize, GEMM_SMEM);
        cudaFuncSetAttribute(flash_mma10, cudaFuncAttributeMaxDynamicSharedMemorySize, FA_SMEM);
        attrs_set = true;
    }

    const int n4 = ROWS_ * DM_ / 4;

    // 1) convert all three inputs to fp16 single
    cvt3<<<dim3((n4 + 255) / 256, 3), 256>>>(
        (const float4*)query, (const float4*)key, (const float4*)value,
        pI4 + 0 * NTOK, pI4 + 1 * NTOK, pI4 + 2 * NTOK, n4);

    // 2) transpose all four weights to fp16 single
    wtsplit4<<<dim3(32, 32, 4), dim3(32, 8)>>>(Wq, Wk, Wv, Wo, pW4);

    // 3) Q,K,V projections (1-pass fp16, BK=64)
    gemm_qkv<<<dim3(DM_ / BN, ROWS_ / BM, 3), 256, GEMM_SMEM>>>(
        pI4 + 0 * NTOK, pI4 + 1 * NTOK, pI4 + 2 * NTOK,
        pW4, bq, bk, bv, pQh, pKh, pVh);

    // 4) attention (1-pass fp16; row sums via ones-MMA)
    flash_mma10<<<dim3(S_ / 128, B_ * NH_), 256, FA_SMEM>>>(
        pQh, pKh, pVh, pAOh);

    // 5) output projection (1-pass fp16, fp32 result)
    gemm_o<<<dim3(DM_ / BN, ROWS_ / BM), 256, GEMM_SMEM>>>(
        pAOh, pW4 + 3 * (size_t)DM_ * DM_, bo, out);
}

// round 16
// speedup vs baseline: 2.7780x; 1.0260x over previous
#include <cuda_runtime.h>
#include <cuda_bf16.h>
#include <cuda_fp16.h>
#include <math.h>
#include <cstdint>

// ---------------------------------------------------------------------------
// Problem constants
// ---------------------------------------------------------------------------
#define B_    4
#define S_    2048
#define DM_   1024
#define NH_   16
#define DH_   64
#define ROWS_ (B_ * S_)          // 8192

// ---------------------------------------------------------------------------
// Scratch (device globals: allocation-free per harness rules)
// ---------------------------------------------------------------------------
__device__ __half g_I4[3][ROWS_ * DM_];   // inputs (q,k,v) fp16 single
__device__ __half g_W4[4][DM_ * DM_];     // W^T fp16 single (q,k,v,o)
__device__ __half g_Qh[ROWS_ * DM_];      // fp16 single
__device__ __half g_Kh[ROWS_ * DM_];      // fp16 single
__device__ __half g_Vh[ROWS_ * DM_];      // fp16 single
__device__ __half g_AOh[ROWS_ * DM_];     // attention out fp16 single

// ===========================================================================
// Generic-PTX helpers (legal on plain sm_103 target: sm_80+ instructions)
// ===========================================================================
__device__ __forceinline__ uint32_t smem_u32(const void* p) {
    uint32_t a;
    asm("{ .reg .u64 t; cvta.to.shared.u64 t, %1; cvt.u32.u64 %0, t; }"
        : "=r"(a) : "l"(p));
    return a;
}

__device__ __forceinline__ void cp16(uint32_t s, const void* g) {
    asm volatile("cp.async.cg.shared.global [%0], [%1], 16;" :: "r"(s), "l"(g));
}
#define CP_COMMIT() asm volatile("cp.async.commit_group;" ::: "memory")
#define CP_WAIT(n)  asm volatile("cp.async.wait_group %0;" :: "n"(n) : "memory")

__device__ __forceinline__ void ldmx4(uint32_t* r, uint32_t addr) {
    asm volatile("ldmatrix.sync.aligned.m8n8.x4.shared.b16 {%0,%1,%2,%3}, [%4];"
                 : "=r"(r[0]), "=r"(r[1]), "=r"(r[2]), "=r"(r[3]) : "r"(addr));
}

__device__ __forceinline__ void ldmx4t(uint32_t* r, uint32_t addr) {
    asm volatile("ldmatrix.sync.aligned.m8n8.x4.trans.shared.b16 {%0,%1,%2,%3}, [%4];"
                 : "=r"(r[0]), "=r"(r[1]), "=r"(r[2]), "=r"(r[3]) : "r"(addr));
}

__device__ __forceinline__ void mma_f16(float* d, const uint32_t* a,
                                        const uint32_t* b) {
    asm volatile(
        "mma.sync.aligned.m16n8k16.row.col.f32.f16.f16.f32 "
        "{%0,%1,%2,%3}, {%4,%5,%6,%7}, {%8,%9}, {%0,%1,%2,%3};"
        : "+f"(d[0]), "+f"(d[1]), "+f"(d[2]), "+f"(d[3])
        : "r"(a[0]), "r"(a[1]), "r"(a[2]), "r"(a[3]), "r"(b[0]), "r"(b[1]));
}

__device__ __forceinline__ float ex2f(float x) {
    float y;
    asm("ex2.approx.ftz.f32 %0, %1;" : "=f"(y) : "f"(x));
    return y;
}

// packed exp2 on fp16 pairs: one MUFU op for two P values.
__device__ __forceinline__ uint32_t h2exp2_pack(float x0, float x1) {
    __half2 xh = __floats2half2_rn(x0, x1);
    uint32_t xb = *reinterpret_cast<uint32_t*>(&xh);
    uint32_t r;
    asm("ex2.approx.f16x2 %0, %1;" : "=r"(r) : "r"(xb));
    return r;
}

// XOR swizzles: conflict-free ldmatrix on unpadded rows.
#define SWZ128B(r, ch) ((((ch) ^ ((r) & 7)) << 4))

__device__ __forceinline__ int inc3(int x) { return (x == 2) ? 0 : x + 1; }

// ===========================================================================
// Prep: convert 3 inputs to fp16 single; transpose 4 weights to fp16 single
// ===========================================================================
__global__ __launch_bounds__(256)
void cvt3(const float4* __restrict__ x0, const float4* __restrict__ x1,
          const float4* __restrict__ x2,
          __half* __restrict__ h0, __half* __restrict__ h1,
          __half* __restrict__ h2, int n4) {
    int i = blockIdx.x * blockDim.x + threadIdx.x;
    if (i >= n4) return;
    const int z = blockIdx.y;
    const float4* x = (z == 0) ? x0 : (z == 1) ? x1 : x2;
    __half* hi = (z == 0) ? h0 : (z == 1) ? h1 : h2;
    float4 v = x[i];
    __half2 a = __floats2half2_rn(v.x, v.y);
    __half2 b = __floats2half2_rn(v.z, v.w);
    ((__half2*)hi)[i * 2 + 0] = a;
    ((__half2*)hi)[i * 2 + 1] = b;
}

__global__ __launch_bounds__(256)
void wtsplit4(const float* __restrict__ w0, const float* __restrict__ w1,
              const float* __restrict__ w2, const float* __restrict__ w3,
              __half* __restrict__ hi4) {
    __shared__ float t[32][33];
    const int z = blockIdx.z;
    const float* W = (z == 0) ? w0 : (z == 1) ? w1 : (z == 2) ? w2 : w3;
    __half* hi = hi4 + (size_t)z * DM_ * DM_;
    const int n0 = blockIdx.x * 32;
    const int k0 = blockIdx.y * 32;
    const int tx = threadIdx.x, ty = threadIdx.y;
#pragma unroll
    for (int i = 0; i < 4; ++i)
        t[ty + i * 8][tx] = W[(size_t)(k0 + ty + i * 8) * DM_ + n0 + tx];
    __syncthreads();
#pragma unroll
    for (int i = 0; i < 4; ++i) {
        float v = t[tx][ty + i * 8];
        hi[(size_t)(n0 + ty + i * 8) * DM_ + k0 + tx] = __float2half_rn(v);
    }
}

// ===========================================================================
// HMMA GEMM (fp16 single, 1 pass, BK=64):  C = A @ Wt^T + bias
// 3-stage cp.async ring, 1 sync per 64-K tile, SWZ128B rows. 2 CTAs/SM.
// Epilogue modes: 0 = fp32, 2 = fp16 single.
// ===========================================================================
#define BM 128
#define BN 128
#define BK 64
#define NKT (DM_ / BK)            // 16
#define GT_TILE 16384             // 128 rows * 128B
#define GT_STAGE (2 * GT_TILE)    // 32768: A, W
#define GEMM_SMEM (3 * GT_STAGE)  // 98304

__device__ __forceinline__ void load_ktile(uint32_t sb, int kt, int stage,
                                           const __half* A, const __half* W,
                                           int rowBase, int colBase) {
    const int tid = threadIdx.x;
    const uint32_t base = sb + stage * GT_STAGE;
    const __half* srcs[2] = {
        A + (size_t)rowBase * DM_ + kt * BK,
        W + (size_t)colBase * DM_ + kt * BK};
#pragma unroll
    for (int t = 0; t < 2; ++t) {
#pragma unroll
        for (int i = 0; i < 4; ++i) {
            int c = tid + i * 256;          // 0..1023: r 0..127, ch 0..7
            int r = c >> 3, ch = c & 7;
            cp16(base + t * GT_TILE + r * 128 + SWZ128B(r, ch),
                 srcs[t] + (size_t)r * DM_ + ch * 8);
        }
    }
}

__device__ __forceinline__ void gemm_body(
    const __half* __restrict__ A, const __half* __restrict__ W,
    const float* __restrict__ bias, float* __restrict__ C,
    __half* __restrict__ Ch, int mode, char* smem) {
    const uint32_t sb = smem_u32(smem);
    const int tid  = threadIdx.x;
    const int wid  = tid >> 5;
    const int lane = tid & 31;
    const int rowBase = blockIdx.y * BM;
    const int colBase = blockIdx.x * BN;

    const int mbase = (wid >> 1) * 32;
    const int nbase = (wid & 1) * 64;

    float acc[2][8][4];
#pragma unroll
    for (int i = 0; i < 2; ++i)
#pragma unroll
        for (int j = 0; j < 8; ++j)
#pragma unroll
            for (int q = 0; q < 4; ++q) acc[i][j][q] = 0.f;

    load_ktile(sb, 0, 0, A, W, rowBase, colBase);
    CP_COMMIT();
    load_ktile(sb, 1, 1, A, W, rowBase, colBase);
    CP_COMMIT();

    const int a_row = lane & 15;
    const int a_kb  = lane >> 4;
    const int b_row = ((lane >> 4) & 1) * 8 + (lane & 7);
    const int b_kb  = (lane >> 3) & 1;

    int cur = 0, pf = 2;
    for (int kt = 0; kt < NKT; ++kt) {
        if (kt + 1 < NKT) { CP_WAIT(1); } else { CP_WAIT(0); }
        __syncthreads();
        if (kt + 2 < NKT) {
            load_ktile(sb, kt + 2, pf, A, W, rowBase, colBase);
            CP_COMMIT();
        }

        const uint32_t st = sb + cur * GT_STAGE;
#pragma unroll
        for (int s = 0; s < 4; ++s) {       // four k16 steps per 64-K tile
            uint32_t ah[2][4];
#pragma unroll
            for (int i = 0; i < 2; ++i) {
                int row = mbase + i * 16 + a_row;
                uint32_t off = row * 128 + SWZ128B(row, s * 2 + a_kb);
                ldmx4(ah[i], st + 0 * GT_TILE + off);
            }
#pragma unroll
            for (int jp = 0; jp < 4; ++jp) {
                int row = nbase + jp * 16 + b_row;
                uint32_t off = row * 128 + SWZ128B(row, s * 2 + b_kb);
                uint32_t tw[4];
                ldmx4(tw, st + 1 * GT_TILE + off);
                uint32_t b0[2] = {tw[0], tw[1]}, b1[2] = {tw[2], tw[3]};
#pragma unroll
                for (int i = 0; i < 2; ++i) {
                    mma_f16(acc[i][jp * 2],     ah[i], b0);
                    mma_f16(acc[i][jp * 2 + 1], ah[i], b1);
                }
            }
        }
        cur = inc3(cur);
        pf  = inc3(pf);
    }

#pragma unroll
    for (int i = 0; i < 2; ++i) {
        const int r0 = rowBase + mbase + i * 16 + (lane >> 2);
#pragma unroll
        for (int j = 0; j < 8; ++j) {
            const int col = colBase + nbase + j * 8 + (lane & 3) * 2;
            const float b0 = bias[col], b1 = bias[col + 1];
            float f0 = acc[i][j][0] + b0, f1 = acc[i][j][1] + b1;
            float f2 = acc[i][j][2] + b0, f3 = acc[i][j][3] + b1;
            if (mode == 0) {
                *(float2*)(C + (size_t)r0 * DM_ + col)       = make_float2(f0, f1);
                *(float2*)(C + (size_t)(r0 + 8) * DM_ + col) = make_float2(f2, f3);
            } else {
                __half2 hh01 = __floats2half2_rn(f0, f1);
                __half2 hh23 = __floats2half2_rn(f2, f3);
                *(uint32_t*)(Ch + (size_t)r0 * DM_ + col)       = *(uint32_t*)&hh01;
                *(uint32_t*)(Ch + (size_t)(r0 + 8) * DM_ + col) = *(uint32_t*)&hh23;
            }
        }
    }
}

__global__ __launch_bounds__(256, 2)
void gemm_qkv(const __half* __restrict__ A0, const __half* __restrict__ A1,
              const __half* __restrict__ A2, const __half* __restrict__ W4,
              const float* __restrict__ b0, const float* __restrict__ b1,
              const float* __restrict__ b2,
              __half* __restrict__ C0, __half* __restrict__ C1,
              __half* __restrict__ C2) {
    extern __shared__ char smem[];
    const int z = blockIdx.z;
    const __half* A = (z == 0) ? A0 : (z == 1) ? A1 : A2;
    const float* bias = (z == 0) ? b0 : (z == 1) ? b1 : b2;
    __half* Ch = (z == 0) ? C0 : (z == 1) ? C1 : C2;
    gemm_body(A, W4 + (size_t)z * DM_ * DM_, bias, nullptr, Ch, 2, smem);
}

__global__ __launch_bounds__(256, 2)
void gemm_o(const __half* __restrict__ A, const __half* __restrict__ W,
            const float* __restrict__ bias, float* __restrict__ C) {
    extern __shared__ char smem[];
    gemm_body(A, W, bias, C, nullptr, 0, smem);
}

// ===========================================================================
// Flash attention v11: single-pass fp16; row sums via ones-column MMA;
// P exponentials via packed ex2.approx.f16x2 (one MUFU per 2 values).
// ===========================================================================
#define KTT  8192                  // 64 rows * 128B
#define FA_SMEM (4 * KTT)          // 32768

#define C2F 0.1803368801111204f    // log2(e)/8 (Dh=64 scale folded into exp2)
#define NT_ (S_ / 64)              // 32 kv tiles
#define ONES2 0x3C003C00u          // fp16 {1.0, 1.0}

__device__ __forceinline__ void fa_load_one(uint32_t dst, const __half* Src,
                                            size_t rowStart, int k0, int colOff) {
    const int tid = threadIdx.x;
    const __half* s = Src + (rowStart + k0) * DM_ + colOff;
#pragma unroll
    for (int i = 0; i < 2; ++i) {
        int c = tid + i * 256;           // 0..511
        int r = c >> 3, ch = c & 7;
        cp16(dst + r * 128 + SWZ128B(r, ch), s + (size_t)r * DM_ + ch * 8);
    }
}

__device__ __forceinline__ void qk_tile(
    uint32_t ksBase, const uint32_t (&qh)[4][4],
    int b_row, int b_kb, float (&s)[8][4]) {
#pragma unroll
    for (int j = 0; j < 8; ++j)
#pragma unroll
        for (int q = 0; q < 4; ++q) s[j][q] = 0.f;
#pragma unroll
    for (int ks = 0; ks < 4; ++ks) {
#pragma unroll
        for (int ntp = 0; ntp < 4; ++ntp) {
            const int krow = ntp * 16 + b_row;
            const uint32_t koff = krow * 128 + SWZ128B(krow, ks * 2 + b_kb);
            uint32_t th[4];
            ldmx4(th, ksBase + koff);
            uint32_t k0h[2] = {th[0], th[1]}, k1h[2] = {th[2], th[3]};
            mma_f16(s[2 * ntp],     qh[ks], k0h);
            mma_f16(s[2 * ntp + 1], qh[ks], k1h);
        }
    }
}

// online softmax: max-reduce, packed fp16 exp2 -> P fragments directly;
// rescale o and accl. Row sums come from the ones-column MMA in pv_accum.
__device__ __forceinline__ void softmax_pack(
    float (&s)[8][4], float (&o)[8][4], float (&accl)[4],
    float& m0, float& m1,
    uint32_t (&Pa)[8], uint32_t (&Pb)[8]) {
    float rmax0 = -1e30f, rmax1 = -1e30f;
#pragma unroll
    for (int j = 0; j < 8; ++j) {
        rmax0 = fmaxf(rmax0, fmaxf(s[j][0], s[j][1]));
        rmax1 = fmaxf(rmax1, fmaxf(s[j][2], s[j][3]));
    }
    rmax0 = fmaxf(rmax0, __shfl_xor_sync(0xffffffffu, rmax0, 1));
    rmax0 = fmaxf(rmax0, __shfl_xor_sync(0xffffffffu, rmax0, 2));
    rmax1 = fmaxf(rmax1, __shfl_xor_sync(0xffffffffu, rmax1, 1));
    rmax1 = fmaxf(rmax1, __shfl_xor_sync(0xffffffffu, rmax1, 2));
    const float m0n = fmaxf(m0, rmax0);
    const float m1n = fmaxf(m1, rmax1);
    const float c0 = ex2f((m0 - m0n) * C2F);
    const float c1 = ex2f((m1 - m1n) * C2F);
    m0 = m0n; m1 = m1n;
    const float mc0 = m0 * C2F, mc1 = m1 * C2F;
#pragma unroll
    for (int j = 0; j < 8; ++j) {
        // x computed in fp32 (score quantization matters), exp2 on packed fp16
        Pa[j] = h2exp2_pack(fmaf(s[j][0], C2F, -mc0),
                            fmaf(s[j][1], C2F, -mc0));
        Pb[j] = h2exp2_pack(fmaf(s[j][2], C2F, -mc1),
                            fmaf(s[j][3], C2F, -mc1));
    }
#pragma unroll
    for (int j = 0; j < 8; ++j) {
        o[j][0] *= c0; o[j][1] *= c0;
        o[j][2] *= c1; o[j][3] *= c1;
    }
    accl[0] *= c0; accl[1] *= c0;
    accl[2] *= c1; accl[3] *= c1;
}

// O += P @ V; accl += P @ ones (row sums on the tensor pipe).
__device__ __forceinline__ void pv_accum(
    uint32_t vsBase, int v_k, int v_db,
    const uint32_t (&Pa)[8], const uint32_t (&Pb)[8],
    float (&o)[8][4], float (&accl)[4]) {
    const uint32_t onesb[2] = {ONES2, ONES2};
#pragma unroll
    for (int ks = 0; ks < 4; ++ks) {
        uint32_t ap[4] = {Pa[2 * ks], Pb[2 * ks],
                          Pa[2 * ks + 1], Pb[2 * ks + 1]};
        mma_f16(accl, ap, onesb);        // row sums of this k16 slice
        const int vrow = 16 * ks + v_k;
#pragma unroll
        for (int dt = 0; dt < 4; ++dt) {
            const uint32_t off = vrow * 128 + SWZ128B(vrow, dt * 2 + v_db);
            uint32_t vh[4];
            ldmx4t(vh, vsBase + off);
            uint32_t b0[2] = {vh[0], vh[1]}, b1[2] = {vh[2], vh[3]};
            mma_f16(o[2 * dt],     ap, b0);
            mma_f16(o[2 * dt + 1], ap, b1);
        }
    }
}

__global__ __launch_bounds__(256, 2)
void flash_mma11(const __half* __restrict__ Qh,
                 const __half* __restrict__ Kh,
                 const __half* __restrict__ Vh,
                 __half* __restrict__ AOh) {
    extern __shared__ char smem[];
    const uint32_t sb = smem_u32(smem);
    const int tid = threadIdx.x, wid = tid >> 5, lane = tid & 31;
    const int bh = blockIdx.y, b = bh >> 4, h = bh & 15;
    const int q0 = blockIdx.x * 128;
    const size_t rowStart = (size_t)b * S_;
    const int colOff = h * DH_;

    const uint32_t Ks0 = sb;
    const uint32_t Ks1 = sb + KTT;
    const uint32_t Vs0 = sb + 2 * KTT;
    const uint32_t Vs1 = sb + 3 * KTT;

    // ---- prologue: Q -> [Ks0..Ks1] (g1); V0 -> Vs0 (g2) ----
    {
        const __half* qsrc = Qh + (rowStart + q0) * DM_ + colOff;
#pragma unroll
        for (int i = 0; i < 4; ++i) {
            int c = tid + i * 256;           // 0..1023: r 0..127, ch 0..7
            int r = c >> 3, ch = c & 7;
            cp16(sb + r * 128 + SWZ128B(r, ch), qsrc + (size_t)r * DM_ + ch * 8);
        }
    }
    CP_COMMIT();                             // g1 (Q)
    fa_load_one(Vs0, Vh, rowStart, 0, colOff);
    CP_COMMIT();                             // g2 (V0)
    CP_WAIT(1);                              // g1 done
    __syncthreads();

    const int a_row = lane & 15;
    const int a_kb  = lane >> 4;
    const int b_row = ((lane >> 4) & 1) * 8 + (lane & 7);
    const int b_kb  = (lane >> 3) & 1;
    const int v_k   = (lane & 7) + ((lane >> 3) & 1) * 8;
    const int v_db  = (lane >> 4) & 1;
    const int qrow  = 16 * wid + a_row;

    uint32_t qh[4][4];
#pragma unroll
    for (int ks = 0; ks < 4; ++ks)
        ldmx4(qh[ks], sb + qrow * 128 + SWZ128B(qrow, ks * 2 + a_kb));
    __syncthreads();                         // all warps done with Q staging

    fa_load_one(Ks0, Kh, rowStart, 0, colOff);
    fa_load_one(Ks1, Kh, rowStart, 64, colOff);
    CP_COMMIT();                             // g3
    CP_WAIT(0);                              // V0, K0, K1 landed
    __syncthreads();

    float m0 = -1e30f, m1 = -1e30f;
    float accl[4] = {0.f, 0.f, 0.f, 0.f};
    float o[8][4];
#pragma unroll
    for (int j = 0; j < 8; ++j)
#pragma unroll
        for (int q = 0; q < 4; ++q) o[j][q] = 0.f;

    float s[8][4];
    qk_tile(Ks0, qh, b_row, b_kb, s);

    for (int jt = 0; jt < NT_ - 1; ++jt) {
        CP_WAIT(0);
        __syncthreads();                 // K(jt+1), V(jt) resident
        const int kc = (jt + 2 < NT_) ? (jt + 2) : (NT_ - 1);
        fa_load_one((jt & 1) ? Ks1 : Ks0, Kh, rowStart, kc * 64, colOff);
        fa_load_one(((jt + 1) & 1) ? Vs1 : Vs0, Vh, rowStart,
                    (jt + 1) * 64, colOff);
        CP_COMMIT();

        uint32_t Pa[8], Pb[8];
        softmax_pack(s, o, accl, m0, m1, Pa, Pb);
        qk_tile(((jt + 1) & 1) ? Ks1 : Ks0, qh, b_row, b_kb, s);
        pv_accum((jt & 1) ? Vs1 : Vs0, v_k, v_db, Pa, Pb, o, accl);
    }

    CP_WAIT(0);
    __syncthreads();
    {
        uint32_t Pa[8], Pb[8];
        softmax_pack(s, o, accl, m0, m1, Pa, Pb);
        pv_accum(((NT_ - 1) & 1) ? Vs1 : Vs0, v_k, v_db, Pa, Pb, o, accl);
    }

    // ---- normalize, write fp16 single ----
    const float i0 = 1.f / accl[0], i1 = 1.f / accl[2];
    const size_t row0 = rowStart + q0 + 16 * wid + (lane >> 2);
    const size_t row1 = row0 + 8;
#pragma unroll
    for (int j = 0; j < 8; ++j) {
        const int col = colOff + j * 8 + (lane & 3) * 2;
        __half2 hh01 = __floats2half2_rn(o[j][0] * i0, o[j][1] * i0);
        __half2 hh23 = __floats2half2_rn(o[j][2] * i1, o[j][3] * i1);
        *(uint32_t*)(AOh + row0 * DM_ + col) = *(uint32_t*)&hh01;
        *(uint32_t*)(AOh + row1 * DM_ + col) = *(uint32_t*)&hh23;
    }
}

// ===========================================================================
// Launch
// ===========================================================================
extern "C" void kernel_launch(void* const* d_in, const int* in_sizes, int n_in,
                              void* d_out, int out_size)
{
    const float* query = (const float*)d_in[0];
    const float* key   = (const float*)d_in[1];
    const float* value = (const float*)d_in[2];
    const float* Wq    = (const float*)d_in[3];
    const float* bq    = (const float*)d_in[4];
    const float* Wk    = (const float*)d_in[5];
    const float* bk    = (const float*)d_in[6];
    const float* Wv    = (const float*)d_in[7];
    const float* bv    = (const float*)d_in[8];
    const float* Wo    = (const float*)d_in[9];
    const float* bo    = (const float*)d_in[10];
    float* out = (float*)d_out;

    __half *pI4, *pW4, *pQh, *pKh, *pVh, *pAOh;
    cudaGetSymbolAddress((void**)&pI4,  g_I4);
    cudaGetSymbolAddress((void**)&pW4,  g_W4);
    cudaGetSymbolAddress((void**)&pQh,  g_Qh);
    cudaGetSymbolAddress((void**)&pKh,  g_Kh);
    cudaGetSymbolAddress((void**)&pVh,  g_Vh);
    cudaGetSymbolAddress((void**)&pAOh, g_AOh);

    const size_t NTOK = (size_t)ROWS_ * DM_;

    static bool attrs_set = false;
    if (!attrs_set) {
        cudaFuncSetAttribute(gemm_qkv, cudaFuncAttributeMaxDynamicSharedMemorySize, GEMM_SMEM);
        cudaFuncSetAttribute(gemm_o,   cudaFuncAttributeMaxDynamicSharedMemorySize, GEMM_SMEM);
        cudaFuncSetAttribute(flash_mma11, cudaFuncAttributeMaxDynamicSharedMemorySize, FA_SMEM);
        attrs_set = true;
    }

    const int n4 = ROWS_ * DM_ / 4;

    // 1) convert all three inputs to fp16 single
    cvt3<<<dim3((n4 + 255) / 256, 3), 256>>>(
        (const float4*)query, (const float4*)key, (const float4*)value,
        pI4 + 0 * NTOK, pI4 + 1 * NTOK, pI4 + 2 * NTOK, n4);

    // 2) transpose all four weights to fp16 single
    wtsplit4<<<dim3(32, 32, 4), dim3(32, 8)>>>(Wq, Wk, Wv, Wo, pW4);

    // 3) Q,K,V projections (1-pass fp16, BK=64)
    gemm_qkv<<<dim3(DM_ / BN, ROWS_ / BM, 3), 256, GEMM_SMEM>>>(
        pI4 + 0 * NTOK, pI4 + 1 * NTOK, pI4 + 2 * NTOK,
        pW4, bq, bk, bv, pQh, pKh, pVh);

    // 4) attention (1-pass fp16; ones-MMA row sums; packed fp16 exp2)
    flash_mma11<<<dim3(S_ / 128, B_ * NH_), 256, FA_SMEM>>>(
        pQh, pKh, pVh, pAOh);

    // 5) output projection (1-pass fp16, fp32 result)
    gemm_o<<<dim3(DM_ / BN, ROWS_ / BM), 256, GEMM_SMEM>>>(
        pAOh, pW4 + 3 * (size_t)DM_ * DM_, bo, out);
}